// round 2
// baseline (speedup 1.0000x reference)
#include <cuda_runtime.h>
#include <cuda_bf16.h>

#define TT 4096

// Reduced-coordinate Kalman filter exploiting the 4-group exchangeability of
// the 64 bias/observation dims. State of the filter: beta[4] (zero-sum-subspace
// eigenvalues), O[4][4] (group-constant bias block), Cc[4][2] (bias-state),
// S2[2][2] (state), mu[4], ms[2].
__global__ void __launch_bounds__(256, 1)
hmm_seq_kernel(const float* __restrict__ track,
               const float* __restrict__ bias_scales,
               const float* __restrict__ obs_noise,
               const float* __restrict__ trans_noise,
               const float* __restrict__ Ain,
               const float* __restrict__ init_cov,
               float* __restrict__ out,
               int T, int out_size)
{
    __shared__ float xs[2 * TT];
    __shared__ float shr[34]; // [0..15] Q, [16..23] Dc, [24..27] E, [28..31] 1/beta, [32] logp

    const int tid = threadIdx.x;
    int n2 = 2 * T;
    if (n2 > 2 * TT) n2 = 2 * TT;
    for (int i = tid; i < n2; i += blockDim.x) xs[i] = track[i];
    __syncthreads();

    if (tid == 0) {
        const float A00 = Ain[0], A01 = Ain[1], A10 = Ain[2], A11 = Ain[3];
        const float on = obs_noise[0], tn = trans_noise[0];
        const float r = on * on;
        const float q = tn * tn;
        const double LOG2PI = 1.8378770664093453;

        // group g = 2*(i>>5) + (i&1); p(g)=g>>1 selects state comp, e(g)=g&1 selects data/bias slot
        float beta[4];
        beta[0] = bias_scales[0]; beta[1] = bias_scales[1];
        beta[2] = bias_scales[0]; beta[3] = bias_scales[1];

        float O[4][4];
        #pragma unroll
        for (int g = 0; g < 4; ++g)
            #pragma unroll
            for (int h = 0; h < 4; ++h) O[g][h] = 0.0f;

        float Cc[4][2];
        #pragma unroll
        for (int g = 0; g < 4; ++g) { Cc[g][0] = 0.0f; Cc[g][1] = 0.0f; }

        float S2_[2][2];
        S2_[0][0] = init_cov[0]; S2_[0][1] = init_cov[1];
        S2_[1][0] = init_cov[2]; S2_[1][1] = init_cov[3];

        float mu[4] = {0.f, 0.f, 0.f, 0.f};
        float ms[2] = {0.f, 0.f};
        double llsum = 0.0;

        const int pg[4] = {0, 0, 1, 1};

        for (int t = 0; t < T; ++t) {
            // ---------------- predict ----------------
            {
                float m0 = A00 * ms[0] + A10 * ms[1];   // (A^T ms)
                float m1 = A01 * ms[0] + A11 * ms[1];
                ms[0] = m0; ms[1] = m1;

                // S2 = A^T S2 A + q I  (B = S2 A)
                float B00 = S2_[0][0] * A00 + S2_[0][1] * A10;
                float B01 = S2_[0][0] * A01 + S2_[0][1] * A11;
                float B10 = S2_[1][0] * A00 + S2_[1][1] * A10;
                float B11 = S2_[1][0] * A01 + S2_[1][1] * A11;
                S2_[0][0] = A00 * B00 + A10 * B10 + q;
                S2_[0][1] = A00 * B01 + A10 * B11;
                S2_[1][0] = S2_[0][1];
                S2_[1][1] = A01 * B01 + A11 * B11 + q;

                // Cc = Cc A
                #pragma unroll
                for (int g = 0; g < 4; ++g) {
                    float c0 = Cc[g][0] * A00 + Cc[g][1] * A10;
                    float c1 = Cc[g][0] * A01 + Cc[g][1] * A11;
                    Cc[g][0] = c0; Cc[g][1] = c1;
                }
            }

            // ---------------- residual ----------------
            float x0 = xs[2 * t], x1 = xs[2 * t + 1];
            float z[4];
            z[0] = x0 - mu[0] - ms[0];
            z[1] = x1 - mu[1] - ms[0];
            z[2] = x0 - mu[2] - ms[1];
            z[3] = x1 - mu[3] - ms[1];

            // ---------------- innovation: Shat = diag(alpha) + 16 W ----------------
            float al[4];
            #pragma unroll
            for (int g = 0; g < 4; ++g) al[g] = beta[g] + r;

            float Sh[4][4];
            #pragma unroll
            for (int g = 0; g < 4; ++g) {
                #pragma unroll
                for (int h = g; h < 4; ++h) {
                    float w = O[g][h] + Cc[g][pg[h]] + Cc[h][pg[g]] + S2_[pg[g]][pg[h]];
                    float v = 16.0f * w + ((g == h) ? al[g] : 0.0f);
                    Sh[g][h] = v; Sh[h][g] = v;
                }
            }

            // ---------------- invert Shat via 2x2 block Schur ----------------
            float a00 = Sh[0][0], a01 = Sh[0][1], a11 = Sh[1][1];
            float detA = a00 * a11 - a01 * a01;
            float idA = 1.0f / detA;
            float Ai00 = a11 * idA, Ai01 = -a01 * idA, Ai11 = a00 * idA;

            float b00 = Sh[0][2], b01 = Sh[0][3], b10 = Sh[1][2], b11 = Sh[1][3];
            float U00 = Ai00 * b00 + Ai01 * b10;
            float U01 = Ai00 * b01 + Ai01 * b11;
            float U10 = Ai01 * b00 + Ai11 * b10;
            float U11 = Ai01 * b01 + Ai11 * b11;

            float c00 = Sh[2][2] - (b00 * U00 + b10 * U10);
            float c01 = Sh[2][3] - (b00 * U01 + b10 * U11);
            float c11 = Sh[3][3] - (b01 * U01 + b11 * U11);
            float detC = c00 * c11 - c01 * c01;
            float idC = 1.0f / detC;
            float Si00 = c11 * idC, Si01 = -c01 * idC, Si11 = c00 * idC;

            float TR00 = -(U00 * Si00 + U01 * Si01);
            float TR01 = -(U00 * Si01 + U01 * Si11);
            float TR10 = -(U10 * Si00 + U11 * Si01);
            float TR11 = -(U10 * Si01 + U11 * Si11);

            float TL00 = Ai00 - (TR00 * U00 + TR01 * U01);
            float TL01 = Ai01 - (TR00 * U10 + TR01 * U11);
            float TL11 = Ai11 - (TR10 * U10 + TR11 * U11);

            float Sinv[4][4];
            Sinv[0][0] = TL00; Sinv[0][1] = TL01; Sinv[0][2] = TR00; Sinv[0][3] = TR01;
            Sinv[1][0] = TL01; Sinv[1][1] = TL11; Sinv[1][2] = TR10; Sinv[1][3] = TR11;
            Sinv[2][0] = TR00; Sinv[2][1] = TR10; Sinv[2][2] = Si00; Sinv[2][3] = Si01;
            Sinv[3][0] = TR01; Sinv[3][1] = TR11; Sinv[3][2] = Si01; Sinv[3][3] = Si11;

            float ldS = logf(detA) + logf(detC);
            float lsum = logf(al[0]) + logf(al[1]) + logf(al[2]) + logf(al[3]);

            // ---------------- u = Sinv z, quad, loglik ----------------
            float u[4];
            #pragma unroll
            for (int g = 0; g < 4; ++g)
                u[g] = Sinv[g][0] * z[0] + Sinv[g][1] * z[1] + Sinv[g][2] * z[2] + Sinv[g][3] * z[3];
            float quad = 16.0f * (z[0] * u[0] + z[1] * u[1] + z[2] * u[2] + z[3] * u[3]);

            llsum += -0.5 * (64.0 * LOG2PI + (double)quad)
                     - 0.5 * (15.0 * (double)lsum + (double)ldS);

            // ---------------- gain pieces ----------------
            float Hb[4][4];
            #pragma unroll
            for (int g = 0; g < 4; ++g) {
                #pragma unroll
                for (int h = 0; h < 4; ++h) Hb[g][h] = O[g][h] + Cc[g][pg[h]];
                Hb[g][g] += beta[g] * 0.0625f;
            }
            float Gs[2][4];
            #pragma unroll
            for (int k = 0; k < 2; ++k) {
                #pragma unroll
                for (int h = 0; h < 4; ++h) Gs[k][h] = Cc[h][k] + S2_[k][pg[h]];
            }

            // ---------------- mean update ----------------
            #pragma unroll
            for (int g = 0; g < 4; ++g)
                mu[g] += 16.0f * (Hb[g][0] * u[0] + Hb[g][1] * u[1] + Hb[g][2] * u[2] + Hb[g][3] * u[3]);
            #pragma unroll
            for (int k = 0; k < 2; ++k)
                ms[k] += 16.0f * (Gs[k][0] * u[0] + Gs[k][1] * u[1] + Gs[k][2] * u[2] + Gs[k][3] * u[3]);

            // ---------------- covariance update ----------------
            float T4[4][4];
            #pragma unroll
            for (int g = 0; g < 4; ++g) {
                #pragma unroll
                for (int h = 0; h < 4; ++h)
                    T4[g][h] = Hb[g][0] * Sinv[0][h] + Hb[g][1] * Sinv[1][h]
                             + Hb[g][2] * Sinv[2][h] + Hb[g][3] * Sinv[3][h];
            }

            // O <- O - 16 * T4 * Hb^T   (symmetric: compute upper, mirror)
            #pragma unroll
            for (int g = 0; g < 4; ++g) {
                #pragma unroll
                for (int h = g; h < 4; ++h) {
                    float d = T4[g][0] * Hb[h][0] + T4[g][1] * Hb[h][1]
                            + T4[g][2] * Hb[h][2] + T4[g][3] * Hb[h][3];
                    float v = O[g][h] - 16.0f * d;
                    O[g][h] = v; O[h][g] = v;
                }
            }
            // diag correction from zero-sum subspace (uses OLD beta)
            #pragma unroll
            for (int g = 0; g < 4; ++g)
                O[g][g] += (beta[g] * beta[g]) / (16.0f * al[g]);

            // Cc <- Cc - 16 * T4 * Gs^T
            #pragma unroll
            for (int g = 0; g < 4; ++g) {
                #pragma unroll
                for (int k = 0; k < 2; ++k) {
                    float d = T4[g][0] * Gs[k][0] + T4[g][1] * Gs[k][1]
                            + T4[g][2] * Gs[k][2] + T4[g][3] * Gs[k][3];
                    Cc[g][k] -= 16.0f * d;
                }
            }

            // S2 <- S2 - 16 * Gs * Sinv * Gs^T
            float G2[2][4];
            #pragma unroll
            for (int k = 0; k < 2; ++k) {
                #pragma unroll
                for (int h = 0; h < 4; ++h)
                    G2[k][h] = Gs[k][0] * Sinv[0][h] + Gs[k][1] * Sinv[1][h]
                             + Gs[k][2] * Sinv[2][h] + Gs[k][3] * Sinv[3][h];
            }
            float s00 = G2[0][0] * Gs[0][0] + G2[0][1] * Gs[0][1] + G2[0][2] * Gs[0][2] + G2[0][3] * Gs[0][3];
            float s01 = G2[0][0] * Gs[1][0] + G2[0][1] * Gs[1][1] + G2[0][2] * Gs[1][2] + G2[0][3] * Gs[1][3];
            float s11 = G2[1][0] * Gs[1][0] + G2[1][1] * Gs[1][1] + G2[1][2] * Gs[1][2] + G2[1][3] * Gs[1][3];
            S2_[0][0] -= 16.0f * s00;
            S2_[0][1] -= 16.0f * s01;
            S2_[1][0] = S2_[0][1];
            S2_[1][1] -= 16.0f * s11;

            // beta <- beta * r / alpha
            #pragma unroll
            for (int g = 0; g < 4; ++g)
                beta[g] = beta[g] * r / al[g];
        }

        // ---------------- final precision: invert 6x6 reduced matrix ----------------
        // M6 = [[diag(beta)+16 O, Cc], [16 Cc^T, S2]]
        float Mm[6][12];
        for (int i = 0; i < 6; ++i)
            for (int j = 0; j < 12; ++j) Mm[i][j] = 0.0f;
        for (int g = 0; g < 4; ++g) {
            for (int h = 0; h < 4; ++h) Mm[g][h] = 16.0f * O[g][h];
            Mm[g][g] += beta[g];
            for (int k = 0; k < 2; ++k) {
                Mm[g][4 + k] = Cc[g][k];
                Mm[4 + k][g] = 16.0f * Cc[g][k];
            }
        }
        for (int k = 0; k < 2; ++k)
            for (int l = 0; l < 2; ++l) Mm[4 + k][4 + l] = S2_[k][l];
        for (int i = 0; i < 6; ++i) Mm[i][6 + i] = 1.0f;

        // Gauss-Jordan with partial pivoting
        for (int c = 0; c < 6; ++c) {
            int piv = c;
            float mx = fabsf(Mm[c][c]);
            for (int rr = c + 1; rr < 6; ++rr) {
                float a = fabsf(Mm[rr][c]);
                if (a > mx) { mx = a; piv = rr; }
            }
            if (piv != c) {
                for (int j = 0; j < 12; ++j) {
                    float tmp = Mm[c][j]; Mm[c][j] = Mm[piv][j]; Mm[piv][j] = tmp;
                }
            }
            float pv = 1.0f / Mm[c][c];
            for (int j = 0; j < 12; ++j) Mm[c][j] *= pv;
            for (int rr = 0; rr < 6; ++rr) {
                if (rr == c) continue;
                float f = Mm[rr][c];
                for (int j = 0; j < 12; ++j) Mm[rr][j] -= f * Mm[c][j];
            }
        }

        float ib[4];
        for (int g = 0; g < 4; ++g) ib[g] = 1.0f / beta[g];
        // Q = (N6_tl - diag(1/beta)) / 16
        for (int g = 0; g < 4; ++g)
            for (int h = 0; h < 4; ++h)
                shr[g * 4 + h] = (Mm[g][6 + h] - ((g == h) ? ib[g] : 0.0f)) * 0.0625f;
        // Dc = N6 top-right
        for (int g = 0; g < 4; ++g)
            for (int k = 0; k < 2; ++k)
                shr[16 + g * 2 + k] = Mm[g][6 + 4 + k];
        // E = N6 bottom-right
        for (int k = 0; k < 2; ++k)
            for (int l = 0; l < 2; ++l)
                shr[24 + k * 2 + l] = Mm[4 + k][6 + 4 + l];
        for (int g = 0; g < 4; ++g) shr[28 + g] = ib[g];
        shr[32] = (float)llsum;
    }
    __syncthreads();

    // ---------------- cooperative output write: out[0]=logp, out[1..] = precision (66x66) ----------------
    if (tid == 0 && out_size > 0) out[0] = shr[32];
    const int NP = 66 * 66;
    for (int idx = tid; idx < NP; idx += blockDim.x) {
        if (idx + 1 >= out_size) break;
        int i = idx / 66;
        int j = idx - 66 * i;
        float v;
        if (i < 64 && j < 64) {
            int gi = ((i >> 5) << 1) | (i & 1);
            int gj = ((j >> 5) << 1) | (j & 1);
            v = shr[gi * 4 + gj] + ((i == j) ? shr[28 + gi] : 0.0f);
        } else if (i < 64) {
            int gi = ((i >> 5) << 1) | (i & 1);
            v = shr[16 + gi * 2 + (j - 64)];
        } else if (j < 64) {
            int gj = ((j >> 5) << 1) | (j & 1);
            v = shr[16 + gj * 2 + (i - 64)];
        } else {
            v = shr[24 + (i - 64) * 2 + (j - 64)];
        }
        out[1 + idx] = v;
    }
}

extern "C" void kernel_launch(void* const* d_in, const int* in_sizes, int n_in,
                              void* d_out, int out_size) {
    const float* track      = (const float*)d_in[0];
    const float* bias_sc    = (const float*)d_in[1];
    const float* obs_noise  = (const float*)d_in[2];
    const float* trans_n    = (const float*)d_in[3];
    const float* A          = (const float*)d_in[4];
    const float* init_cov   = (const float*)d_in[5];
    float* out = (float*)d_out;
    int T = in_sizes[0] / 2;
    if (T > TT) T = TT;
    hmm_seq_kernel<<<1, 256>>>(track, bias_sc, obs_noise, trans_n, A, init_cov,
                               out, T, out_size);
}

// round 3
// speedup vs baseline: 3.4895x; 3.4895x over previous
#include <cuda_runtime.h>
#include <cuda_bf16.h>

#define TT 4096

__device__ double g_ld2_slot;

__global__ void __launch_bounds__(256, 1)
hmm_chan_kernel(const float* __restrict__ track,
                const float* __restrict__ bias_scales,
                const float* __restrict__ obs_noise,
                const float* __restrict__ trans_noise,
                const float* __restrict__ Ain,
                const float* __restrict__ init_cov,
                float* __restrict__ out,
                int T, int out_size)
{
    __shared__ float sig[TT];
    __shared__ float del[TT];
    __shared__ float wtot[8];
    __shared__ double sdbl[256];
    __shared__ double s_wq;
    __shared__ float shr[20];

    const int tid = threadIdx.x;
    const int lane = tid & 31;
    const int wid = tid >> 5;
    const float SQ8 = 2.8284271247461903f;

    for (int t = tid; t < T; t += 256) {
        float x0 = track[2 * t], x1 = track[2 * t + 1];
        sig[t] = SQ8 * (x0 + x1);
        del[t] = SQ8 * (x0 - x1);
    }
    __syncthreads();

    const float bs0 = bias_scales[0], bs1 = bias_scales[1];
    const float bsu = 0.5f * (bs0 + bs1);
    const float on = obs_noise[0], tn = trans_noise[0];
    const float r = on * on;
    const float q = tn * tn;

    // ---- phase 1: diff channel via block prefix scan ----
    {
        const float adf = r / bsu;
        const int base = tid * 16;
        float loc[16];
        float s = 0.0f;
        #pragma unroll
        for (int k = 0; k < 16; ++k) {
            float v = (base + k < T) ? del[base + k] : 0.0f;
            loc[k] = v; s += v;
        }
        float v = s;
        #pragma unroll
        for (int off = 1; off < 32; off <<= 1) {
            float n = __shfl_up_sync(0xffffffffu, v, off);
            if (lane >= off) v += n;
        }
        if (lane == 31) wtot[wid] = v;
        __syncthreads();
        if (wid == 0 && lane < 8) {
            float orig = wtot[lane];
            float w = orig;
            #pragma unroll
            for (int off = 1; off < 8; off <<= 1) {
                float n = __shfl_up_sync(0xffu, w, off);
                if (lane >= off) w += n;
            }
            wtot[lane] = w - orig;
        }
        __syncthreads();
        float run = (v - s) + wtot[wid];

        double wq = 0.0;
        #pragma unroll
        for (int k = 0; k < 16; ++k) {
            int t = base + k;
            if (t < T) {
                float at = adf + (float)t;
                float mdt = run / at;
                float zd = loc[k] - mdt;
                float w = at / (r * (at + 1.0f));
                wq += (double)(zd * zd * w);
            }
            run += loc[k];
        }
        sdbl[tid] = wq;
        __syncthreads();
        if (tid == 0) {
            double acc = 0.0;
            for (int i = 0; i < 256; ++i) acc += sdbl[i];
            s_wq = acc;
        }
    }
    __syncthreads();

    // ---- phase 2: sequential 4-dim sum-channel Riccati on thread 0 ----
    if (tid == 0) {
        const float A00 = Ain[0], A01 = Ain[1], A10 = Ain[2], A11 = Ain[3];
        const float c = 5.656854249492381f;  // 4*sqrt(2)
        const float c2 = 32.0f;

        float puu00 = bsu, puu01 = 0.0f, puu11 = bsu;
        float pus00 = 0.f, pus01 = 0.f, pus10 = 0.f, pus11 = 0.f;
        float pss00 = init_cov[0], pss01 = init_cov[1], pss11 = init_cov[3];
        float mu0 = 0.f, mu1 = 0.f, m0 = 0.f, m1 = 0.f;
        float prodm = 1.0f;
        int eacc = 0;

        for (int t = 0; t < T; ++t) {
            float n0 = A00 * m0 + A10 * m1;
            float n1 = A01 * m0 + A11 * m1;
            m0 = n0; m1 = n1;

            float b00 = pss00 * A00 + pss01 * A10;
            float b01 = pss00 * A01 + pss01 * A11;
            float b10 = pss01 * A00 + pss11 * A10;
            float b11 = pss01 * A01 + pss11 * A11;
            pss00 = A00 * b00 + A10 * b10 + q;
            pss01 = A00 * b01 + A10 * b11;
            pss11 = A01 * b01 + A11 * b11 + q;

            float t00 = pus00 * A00 + pus01 * A10;
            float t01 = pus00 * A01 + pus01 * A11;
            float t10 = pus10 * A00 + pus11 * A10;
            float t11 = pus10 * A01 + pus11 * A11;
            pus00 = t00; pus01 = t01; pus10 = t10; pus11 = t11;

            float S00 = puu00 + 2.0f * c * pus00 + c2 * pss00 + r;
            float S01 = puu01 + c * (pus01 + pus10) + c2 * pss01;
            float S11 = puu11 + 2.0f * c * pus11 + c2 * pss11 + r;
            float det = S00 * S11 - S01 * S01;
            float id = 1.0f / det;

            int bi = __float_as_int(det);
            eacc += ((bi >> 23) & 255) - 127;
            prodm *= __int_as_float((bi & 0x807FFFFF) | 0x3F800000);
            int pb = __float_as_int(prodm);
            eacc += ((pb >> 23) & 255) - 127;
            prodm = __int_as_float((pb & 0x807FFFFF) | 0x3F800000);

            float G00 = puu00 + c * pus00, G01 = puu01 + c * pus01;
            float G10 = puu01 + c * pus10, G11 = puu11 + c * pus11;
            float G20 = pus00 + c * pss00, G21 = pus10 + c * pss01;
            float G30 = pus01 + c * pss01, G31 = pus11 + c * pss11;

            float y = sig[t];
            float z0 = y - mu0 - c * m0;
            float z1 = y - mu1 - c * m1;
            float u0 = (S11 * z0 - S01 * z1) * id;
            float u1 = (S00 * z1 - S01 * z0) * id;
            del[t] = z0 * u0 + z1 * u1;

            mu0 += G00 * u0 + G01 * u1;
            mu1 += G10 * u0 + G11 * u1;
            m0  += G20 * u0 + G21 * u1;
            m1  += G30 * u0 + G31 * u1;

            float W00 = (G00 * S11 - G01 * S01) * id, W01 = (G01 * S00 - G00 * S01) * id;
            float W10 = (G10 * S11 - G11 * S01) * id, W11 = (G11 * S00 - G10 * S01) * id;
            float W20 = (G20 * S11 - G21 * S01) * id, W21 = (G21 * S00 - G20 * S01) * id;
            float W30 = (G30 * S11 - G31 * S01) * id, W31 = (G31 * S00 - G30 * S01) * id;

            puu00 -= W00 * G00 + W01 * G01;
            puu01 -= W00 * G10 + W01 * G11;
            puu11 -= W10 * G10 + W11 * G11;
            pus00 -= W00 * G20 + W01 * G21;
            pus01 -= W00 * G30 + W01 * G31;
            pus10 -= W10 * G20 + W11 * G21;
            pus11 -= W10 * G30 + W11 * G31;
            pss00 -= W20 * G20 + W21 * G21;
            pss01 -= W20 * G30 + W21 * G31;
            pss11 -= W30 * G30 + W31 * G31;
        }

        g_ld2_slot = (double)eacc * 0.6931471805599453 + log((double)prodm);

        // invert final 4x4 (U0,U1,s0,s1) covariance
        float Mm[4][8];
        Mm[0][0] = puu00; Mm[0][1] = puu01; Mm[0][2] = pus00; Mm[0][3] = pus01;
        Mm[1][0] = puu01; Mm[1][1] = puu11; Mm[1][2] = pus10; Mm[1][3] = pus11;
        Mm[2][0] = pus00; Mm[2][1] = pus10; Mm[2][2] = pss00; Mm[2][3] = pss01;
        Mm[3][0] = pus01; Mm[3][1] = pus11; Mm[3][2] = pss01; Mm[3][3] = pss11;
        for (int i = 0; i < 4; ++i)
            for (int j = 0; j < 4; ++j) Mm[i][4 + j] = (i == j) ? 1.0f : 0.0f;
        for (int cc = 0; cc < 4; ++cc) {
            int piv = cc; float mx = fabsf(Mm[cc][cc]);
            for (int rr = cc + 1; rr < 4; ++rr) {
                float a = fabsf(Mm[rr][cc]);
                if (a > mx) { mx = a; piv = rr; }
            }
            if (piv != cc)
                for (int j = 0; j < 8; ++j) { float tmp = Mm[cc][j]; Mm[cc][j] = Mm[piv][j]; Mm[piv][j] = tmp; }
            float pv = 1.0f / Mm[cc][cc];
            for (int j = 0; j < 8; ++j) Mm[cc][j] *= pv;
            for (int rr = 0; rr < 4; ++rr) {
                if (rr == cc) continue;
                float f = Mm[rr][cc];
                for (int j = 0; j < 8; ++j) Mm[rr][j] -= f * Mm[cc][j];
            }
        }
        for (int i = 0; i < 4; ++i)
            for (int j = 0; j < 4; ++j) shr[i * 4 + j] = Mm[i][4 + j];

        double Td = (double)T, rr_ = (double)r;
        shr[16] = (float)(1.0 / (double)bs0 + Td / rr_);
        shr[17] = (float)(1.0 / (double)bs1 + Td / rr_);
        shr[18] = (float)(1.0 / (double)bsu + Td / rr_);
    }
    __syncthreads();

    // ---- phase 3: reduce per-step quads, assemble logp ----
    {
        double acc = 0.0;
        for (int t = tid; t < T; t += 256) acc += (double)del[t];
        sdbl[tid] = acc;
    }
    __syncthreads();
    if (tid == 0) {
        double quad_sum = 0.0;
        for (int i = 0; i < 256; ++i) quad_sum += sdbl[i];
        double Td = (double)T, rr_ = (double)r;
        double a0 = rr_ / (double)bs0, a1 = rr_ / (double)bs1, au = rr_ / (double)bsu;
        const double LOG2PI = 1.8378770664093453;
        double ld_contrast = 15.0 * (4.0 * Td * log(rr_)
                                     + 2.0 * log((a0 + Td) / a0)
                                     + 2.0 * log((a1 + Td) / a1));
        double ld_diff = 2.0 * (Td * log(rr_) + log((au + Td) / au));
        double logp = -0.5 * (64.0 * Td * LOG2PI)
                      - 0.5 * (quad_sum + 2.0 * s_wq)
                      - 0.5 * (g_ld2_slot + ld_contrast + ld_diff);
        shr[19] = (float)logp;
    }
    __syncthreads();

    // ---- output: out[0]=logp, out[1..]=66x66 precision ----
    if (tid == 0 && out_size > 0) out[0] = shr[19];
    const int NP = 66 * 66;
    const float INV32 = 0.03125f;
    const float INVS32 = 0.17677669529663687f;
    for (int idx = tid; idx < NP; idx += 256) {
        if (idx + 1 >= out_size) break;
        int i = idx / 66;
        int j = idx - 66 * i;
        float v;
        if (i < 64 && j < 64) {
            int pi = i >> 5, pj = j >> 5, ei = i & 1, ej = j & 1;
            v = shr[pi * 4 + pj] * INV32;
            if (pi == pj) {
                v += ((ei == ej) ? shr[18] : -shr[18]) * INV32;
                if (ei == ej) {
                    v -= shr[16 + ei] * 0.0625f;
                    if (i == j) v += shr[16 + ei];
                }
            }
        } else if (i < 64) {
            int pi = i >> 5;
            v = shr[pi * 4 + 2 + (j - 64)] * INVS32;
        } else if (j < 64) {
            int pj = j >> 5;
            v = shr[pj * 4 + 2 + (i - 64)] * INVS32;
        } else {
            v = shr[(2 + i - 64) * 4 + (2 + j - 64)];
        }
        out[1 + idx] = v;
    }
}

extern "C" void kernel_launch(void* const* d_in, const int* in_sizes, int n_in,
                              void* d_out, int out_size) {
    const float* track     = (const float*)d_in[0];
    const float* bias_sc   = (const float*)d_in[1];
    const float* obs_noise = (const float*)d_in[2];
    const float* trans_n   = (const float*)d_in[3];
    const float* A         = (const float*)d_in[4];
    const float* init_cov  = (const float*)d_in[5];
    float* out = (float*)d_out;
    int T = in_sizes[0] / 2;
    if (T > TT) T = TT;
    hmm_chan_kernel<<<1, 256>>>(track, bias_sc, obs_noise, trans_n, A, init_cov,
                                out, T, out_size);
}

// round 4
// speedup vs baseline: 5.7269x; 1.6412x over previous
#include <cuda_runtime.h>
#include <cuda_bf16.h>

#define TT 4096

__device__ double g_ld2_slot;

__global__ void __launch_bounds__(256, 1)
hmm_chan_kernel(const float* __restrict__ track,
                const float* __restrict__ bias_scales,
                const float* __restrict__ obs_noise,
                const float* __restrict__ trans_noise,
                const float* __restrict__ Ain,
                const float* __restrict__ init_cov,
                float* __restrict__ out,
                int T, int out_size)
{
    __shared__ float sig[TT];
    __shared__ float del[TT];
    __shared__ float wtot[8];
    __shared__ double sdbl[256];
    __shared__ double s_wq;
    __shared__ float shr[20];

    const int tid = threadIdx.x;
    const int lane = tid & 31;
    const int wid = tid >> 5;
    const float SQ8 = 2.8284271247461903f;

    for (int t = tid; t < T; t += 256) {
        float x0 = track[2 * t], x1 = track[2 * t + 1];
        sig[t] = SQ8 * (x0 + x1);
        del[t] = SQ8 * (x0 - x1);
    }
    __syncthreads();

    const float bs0 = bias_scales[0], bs1 = bias_scales[1];
    const float bsu = 0.5f * (bs0 + bs1);
    const float on = obs_noise[0], tn = trans_noise[0];
    const float r = on * on;
    const float q = tn * tn;

    // ---- phase 1: diff channel via block prefix scan ----
    {
        const float adf = r / bsu;
        const int base = tid * 16;
        float loc[16];
        float s = 0.0f;
        #pragma unroll
        for (int k = 0; k < 16; ++k) {
            float v = (base + k < T) ? del[base + k] : 0.0f;
            loc[k] = v; s += v;
        }
        float v = s;
        #pragma unroll
        for (int off = 1; off < 32; off <<= 1) {
            float n = __shfl_up_sync(0xffffffffu, v, off);
            if (lane >= off) v += n;
        }
        if (lane == 31) wtot[wid] = v;
        __syncthreads();
        if (wid == 0 && lane < 8) {
            float orig = wtot[lane];
            float w = orig;
            #pragma unroll
            for (int off = 1; off < 8; off <<= 1) {
                float n = __shfl_up_sync(0xffu, w, off);
                if (lane >= off) w += n;
            }
            wtot[lane] = w - orig;
        }
        __syncthreads();
        float run = (v - s) + wtot[wid];

        double wq = 0.0;
        #pragma unroll
        for (int k = 0; k < 16; ++k) {
            int t = base + k;
            if (t < T) {
                float at = adf + (float)t;
                float mdt = run / at;
                float zd = loc[k] - mdt;
                float w = at / (r * (at + 1.0f));
                wq += (double)(zd * zd * w);
            }
            run += loc[k];
        }
        sdbl[tid] = wq;
        __syncthreads();
        if (tid == 0) {
            double acc = 0.0;
            for (int i = 0; i < 256; ++i) acc += sdbl[i];
            s_wq = acc;
        }
    }
    __syncthreads();

    // ---- phase 2: sequential 4-dim sum-channel Riccati on thread 0 ----
    if (tid == 0) {
        const float A00 = Ain[0], A01 = Ain[1], A10 = Ain[2], A11 = Ain[3];
        const float c = 5.656854249492381f;  // 4*sqrt(2)
        const float c2 = 32.0f;

        float puu00 = bsu, puu01 = 0.0f, puu11 = bsu;
        float pus00 = 0.f, pus01 = 0.f, pus10 = 0.f, pus11 = 0.f;
        float pss00 = init_cov[0], pss01 = init_cov[1], pss11 = init_cov[3];
        float mu0 = 0.f, mu1 = 0.f, m0 = 0.f, m1 = 0.f;
        float prodm = 1.0f;
        int eacc = 0;

        for (int t = 0; t < T; ++t) {
            float n0 = A00 * m0 + A10 * m1;
            float n1 = A01 * m0 + A11 * m1;
            m0 = n0; m1 = n1;

            float b00 = pss00 * A00 + pss01 * A10;
            float b01 = pss00 * A01 + pss01 * A11;
            float b10 = pss01 * A00 + pss11 * A10;
            float b11 = pss01 * A01 + pss11 * A11;
            pss00 = A00 * b00 + A10 * b10 + q;
            pss01 = A00 * b01 + A10 * b11;
            pss11 = A01 * b01 + A11 * b11 + q;

            float t00 = pus00 * A00 + pus01 * A10;
            float t01 = pus00 * A01 + pus01 * A11;
            float t10 = pus10 * A00 + pus11 * A10;
            float t11 = pus10 * A01 + pus11 * A11;
            pus00 = t00; pus01 = t01; pus10 = t10; pus11 = t11;

            float S00 = puu00 + 2.0f * c * pus00 + c2 * pss00 + r;
            float S01 = puu01 + c * (pus01 + pus10) + c2 * pss01;
            float S11 = puu11 + 2.0f * c * pus11 + c2 * pss11 + r;
            float det = S00 * S11 - S01 * S01;
            float id = 1.0f / det;

            int bi = __float_as_int(det);
            eacc += ((bi >> 23) & 255) - 127;
            prodm *= __int_as_float((bi & 0x807FFFFF) | 0x3F800000);
            int pb = __float_as_int(prodm);
            eacc += ((pb >> 23) & 255) - 127;
            prodm = __int_as_float((pb & 0x807FFFFF) | 0x3F800000);

            float G00 = puu00 + c * pus00, G01 = puu01 + c * pus01;
            float G10 = puu01 + c * pus10, G11 = puu11 + c * pus11;
            float G20 = pus00 + c * pss00, G21 = pus10 + c * pss01;
            float G30 = pus01 + c * pss01, G31 = pus11 + c * pss11;

            float y = sig[t];
            float z0 = y - mu0 - c * m0;
            float z1 = y - mu1 - c * m1;
            float u0 = (S11 * z0 - S01 * z1) * id;
            float u1 = (S00 * z1 - S01 * z0) * id;
            del[t] = z0 * u0 + z1 * u1;

            mu0 += G00 * u0 + G01 * u1;
            mu1 += G10 * u0 + G11 * u1;
            m0  += G20 * u0 + G21 * u1;
            m1  += G30 * u0 + G31 * u1;

            float W00 = (G00 * S11 - G01 * S01) * id, W01 = (G01 * S00 - G00 * S01) * id;
            float W10 = (G10 * S11 - G11 * S01) * id, W11 = (G11 * S00 - G10 * S01) * id;
            float W20 = (G20 * S11 - G21 * S01) * id, W21 = (G21 * S00 - G20 * S01) * id;
            float W30 = (G30 * S11 - G31 * S01) * id, W31 = (G31 * S00 - G30 * S01) * id;

            puu00 -= W00 * G00 + W01 * G01;
            puu01 -= W00 * G10 + W01 * G11;
            puu11 -= W10 * G10 + W11 * G11;
            pus00 -= W00 * G20 + W01 * G21;
            pus01 -= W00 * G30 + W01 * G31;
            pus10 -= W10 * G20 + W11 * G21;
            pus11 -= W10 * G30 + W11 * G31;
            pss00 -= W20 * G20 + W21 * G21;
            pss01 -= W20 * G30 + W21 * G31;
            pss11 -= W30 * G30 + W31 * G31;
        }

        g_ld2_slot = (double)eacc * 0.6931471805599453 + log((double)prodm);

        // invert final 4x4 (U0,U1,s0,s1) covariance
        float Mm[4][8];
        Mm[0][0] = puu00; Mm[0][1] = puu01; Mm[0][2] = pus00; Mm[0][3] = pus01;
        Mm[1][0] = puu01; Mm[1][1] = puu11; Mm[1][2] = pus10; Mm[1][3] = pus11;
        Mm[2][0] = pus00; Mm[2][1] = pus10; Mm[2][2] = pss00; Mm[2][3] = pss01;
        Mm[3][0] = pus01; Mm[3][1] = pus11; Mm[3][2] = pss01; Mm[3][3] = pss11;
        for (int i = 0; i < 4; ++i)
            for (int j = 0; j < 4; ++j) Mm[i][4 + j] = (i == j) ? 1.0f : 0.0f;
        for (int cc = 0; cc < 4; ++cc) {
            int piv = cc; float mx = fabsf(Mm[cc][cc]);
            for (int rr = cc + 1; rr < 4; ++rr) {
                float a = fabsf(Mm[rr][cc]);
                if (a > mx) { mx = a; piv = rr; }
            }
            if (piv != cc)
                for (int j = 0; j < 8; ++j) { float tmp = Mm[cc][j]; Mm[cc][j] = Mm[piv][j]; Mm[piv][j] = tmp; }
            float pv = 1.0f / Mm[cc][cc];
            for (int j = 0; j < 8; ++j) Mm[cc][j] *= pv;
            for (int rr = 0; rr < 4; ++rr) {
                if (rr == cc) continue;
                float f = Mm[rr][cc];
                for (int j = 0; j < 8; ++j) Mm[rr][j] -= f * Mm[cc][j];
            }
        }
        for (int i = 0; i < 4; ++i)
            for (int j = 0; j < 4; ++j) shr[i * 4 + j] = Mm[i][4 + j];

        double Td = (double)T, rr_ = (double)r;
        shr[16] = (float)(1.0 / (double)bs0 + Td / rr_);
        shr[17] = (float)(1.0 / (double)bs1 + Td / rr_);
        shr[18] = (float)(1.0 / (double)bsu + Td / rr_);
    }
    __syncthreads();

    // ---- phase 3: reduce per-step quads, assemble logp ----
    {
        double acc = 0.0;
        for (int t = tid; t < T; t += 256) acc += (double)del[t];
        sdbl[tid] = acc;
    }
    __syncthreads();
    if (tid == 0) {
        double quad_sum = 0.0;
        for (int i = 0; i < 256; ++i) quad_sum += sdbl[i];
        double Td = (double)T, rr_ = (double)r;
        double a0 = rr_ / (double)bs0, a1 = rr_ / (double)bs1, au = rr_ / (double)bsu;
        const double LOG2PI = 1.8378770664093453;
        double ld_contrast = 15.0 * (4.0 * Td * log(rr_)
                                     + 2.0 * log((a0 + Td) / a0)
                                     + 2.0 * log((a1 + Td) / a1));
        double ld_diff = 2.0 * (Td * log(rr_) + log((au + Td) / au));
        double logp = -0.5 * (64.0 * Td * LOG2PI)
                      - 0.5 * (quad_sum + 2.0 * s_wq)
                      - 0.5 * (g_ld2_slot + ld_contrast + ld_diff);
        shr[19] = (float)logp;
    }
    __syncthreads();

    // ---- output: out[0]=logp, out[1..]=66x66 precision ----
    if (tid == 0 && out_size > 0) out[0] = shr[19];
    const int NP = 66 * 66;
    const float INV32 = 0.03125f;
    const float INVS32 = 0.17677669529663687f;
    for (int idx = tid; idx < NP; idx += 256) {
        if (idx + 1 >= out_size) break;
        int i = idx / 66;
        int j = idx - 66 * i;
        float v;
        if (i < 64 && j < 64) {
            int pi = i >> 5, pj = j >> 5, ei = i & 1, ej = j & 1;
            v = shr[pi * 4 + pj] * INV32;
            if (pi == pj) {
                v += ((ei == ej) ? shr[18] : -shr[18]) * INV32;
                if (ei == ej) {
                    v -= shr[16 + ei] * 0.0625f;
                    if (i == j) v += shr[16 + ei];
                }
            }
        } else if (i < 64) {
            int pi = i >> 5;
            v = shr[pi * 4 + 2 + (j - 64)] * INVS32;
        } else if (j < 64) {
            int pj = j >> 5;
            v = shr[pj * 4 + 2 + (i - 64)] * INVS32;
        } else {
            v = shr[(2 + i - 64) * 4 + (2 + j - 64)];
        }
        out[1 + idx] = v;
    }
}

extern "C" void kernel_launch(void* const* d_in, const int* in_sizes, int n_in,
                              void* d_out, int out_size) {
    const float* track     = (const float*)d_in[0];
    const float* bias_sc   = (const float*)d_in[1];
    const float* obs_noise = (const float*)d_in[2];
    const float* trans_n   = (const float*)d_in[3];
    const float* A         = (const float*)d_in[4];
    const float* init_cov  = (const float*)d_in[5];
    float* out = (float*)d_out;
    int T = in_sizes[0] / 2;
    if (T > TT) T = TT;
    hmm_chan_kernel<<<1, 256>>>(track, bias_sc, obs_noise, trans_n, A, init_cov,
                                out, T, out_size);
}

// round 7
// speedup vs baseline: 6.0265x; 1.0523x over previous
#include <cuda_runtime.h>
#include <math.h>

#define NTH 256
#define CH 16
#define TT 4096

__device__ float4 g_kv[TT*3];

__global__ void __launch_bounds__(NTH,1)
hmm_hyb(const float* __restrict__ track, const float* __restrict__ bias_scales,
        const float* __restrict__ obs_noise, const float* __restrict__ trans_noise,
        const float* __restrict__ Ain, const float* __restrict__ init_cov,
        float* __restrict__ out, int T, int out_size)
{
    __shared__ float elems[NTH*20];
    __shared__ double dbl[NTH+4];
    __shared__ float wtot[8];
    __shared__ float pTf[16];
    __shared__ float shr[24];

    const int c = threadIdx.x;
    const int lane = c&31, wid = c>>5;
    const float SQ8 = 2.8284271247461903f;
    const float cst = 5.656854249492381f;   // 4*sqrt(2)

    const float bs0=bias_scales[0], bs1=bias_scales[1];
    const float bsu=0.5f*(bs0+bs1);
    const float r=obs_noise[0]*obs_noise[0];
    const float q=trans_noise[0]*trans_noise[0];
    const float A00=Ain[0], A01=Ain[1], A10=Ain[2], A11=Ain[3];

    // per-thread chunk data in registers
    float sig[CH], del[CH];
    #pragma unroll
    for(int k=0;k<CH;++k){
        int t=c*CH+k;
        float x0 = (t<T)?track[2*t]:0.0f;
        float x1 = (t<T)?track[2*t+1]:0.0f;
        sig[k]=SQ8*(x0+x1);
        del[k]=SQ8*(x0-x1);
    }

    // ---- phase 1: diff channel prefix scan (R2-proven) ----
    {
        const float adf=r/bsu;
        float s=0.0f;
        #pragma unroll
        for(int k=0;k<CH;++k) s+=del[k];
        float v=s;
        #pragma unroll
        for(int off=1;off<32;off<<=1){
            float n=__shfl_up_sync(0xffffffffu,v,off);
            if(lane>=off) v+=n;
        }
        if(lane==31) wtot[wid]=v;
        __syncthreads();
        if(wid==0 && lane<8){
            float orig=wtot[lane], w=orig;
            #pragma unroll
            for(int off=1;off<8;off<<=1){
                float n=__shfl_up_sync(0xffu,w,off);
                if(lane>=off) w+=n;
            }
            wtot[lane]=w-orig;
        }
        __syncthreads();
        float run=(v-s)+wtot[wid];
        double wq=0.0;
        #pragma unroll
        for(int k=0;k<CH;++k){
            int t=c*CH+k;
            if(t<T){
                float at=adf+(float)t;
                float zd=del[k]-run/at;
                wq += (double)(zd*zd*at/(r*(at+1.0f)));
            }
            run+=del[k];
        }
        dbl[c]=wq;
        __syncthreads();
        if(c==0){
            double acc=0.0;
            for(int i=0;i<NTH;++i) acc+=dbl[i];
            dbl[NTH]=acc;         // s_wq
        }
        __syncthreads();
    }

    // ---- phase 2: thread 0 sequential covariance-only Riccati (R2-proven math) ----
    if(c==0){
        float puu00=bsu, puu01=0.0f, puu11=bsu;
        float pus00=0.f, pus01=0.f, pus10=0.f, pus11=0.f;
        float pss00=init_cov[0], pss01=init_cov[1], pss11=init_cov[3];
        const float c2=32.0f;
        float4* gp = g_kv;
        for(int t=0;t<T;++t){
            // predict
            float b00=pss00*A00+pss01*A10;
            float b01=pss00*A01+pss01*A11;
            float b10=pss01*A00+pss11*A10;
            float b11=pss01*A01+pss11*A11;
            pss00=A00*b00+A10*b10+q;
            pss01=A00*b01+A10*b11;
            pss11=A01*b01+A11*b11+q;
            float t00=pus00*A00+pus01*A10;
            float t01=pus00*A01+pus01*A11;
            float t10=pus10*A00+pus11*A10;
            float t11=pus10*A01+pus11*A11;
            pus00=t00;pus01=t01;pus10=t10;pus11=t11;
            // innovation
            float S00=puu00+2.0f*cst*pus00+c2*pss00+r;
            float S01=puu01+cst*(pus01+pus10)+c2*pss01;
            float S11=puu11+2.0f*cst*pus11+c2*pss11+r;
            float det=S00*S11-S01*S01;
            float id=1.0f/det;
            // G = P H^T
            float G00=puu00+cst*pus00, G01=puu01+cst*pus01;
            float G10=puu01+cst*pus10, G11=puu11+cst*pus11;
            float G20=pus00+cst*pss00, G21=pus10+cst*pss01;
            float G30=pus01+cst*pss01, G31=pus11+cst*pss11;
            // K = G Sinv
            float W00=(G00*S11-G01*S01)*id, W01=(G01*S00-G00*S01)*id;
            float W10=(G10*S11-G11*S01)*id, W11=(G11*S00-G10*S01)*id;
            float W20=(G20*S11-G21*S01)*id, W21=(G21*S00-G20*S01)*id;
            float W30=(G30*S11-G31*S01)*id, W31=(G31*S00-G30*S01)*id;
            gp[0]=make_float4(W00,W01,W10,W11);
            gp[1]=make_float4(W20,W21,W30,W31);
            gp[2]=make_float4(S00,S01,S11,id);
            gp+=3;
            // P <- P - K G^T (symmetric)
            puu00-=W00*G00+W01*G01;
            puu01-=W00*G10+W01*G11;
            puu11-=W10*G10+W11*G11;
            pus00-=W00*G20+W01*G21;
            pus01-=W00*G30+W01*G31;
            pus10-=W10*G20+W11*G21;
            pus11-=W10*G30+W11*G31;
            pss00-=W20*G20+W21*G21;
            pss01-=W20*G30+W21*G31;
            pss11-=W30*G30+W31*G31;
        }
        pTf[0]=puu00; pTf[1]=puu01; pTf[2]=pus00; pTf[3]=pus01;
        pTf[4]=puu01; pTf[5]=puu11; pTf[6]=pus10; pTf[7]=pus11;
        pTf[8]=pus00; pTf[9]=pus10; pTf[10]=pss00; pTf[11]=pss01;
        pTf[12]=pus01; pTf[13]=pus11; pTf[14]=pss01; pTf[15]=pss11;
    }
    __syncthreads();

    // ---- pass 1: per-chunk affine composition of the mean map ----
    float Eo[16]={1,0,0,0, 0,1,0,0, 0,0,1,0, 0,0,0,1};
    float bo[4]={0,0,0,0};
    #pragma unroll
    for(int k=0;k<CH;++k){
        int t=c*CH+k;
        float4 ka = g_kv[t*3+0];
        float4 kb = g_kv[t*3+1];
        // N = I - K H rows
        float N0[4]={1.0f-ka.x, -ka.y, -cst*ka.x, -cst*ka.y};
        float N1[4]={-ka.z, 1.0f-ka.w, -cst*ka.z, -cst*ka.w};
        float N2[4]={-kb.x, -kb.y, 1.0f-cst*kb.x, -cst*kb.y};
        float N3[4]={-kb.z, -kb.w, -cst*kb.z, 1.0f-cst*kb.w};
        float Ek[16];
        Ek[0]=N0[0]; Ek[1]=N0[1]; Ek[2]=N0[2]*A00+N0[3]*A01; Ek[3]=N0[2]*A10+N0[3]*A11;
        Ek[4]=N1[0]; Ek[5]=N1[1]; Ek[6]=N1[2]*A00+N1[3]*A01; Ek[7]=N1[2]*A10+N1[3]*A11;
        Ek[8]=N2[0]; Ek[9]=N2[1]; Ek[10]=N2[2]*A00+N2[3]*A01; Ek[11]=N2[2]*A10+N2[3]*A11;
        Ek[12]=N3[0]; Ek[13]=N3[1]; Ek[14]=N3[2]*A00+N3[3]*A01; Ek[15]=N3[2]*A10+N3[3]*A11;
        float y=sig[k];
        float bs_[4]={(ka.x+ka.y)*y,(ka.z+ka.w)*y,(kb.x+kb.y)*y,(kb.z+kb.w)*y};
        float En[16], bn[4];
        #pragma unroll
        for(int i=0;i<4;++i){
            #pragma unroll
            for(int j=0;j<4;++j)
                En[i*4+j]=Ek[i*4]*Eo[j]+Ek[i*4+1]*Eo[4+j]+Ek[i*4+2]*Eo[8+j]+Ek[i*4+3]*Eo[12+j];
            bn[i]=Ek[i*4]*bo[0]+Ek[i*4+1]*bo[1]+Ek[i*4+2]*bo[2]+Ek[i*4+3]*bo[3]+bs_[i];
        }
        #pragma unroll
        for(int i=0;i<16;++i) Eo[i]=En[i];
        #pragma unroll
        for(int i=0;i<4;++i) bo[i]=bn[i];
    }
    #pragma unroll
    for(int i=0;i<16;++i) elems[c*20+i]=Eo[i];
    #pragma unroll
    for(int i=0;i<4;++i) elems[c*20+16+i]=bo[i];
    __syncthreads();

    // ---- Hillis-Steele inclusive scan over 256 affine elements ----
    for(int off=1; off<NTH; off<<=1){
        float El[16], bl[4];
        bool act = (c>=off);
        if(act){
            const float* lp=elems+(c-off)*20;
            #pragma unroll
            for(int i=0;i<16;++i) El[i]=lp[i];
            #pragma unroll
            for(int i=0;i<4;++i) bl[i]=lp[16+i];
        }
        __syncthreads();
        if(act){
            float En[16], bn[4];
            #pragma unroll
            for(int i=0;i<4;++i){
                #pragma unroll
                for(int j=0;j<4;++j)
                    En[i*4+j]=Eo[i*4]*El[j]+Eo[i*4+1]*El[4+j]+Eo[i*4+2]*El[8+j]+Eo[i*4+3]*El[12+j];
                bn[i]=Eo[i*4]*bl[0]+Eo[i*4+1]*bl[1]+Eo[i*4+2]*bl[2]+Eo[i*4+3]*bl[3]+bo[i];
            }
            #pragma unroll
            for(int i=0;i<16;++i){ Eo[i]=En[i]; elems[c*20+i]=En[i]; }
            #pragma unroll
            for(int i=0;i<4;++i){ bo[i]=bn[i]; elems[c*20+16+i]=bn[i]; }
        }
        __syncthreads();
    }

    // ---- replay: quads + logdets in parallel ----
    float m0=0.f,m1=0.f,m2=0.f,m3=0.f;
    if(c>0){
        const float* pp=elems+(c-1)*20+16;
        m0=pp[0]; m1=pp[1]; m2=pp[2]; m3=pp[3];
    }
    double qd=0.0;
    float prodm=1.0f;
    int eacc=0;
    #pragma unroll
    for(int k=0;k<CH;++k){
        int t=c*CH+k;
        float4 ka = g_kv[t*3+0];
        float4 kb = g_kv[t*3+1];
        float4 sc = g_kv[t*3+2];
        // predict mean
        float p2=A00*m2+A10*m3;
        float p3=A01*m2+A11*m3;
        float y=sig[k];
        float z0=y-m0-cst*p2;
        float z1=y-m1-cst*p3;
        float id=sc.w;
        float u0=(sc.z*z0-sc.y*z1)*id;   // (S11 z0 - S01 z1)/det
        float u1=(sc.x*z1-sc.y*z0)*id;   // (S00 z1 - S01 z0)/det
        qd += (double)(z0*u0+z1*u1);
        float det=sc.x*sc.z-sc.y*sc.y;
        int bi=__float_as_int(det);
        eacc += ((bi>>23)&255)-127;
        prodm *= __int_as_float((bi&0x807FFFFF)|0x3F800000);
        int pb=__float_as_int(prodm);
        eacc += ((pb>>23)&255)-127;
        prodm = __int_as_float((pb&0x807FFFFF)|0x3F800000);
        // update mean: m += K z
        m0 += ka.x*z0+ka.y*z1;
        m1 += ka.z*z0+ka.w*z1;
        m2  = p2 + kb.x*z0+kb.y*z1;
        m3  = p3 + kb.z*z0+kb.w*z1;
    }
    double ldt=(double)eacc*0.6931471805599453 + log((double)prodm);

    dbl[c]=qd;
    __syncthreads();
    if(c==0){
        double acc=0.0;
        for(int i=0;i<NTH;++i) acc+=dbl[i];
        dbl[NTH+1]=acc;       // s_qd
    }
    __syncthreads();
    dbl[c]=ldt;
    __syncthreads();

    if(c==0){
        double ld2=0.0;
        for(int i=0;i<NTH;++i) ld2+=dbl[i];
        double s_wq=dbl[NTH], s_qd=dbl[NTH+1];
        double Td=(double)T, rr_=(double)r;
        double a0d=rr_/(double)bs0, a1d=rr_/(double)bs1, aud=rr_/(double)bsu;
        const double LOG2PI=1.8378770664093453;
        double ld_contrast=15.0*(4.0*Td*log(rr_)+2.0*log((a0d+Td)/a0d)+2.0*log((a1d+Td)/a1d));
        double ld_diff=2.0*(Td*log(rr_)+log((aud+Td)/aud));
        double logp=-0.5*(64.0*Td*LOG2PI)-0.5*(s_qd+2.0*s_wq)-0.5*(ld2+ld_contrast+ld_diff);
        shr[19]=(float)logp;

        // invert final filtered 4x4 covariance (Gauss-Jordan, pivoted — R2-proven)
        float Mm[4][8];
        for(int i=0;i<4;++i)
            for(int j=0;j<4;++j){ Mm[i][j]=pTf[i*4+j]; Mm[i][4+j]=(i==j)?1.0f:0.0f; }
        for(int cc=0;cc<4;++cc){
            int piv=cc; float mx=fabsf(Mm[cc][cc]);
            for(int rr=cc+1;rr<4;++rr){
                float aa=fabsf(Mm[rr][cc]);
                if(aa>mx){mx=aa;piv=rr;}
            }
            if(piv!=cc)
                for(int j=0;j<8;++j){ float tm=Mm[cc][j]; Mm[cc][j]=Mm[piv][j]; Mm[piv][j]=tm; }
            float pv=1.0f/Mm[cc][cc];
            for(int j=0;j<8;++j) Mm[cc][j]*=pv;
            for(int rr=0;rr<4;++rr){
                if(rr==cc) continue;
                float f=Mm[rr][cc];
                for(int j=0;j<8;++j) Mm[rr][j]-=f*Mm[cc][j];
            }
        }
        for(int i=0;i<4;++i)
            for(int j=0;j<4;++j) shr[i*4+j]=Mm[i][4+j];
        shr[16]=(float)(1.0/(double)bs0+Td/rr_);
        shr[17]=(float)(1.0/(double)bs1+Td/rr_);
        shr[18]=(float)(1.0/(double)bsu+Td/rr_);
    }
    __syncthreads();

    // ---- output: out[0]=logp, out[1..]=66x66 precision (R2-proven mapping) ----
    if(c==0 && out_size>0) out[0]=shr[19];
    const int NP=66*66;
    const float INV32=0.03125f;
    const float INVS32=0.17677669529663687f;
    for(int idx=c; idx<NP; idx+=NTH){
        if(idx+1>=out_size) break;
        int i=idx/66, j=idx-66*i;
        float v;
        if(i<64 && j<64){
            int pi=i>>5, pj=j>>5, ei=i&1, ej=j&1;
            v=shr[pi*4+pj]*INV32;
            if(pi==pj){
                v += ((ei==ej)?shr[18]:-shr[18])*INV32;
                if(ei==ej){
                    v -= shr[16+ei]*0.0625f;
                    if(i==j) v += shr[16+ei];
                }
            }
        } else if(i<64){
            int pi=i>>5;
            v=shr[pi*4+2+(j-64)]*INVS32;
        } else if(j<64){
            int pj=j>>5;
            v=shr[pj*4+2+(i-64)]*INVS32;
        } else {
            v=shr[(2+i-64)*4+(2+j-64)];
        }
        out[1+idx]=v;
    }
}

extern "C" void kernel_launch(void* const* d_in, const int* in_sizes, int n_in,
                              void* d_out, int out_size) {
    const float* track     = (const float*)d_in[0];
    const float* bias_sc   = (const float*)d_in[1];
    const float* obs_noise = (const float*)d_in[2];
    const float* trans_n   = (const float*)d_in[3];
    const float* A         = (const float*)d_in[4];
    const float* init_cov  = (const float*)d_in[5];
    float* out = (float*)d_out;
    int T = in_sizes[0]/2;
    if (T > TT) T = TT;
    hmm_hyb<<<1, NTH>>>(track, bias_sc, obs_noise, trans_n, A, init_cov,
                        out, T, out_size);
}

// round 8
// speedup vs baseline: 15.3266x; 2.5432x over previous
#include <cuda_runtime.h>
#include <math.h>

#define NTH 256
#define CH 16
#define TT 4096
#define T0 1024

__device__ float4 g_kv[TT*3];

__device__ __forceinline__ void dinv4(const double* m, double* inv){
    double Mm[4][8];
    for(int i=0;i<4;++i)
        for(int j=0;j<4;++j){ Mm[i][j]=m[i*4+j]; Mm[i][4+j]=(i==j)?1.0:0.0; }
    for(int cc=0;cc<4;++cc){
        int piv=cc; double mx=fabs(Mm[cc][cc]);
        for(int rr=cc+1;rr<4;++rr){
            double aa=fabs(Mm[rr][cc]);
            if(aa>mx){mx=aa;piv=rr;}
        }
        if(piv!=cc)
            for(int j=0;j<8;++j){ double tm=Mm[cc][j]; Mm[cc][j]=Mm[piv][j]; Mm[piv][j]=tm; }
        double pv=1.0/Mm[cc][cc];
        for(int j=0;j<8;++j) Mm[cc][j]*=pv;
        for(int rr=0;rr<4;++rr){
            if(rr==cc) continue;
            double f=Mm[rr][cc];
            for(int j=0;j<8;++j) Mm[rr][j]-=f*Mm[cc][j];
        }
    }
    for(int i=0;i<4;++i)
        for(int j=0;j<4;++j) inv[i*4+j]=Mm[i][4+j];
}

__global__ void __launch_bounds__(NTH,1)
hmm_hyb2(const float* __restrict__ track, const float* __restrict__ bias_scales,
         const float* __restrict__ obs_noise, const float* __restrict__ trans_noise,
         const float* __restrict__ Ain, const float* __restrict__ init_cov,
         float* __restrict__ out, int T, int out_size)
{
    __shared__ float elems[NTH*20];
    __shared__ double dbl[NTH+4];
    __shared__ double lamW[20];   // [0..15] Lambda_pred(t0), [16..18] Wbb (00,01,11)
    __shared__ float wtot[8];
    __shared__ float pTf[16];
    __shared__ float shr[24];

    const int c = threadIdx.x;
    const int lane = c&31, wid = c>>5;
    const float SQ8 = 2.8284271247461903f;
    const float cst = 5.656854249492381f;   // 4*sqrt(2)

    const float bs0=bias_scales[0], bs1=bias_scales[1];
    const float bsu=0.5f*(bs0+bs1);
    const float r=obs_noise[0]*obs_noise[0];
    const float q=trans_noise[0]*trans_noise[0];
    const float A00=Ain[0], A01=Ain[1], A10=Ain[2], A11=Ain[3];

    const int t0 = (T >= T0) ? T0 : T;

    // per-thread chunk data in registers
    float sig[CH], del[CH];
    #pragma unroll
    for(int k=0;k<CH;++k){
        int t=c*CH+k;
        float x0 = (t<T)?track[2*t]:0.0f;
        float x1 = (t<T)?track[2*t+1]:0.0f;
        sig[k]=SQ8*(x0+x1);
        del[k]=SQ8*(x0-x1);
    }

    // ---- phase 1: diff channel prefix scan (proven) ----
    {
        const float adf=r/bsu;
        float s=0.0f;
        #pragma unroll
        for(int k=0;k<CH;++k) s+=del[k];
        float v=s;
        #pragma unroll
        for(int off=1;off<32;off<<=1){
            float n=__shfl_up_sync(0xffffffffu,v,off);
            if(lane>=off) v+=n;
        }
        if(lane==31) wtot[wid]=v;
        __syncthreads();
        if(wid==0 && lane<8){
            float orig=wtot[lane], w=orig;
            #pragma unroll
            for(int off=1;off<8;off<<=1){
                float n=__shfl_up_sync(0xffu,w,off);
                if(lane>=off) w+=n;
            }
            wtot[lane]=w-orig;
        }
        __syncthreads();
        float run=(v-s)+wtot[wid];
        double wq=0.0;
        #pragma unroll
        for(int k=0;k<CH;++k){
            int t=c*CH+k;
            if(t<T){
                float at=adf+(float)t;
                float zd=del[k]-run/at;
                wq += (double)(zd*zd*at/(r*(at+1.0f)));
            }
            run+=del[k];
        }
        dbl[c]=wq;
        __syncthreads();
        if(c==0){
            double acc=0.0;
            for(int i=0;i<NTH;++i) acc+=dbl[i];
            dbl[NTH]=acc;         // s_wq
        }
        __syncthreads();
    }

    // ---- phase 2: thread 0 sequential covariance Riccati, t < t0 (proven math) ----
    if(c==0){
        float puu00=bsu, puu01=0.0f, puu11=bsu;
        float pus00=0.f, pus01=0.f, pus10=0.f, pus11=0.f;
        float pss00=init_cov[0], pss01=init_cov[1], pss11=init_cov[3];
        const float c2=32.0f;
        float4* gp = g_kv;
        for(int t=0;t<t0;++t){
            float b00=pss00*A00+pss01*A10;
            float b01=pss00*A01+pss01*A11;
            float b10=pss01*A00+pss11*A10;
            float b11=pss01*A01+pss11*A11;
            pss00=A00*b00+A10*b10+q;
            pss01=A00*b01+A10*b11;
            pss11=A01*b01+A11*b11+q;
            float t00=pus00*A00+pus01*A10;
            float t01=pus00*A01+pus01*A11;
            float t10=pus10*A00+pus11*A10;
            float t11=pus10*A01+pus11*A11;
            pus00=t00;pus01=t01;pus10=t10;pus11=t11;
            float S00=puu00+2.0f*cst*pus00+c2*pss00+r;
            float S01=puu01+cst*(pus01+pus10)+c2*pss01;
            float S11=puu11+2.0f*cst*pus11+c2*pss11+r;
            float det=S00*S11-S01*S01;
            float id=1.0f/det;
            float G00=puu00+cst*pus00, G01=puu01+cst*pus01;
            float G10=puu01+cst*pus10, G11=puu11+cst*pus11;
            float G20=pus00+cst*pss00, G21=pus10+cst*pss01;
            float G30=pus01+cst*pss01, G31=pus11+cst*pss11;
            float W00=(G00*S11-G01*S01)*id, W01=(G01*S00-G00*S01)*id;
            float W10=(G10*S11-G11*S01)*id, W11=(G11*S00-G10*S01)*id;
            float W20=(G20*S11-G21*S01)*id, W21=(G21*S00-G20*S01)*id;
            float W30=(G30*S11-G31*S01)*id, W31=(G31*S00-G30*S01)*id;
            gp[0]=make_float4(W00,W01,W10,W11);
            gp[1]=make_float4(W20,W21,W30,W31);
            gp[2]=make_float4(S00,S01,S11,id);
            gp+=3;
            puu00-=W00*G00+W01*G01;
            puu01-=W00*G10+W01*G11;
            puu11-=W10*G10+W11*G11;
            pus00-=W00*G20+W01*G21;
            pus01-=W00*G30+W01*G31;
            pus10-=W10*G20+W11*G21;
            pus11-=W10*G30+W11*G31;
            pss00-=W20*G20+W21*G21;
            pss01-=W20*G30+W21*G31;
            pss11-=W30*G30+W31*G31;
        }
        if(t0==T){
            pTf[0]=puu00; pTf[1]=puu01; pTf[2]=pus00; pTf[3]=pus01;
            pTf[4]=puu01; pTf[5]=puu11; pTf[6]=pus10; pTf[7]=pus11;
            pTf[8]=pus00; pTf[9]=pus10; pTf[10]=pss00; pTf[11]=pss01;
            pTf[12]=pus01; pTf[13]=pus11; pTf[14]=pss01; pTf[15]=pss11;
        } else {
            // ---- one-time double bridge: Lambda_pred(t0), Lambda_pred(t0+1), Wbb ----
            double dA00=A00, dA01=A01, dA10=A10, dA11=A11;
            double dq=q, dr=r, dc=5.65685424949238019521;  // 4*sqrt(2)
            double uu00=puu00, uu01=puu01, uu11=puu11;
            double us00=pus00, us01=pus01, us10=pus10, us11=pus11;
            double ss00=pss00, ss01=pss01, ss11=pss11;
            double L0[16], L1[16], M[16];
            for(int rep=0;rep<2;++rep){
                // predict
                double b00=ss00*dA00+ss01*dA10, b01=ss00*dA01+ss01*dA11;
                double b10=ss01*dA00+ss11*dA10, b11=ss01*dA01+ss11*dA11;
                ss00=dA00*b00+dA10*b10+dq;
                ss01=dA00*b01+dA10*b11;
                ss11=dA01*b01+dA11*b11+dq;
                double t00=us00*dA00+us01*dA10, t01=us00*dA01+us01*dA11;
                double t10=us10*dA00+us11*dA10, t11=us10*dA01+us11*dA11;
                us00=t00;us01=t01;us10=t10;us11=t11;
                // Lambda_pred = inv(P_pred)
                M[0]=uu00; M[1]=uu01; M[2]=us00; M[3]=us01;
                M[4]=uu01; M[5]=uu11; M[6]=us10; M[7]=us11;
                M[8]=us00; M[9]=us10; M[10]=ss00; M[11]=ss01;
                M[12]=us01; M[13]=us11; M[14]=ss01; M[15]=ss11;
                dinv4(M, (rep==0)?L0:L1);
                if(rep==1) break;
                // downdate (double)
                double S00=uu00+2.0*dc*us00+32.0*ss00+dr;
                double S01=uu01+dc*(us01+us10)+32.0*ss01;
                double S11=uu11+2.0*dc*us11+32.0*ss11+dr;
                double id=1.0/(S00*S11-S01*S01);
                double G00=uu00+dc*us00, G01=uu01+dc*us01;
                double G10=uu01+dc*us10, G11=uu11+dc*us11;
                double G20=us00+dc*ss00, G21=us10+dc*ss01;
                double G30=us01+dc*ss01, G31=us11+dc*ss11;
                double W00=(G00*S11-G01*S01)*id, W01=(G01*S00-G00*S01)*id;
                double W10=(G10*S11-G11*S01)*id, W11=(G11*S00-G10*S01)*id;
                double W20=(G20*S11-G21*S01)*id, W21=(G21*S00-G20*S01)*id;
                double W30=(G30*S11-G31*S01)*id, W31=(G31*S00-G30*S01)*id;
                uu00-=W00*G00+W01*G01;
                uu01-=W00*G10+W01*G11;
                uu11-=W10*G10+W11*G11;
                us00-=W00*G20+W01*G21;
                us01-=W00*G30+W01*G31;
                us10-=W10*G20+W11*G21;
                us11-=W10*G30+W11*G31;
                ss00-=W20*G20+W21*G21;
                ss01-=W20*G30+W21*G31;
                ss11-=W30*G30+W31*G31;
            }
            for(int i=0;i<16;++i) lamW[i]=L0[i];
            lamW[16]=L1[0]-L0[0];
            lamW[17]=L1[1]-L0[1];
            lamW[18]=L1[5]-L0[5];
        }
    }
    __syncthreads();

    // ---- phase 2b: parallel gain fill for t >= t0 ----
    if(t0 < T && c*CH >= t0){
        const float c2=32.0f;
        const int last_owner = (T-1)/CH;
        #pragma unroll
        for(int k=0;k<CH;++k){
            int t=c*CH+k;
            double kd=(double)(t-t0);
            float l00=(float)(lamW[0]+kd*lamW[16]);
            float l01=(float)(lamW[1]+kd*lamW[17]);
            float l11=(float)(lamW[5]+kd*lamW[18]);
            float l02=(float)lamW[2],  l03=(float)lamW[3];
            float l12=(float)lamW[6],  l13=(float)lamW[7];
            float l22=(float)lamW[10], l23=(float)lamW[11], l33=(float)lamW[15];
            // X = inv(Lambda_bb)
            float iX=1.0f/(l00*l11-l01*l01);
            float X00=l11*iX, X01=-l01*iX, X11=l00*iX;
            // B1 = X * Lambda_bs
            float B100=X00*l02+X01*l12, B101=X00*l03+X01*l13;
            float B110=X01*l02+X11*l12, B111=X01*l03+X11*l13;
            // Sp = Lambda_ss - Lambda_sb * B1
            float Sp00=l22-(l02*B100+l12*B110);
            float Sp01=l23-(l02*B101+l12*B111);
            float Sp11=l33-(l03*B101+l13*B111);
            float iS=1.0f/(Sp00*Sp11-Sp01*Sp01);
            float Z00=Sp11*iS, Z01=-Sp01*iS, Z11=Sp00*iS;
            // P_pred blocks
            float pus00=-(B100*Z00+B101*Z01);
            float pus01=-(B100*Z01+B101*Z11);
            float pus10=-(B110*Z00+B111*Z01);
            float pus11=-(B110*Z01+B111*Z11);
            float puu00=X00-(pus00*B100+pus01*B101);
            float puu01=X01-(pus00*B110+pus01*B111);
            float puu11=X11-(pus10*B110+pus11*B111);
            float pss00=Z00, pss01=Z01, pss11=Z11;
            // gains (verbatim proven formulas)
            float S00=puu00+2.0f*cst*pus00+c2*pss00+r;
            float S01=puu01+cst*(pus01+pus10)+c2*pss01;
            float S11=puu11+2.0f*cst*pus11+c2*pss11+r;
            float det=S00*S11-S01*S01;
            float id=1.0f/det;
            float G00=puu00+cst*pus00, G01=puu01+cst*pus01;
            float G10=puu01+cst*pus10, G11=puu11+cst*pus11;
            float G20=pus00+cst*pss00, G21=pus10+cst*pss01;
            float G30=pus01+cst*pss01, G31=pus11+cst*pss11;
            float W00=(G00*S11-G01*S01)*id, W01=(G01*S00-G00*S01)*id;
            float W10=(G10*S11-G11*S01)*id, W11=(G11*S00-G10*S01)*id;
            float W20=(G20*S11-G21*S01)*id, W21=(G21*S00-G20*S01)*id;
            float W30=(G30*S11-G31*S01)*id, W31=(G31*S00-G30*S01)*id;
            g_kv[t*3+0]=make_float4(W00,W01,W10,W11);
            g_kv[t*3+1]=make_float4(W20,W21,W30,W31);
            g_kv[t*3+2]=make_float4(S00,S01,S11,id);
            if(c==last_owner && t==T-1){
                pTf[0]=puu00-(W00*G00+W01*G01);
                pTf[1]=puu01-(W00*G10+W01*G11);
                pTf[5]=puu11-(W10*G10+W11*G11);
                pTf[2]=pus00-(W00*G20+W01*G21);
                pTf[3]=pus01-(W00*G30+W01*G31);
                pTf[6]=pus10-(W10*G20+W11*G21);
                pTf[7]=pus11-(W10*G30+W11*G31);
                pTf[10]=pss00-(W20*G20+W21*G21);
                pTf[11]=pss01-(W20*G30+W21*G31);
                pTf[15]=pss11-(W30*G30+W31*G31);
                pTf[4]=pTf[1]; pTf[8]=pTf[2]; pTf[9]=pTf[6];
                pTf[12]=pTf[3]; pTf[13]=pTf[7]; pTf[14]=pTf[11];
            }
        }
    }
    __syncthreads();

    // ---- pass 1: per-chunk affine composition of the mean map (proven) ----
    float Eo[16]={1,0,0,0, 0,1,0,0, 0,0,1,0, 0,0,0,1};
    float bo[4]={0,0,0,0};
    #pragma unroll
    for(int k=0;k<CH;++k){
        int t=c*CH+k;
        float4 ka = g_kv[t*3+0];
        float4 kb = g_kv[t*3+1];
        float N0[4]={1.0f-ka.x, -ka.y, -cst*ka.x, -cst*ka.y};
        float N1[4]={-ka.z, 1.0f-ka.w, -cst*ka.z, -cst*ka.w};
        float N2[4]={-kb.x, -kb.y, 1.0f-cst*kb.x, -cst*kb.y};
        float N3[4]={-kb.z, -kb.w, -cst*kb.z, 1.0f-cst*kb.w};
        float Ek[16];
        Ek[0]=N0[0]; Ek[1]=N0[1]; Ek[2]=N0[2]*A00+N0[3]*A01; Ek[3]=N0[2]*A10+N0[3]*A11;
        Ek[4]=N1[0]; Ek[5]=N1[1]; Ek[6]=N1[2]*A00+N1[3]*A01; Ek[7]=N1[2]*A10+N1[3]*A11;
        Ek[8]=N2[0]; Ek[9]=N2[1]; Ek[10]=N2[2]*A00+N2[3]*A01; Ek[11]=N2[2]*A10+N2[3]*A11;
        Ek[12]=N3[0]; Ek[13]=N3[1]; Ek[14]=N3[2]*A00+N3[3]*A01; Ek[15]=N3[2]*A10+N3[3]*A11;
        float y=sig[k];
        float bs_[4]={(ka.x+ka.y)*y,(ka.z+ka.w)*y,(kb.x+kb.y)*y,(kb.z+kb.w)*y};
        float En[16], bn[4];
        #pragma unroll
        for(int i=0;i<4;++i){
            #pragma unroll
            for(int j=0;j<4;++j)
                En[i*4+j]=Ek[i*4]*Eo[j]+Ek[i*4+1]*Eo[4+j]+Ek[i*4+2]*Eo[8+j]+Ek[i*4+3]*Eo[12+j];
            bn[i]=Ek[i*4]*bo[0]+Ek[i*4+1]*bo[1]+Ek[i*4+2]*bo[2]+Ek[i*4+3]*bo[3]+bs_[i];
        }
        #pragma unroll
        for(int i=0;i<16;++i) Eo[i]=En[i];
        #pragma unroll
        for(int i=0;i<4;++i) bo[i]=bn[i];
    }
    #pragma unroll
    for(int i=0;i<16;++i) elems[c*20+i]=Eo[i];
    #pragma unroll
    for(int i=0;i<4;++i) elems[c*20+16+i]=bo[i];
    __syncthreads();

    // ---- Hillis-Steele inclusive scan over 256 affine elements (proven) ----
    for(int off=1; off<NTH; off<<=1){
        float El[16], bl[4];
        bool act = (c>=off);
        if(act){
            const float* lp=elems+(c-off)*20;
            #pragma unroll
            for(int i=0;i<16;++i) El[i]=lp[i];
            #pragma unroll
            for(int i=0;i<4;++i) bl[i]=lp[16+i];
        }
        __syncthreads();
        if(act){
            float En[16], bn[4];
            #pragma unroll
            for(int i=0;i<4;++i){
                #pragma unroll
                for(int j=0;j<4;++j)
                    En[i*4+j]=Eo[i*4]*El[j]+Eo[i*4+1]*El[4+j]+Eo[i*4+2]*El[8+j]+Eo[i*4+3]*El[12+j];
                bn[i]=Eo[i*4]*bl[0]+Eo[i*4+1]*bl[1]+Eo[i*4+2]*bl[2]+Eo[i*4+3]*bl[3]+bo[i];
            }
            #pragma unroll
            for(int i=0;i<16;++i){ Eo[i]=En[i]; elems[c*20+i]=En[i]; }
            #pragma unroll
            for(int i=0;i<4;++i){ bo[i]=bn[i]; elems[c*20+16+i]=bn[i]; }
        }
        __syncthreads();
    }

    // ---- replay: quads + logdets in parallel (proven) ----
    float m0=0.f,m1=0.f,m2=0.f,m3=0.f;
    if(c>0){
        const float* pp=elems+(c-1)*20+16;
        m0=pp[0]; m1=pp[1]; m2=pp[2]; m3=pp[3];
    }
    double qd=0.0;
    float prodm=1.0f;
    int eacc=0;
    #pragma unroll
    for(int k=0;k<CH;++k){
        int t=c*CH+k;
        float4 ka = g_kv[t*3+0];
        float4 kb = g_kv[t*3+1];
        float4 sc = g_kv[t*3+2];
        float p2=A00*m2+A10*m3;
        float p3=A01*m2+A11*m3;
        float y=sig[k];
        float z0=y-m0-cst*p2;
        float z1=y-m1-cst*p3;
        float id=sc.w;
        float u0=(sc.z*z0-sc.y*z1)*id;
        float u1=(sc.x*z1-sc.y*z0)*id;
        qd += (double)(z0*u0+z1*u1);
        float det=sc.x*sc.z-sc.y*sc.y;
        int bi=__float_as_int(det);
        eacc += ((bi>>23)&255)-127;
        prodm *= __int_as_float((bi&0x807FFFFF)|0x3F800000);
        int pb=__float_as_int(prodm);
        eacc += ((pb>>23)&255)-127;
        prodm = __int_as_float((pb&0x807FFFFF)|0x3F800000);
        m0 += ka.x*z0+ka.y*z1;
        m1 += ka.z*z0+ka.w*z1;
        m2  = p2 + kb.x*z0+kb.y*z1;
        m3  = p3 + kb.z*z0+kb.w*z1;
    }
    double ldt=(double)eacc*0.6931471805599453 + log((double)prodm);

    dbl[c]=qd;
    __syncthreads();
    if(c==0){
        double acc=0.0;
        for(int i=0;i<NTH;++i) acc+=dbl[i];
        dbl[NTH+1]=acc;       // s_qd
    }
    __syncthreads();
    dbl[c]=ldt;
    __syncthreads();

    if(c==0){
        double ld2=0.0;
        for(int i=0;i<NTH;++i) ld2+=dbl[i];
        double s_wq=dbl[NTH], s_qd=dbl[NTH+1];
        double Td=(double)T, rr_=(double)r;
        double a0d=rr_/(double)bs0, a1d=rr_/(double)bs1, aud=rr_/(double)bsu;
        const double LOG2PI=1.8378770664093453;
        double ld_contrast=15.0*(4.0*Td*log(rr_)+2.0*log((a0d+Td)/a0d)+2.0*log((a1d+Td)/a1d));
        double ld_diff=2.0*(Td*log(rr_)+log((aud+Td)/aud));
        double logp=-0.5*(64.0*Td*LOG2PI)-0.5*(s_qd+2.0*s_wq)-0.5*(ld2+ld_contrast+ld_diff);
        shr[19]=(float)logp;

        float Mm[4][8];
        for(int i=0;i<4;++i)
            for(int j=0;j<4;++j){ Mm[i][j]=pTf[i*4+j]; Mm[i][4+j]=(i==j)?1.0f:0.0f; }
        for(int cc=0;cc<4;++cc){
            int piv=cc; float mx=fabsf(Mm[cc][cc]);
            for(int rr=cc+1;rr<4;++rr){
                float aa=fabsf(Mm[rr][cc]);
                if(aa>mx){mx=aa;piv=rr;}
            }
            if(piv!=cc)
                for(int j=0;j<8;++j){ float tm=Mm[cc][j]; Mm[cc][j]=Mm[piv][j]; Mm[piv][j]=tm; }
            float pv=1.0f/Mm[cc][cc];
            for(int j=0;j<8;++j) Mm[cc][j]*=pv;
            for(int rr=0;rr<4;++rr){
                if(rr==cc) continue;
                float f=Mm[rr][cc];
                for(int j=0;j<8;++j) Mm[rr][j]-=f*Mm[cc][j];
            }
        }
        for(int i=0;i<4;++i)
            for(int j=0;j<4;++j) shr[i*4+j]=Mm[i][4+j];
        shr[16]=(float)(1.0/(double)bs0+Td/rr_);
        shr[17]=(float)(1.0/(double)bs1+Td/rr_);
        shr[18]=(float)(1.0/(double)bsu+Td/rr_);
    }
    __syncthreads();

    // ---- output: out[0]=logp, out[1..]=66x66 precision (proven mapping) ----
    if(c==0 && out_size>0) out[0]=shr[19];
    const int NP=66*66;
    const float INV32=0.03125f;
    const float INVS32=0.17677669529663687f;
    for(int idx=c; idx<NP; idx+=NTH){
        if(idx+1>=out_size) break;
        int i=idx/66, j=idx-66*i;
        float v;
        if(i<64 && j<64){
            int pi=i>>5, pj=j>>5, ei=i&1, ej=j&1;
            v=shr[pi*4+pj]*INV32;
            if(pi==pj){
                v += ((ei==ej)?shr[18]:-shr[18])*INV32;
                if(ei==ej){
                    v -= shr[16+ei]*0.0625f;
                    if(i==j) v += shr[16+ei];
                }
            }
        } else if(i<64){
            int pi=i>>5;
            v=shr[pi*4+2+(j-64)]*INVS32;
        } else if(j<64){
            int pj=j>>5;
            v=shr[pj*4+2+(i-64)]*INVS32;
        } else {
            v=shr[(2+i-64)*4+(2+j-64)];
        }
        out[1+idx]=v;
    }
}

extern "C" void kernel_launch(void* const* d_in, const int* in_sizes, int n_in,
                              void* d_out, int out_size) {
    const float* track     = (const float*)d_in[0];
    const float* bias_sc   = (const float*)d_in[1];
    const float* obs_noise = (const float*)d_in[2];
    const float* trans_n   = (const float*)d_in[3];
    const float* A         = (const float*)d_in[4];
    const float* init_cov  = (const float*)d_in[5];
    float* out = (float*)d_out;
    int T = in_sizes[0]/2;
    if (T > TT) T = TT;
    hmm_hyb2<<<1, NTH>>>(track, bias_sc, obs_noise, trans_n, A, init_cov,
                         out, T, out_size);
}

// round 9
// speedup vs baseline: 26.3681x; 1.7204x over previous
#include <cuda_runtime.h>
#include <math.h>

#define NTH 256
#define CH 16
#define TT 4096
#define T0 256

__device__ float4 g_kv[TT*3];

__device__ __forceinline__ void dinv4(const double* m, double* inv){
    double Mm[4][8];
    for(int i=0;i<4;++i)
        for(int j=0;j<4;++j){ Mm[i][j]=m[i*4+j]; Mm[i][4+j]=(i==j)?1.0:0.0; }
    for(int cc=0;cc<4;++cc){
        int piv=cc; double mx=fabs(Mm[cc][cc]);
        for(int rr=cc+1;rr<4;++rr){
            double aa=fabs(Mm[rr][cc]);
            if(aa>mx){mx=aa;piv=rr;}
        }
        if(piv!=cc)
            for(int j=0;j<8;++j){ double tm=Mm[cc][j]; Mm[cc][j]=Mm[piv][j]; Mm[piv][j]=tm; }
        double pv=1.0/Mm[cc][cc];
        for(int j=0;j<8;++j) Mm[cc][j]*=pv;
        for(int rr=0;rr<4;++rr){
            if(rr==cc) continue;
            double f=Mm[rr][cc];
            for(int j=0;j<8;++j) Mm[rr][j]-=f*Mm[cc][j];
        }
    }
    for(int i=0;i<4;++i)
        for(int j=0;j<4;++j) inv[i*4+j]=Mm[i][4+j];
}

// 4-way split serial reduction of NTH doubles (breaks DADD dependency chain)
__device__ __forceinline__ double red256(const double* a){
    double s0=0.0,s1=0.0,s2=0.0,s3=0.0;
    for(int i=0;i<NTH;i+=4){
        s0+=a[i]; s1+=a[i+1]; s2+=a[i+2]; s3+=a[i+3];
    }
    return (s0+s1)+(s2+s3);
}

__global__ void __launch_bounds__(NTH,1)
hmm_hyb3(const float* __restrict__ track, const float* __restrict__ bias_scales,
         const float* __restrict__ obs_noise, const float* __restrict__ trans_noise,
         const float* __restrict__ Ain, const float* __restrict__ init_cov,
         float* __restrict__ out, int T, int out_size)
{
    __shared__ float elems[NTH*20];
    __shared__ double dbl[NTH+4];
    __shared__ double lamW[20];   // [0..15] Lambda_pred(t0), [16..18] Wbb (00,01,11)
    __shared__ float wtot[8];
    __shared__ float pTf[16];
    __shared__ float shr[24];

    const int c = threadIdx.x;
    const int lane = c&31, wid = c>>5;
    const float SQ8 = 2.8284271247461903f;
    const float cst = 5.656854249492381f;   // 4*sqrt(2)

    const float bs0=bias_scales[0], bs1=bias_scales[1];
    const float bsu=0.5f*(bs0+bs1);
    const float r=obs_noise[0]*obs_noise[0];
    const float q=trans_noise[0]*trans_noise[0];
    const float A00=Ain[0], A01=Ain[1], A10=Ain[2], A11=Ain[3];

    const int t0 = (T >= T0) ? T0 : T;

    // per-thread chunk data in registers
    float sig[CH], del[CH];
    #pragma unroll
    for(int k=0;k<CH;++k){
        int t=c*CH+k;
        float x0 = (t<T)?track[2*t]:0.0f;
        float x1 = (t<T)?track[2*t+1]:0.0f;
        sig[k]=SQ8*(x0+x1);
        del[k]=SQ8*(x0-x1);
    }

    // ---- phase 1: diff channel prefix scan (proven) ----
    {
        const float adf=r/bsu;
        float s=0.0f;
        #pragma unroll
        for(int k=0;k<CH;++k) s+=del[k];
        float v=s;
        #pragma unroll
        for(int off=1;off<32;off<<=1){
            float n=__shfl_up_sync(0xffffffffu,v,off);
            if(lane>=off) v+=n;
        }
        if(lane==31) wtot[wid]=v;
        __syncthreads();
        if(wid==0 && lane<8){
            float orig=wtot[lane], w=orig;
            #pragma unroll
            for(int off=1;off<8;off<<=1){
                float n=__shfl_up_sync(0xffu,w,off);
                if(lane>=off) w+=n;
            }
            wtot[lane]=w-orig;
        }
        __syncthreads();
        float run=(v-s)+wtot[wid];
        double wq=0.0;
        #pragma unroll
        for(int k=0;k<CH;++k){
            int t=c*CH+k;
            if(t<T){
                float at=adf+(float)t;
                float zd=del[k]-run/at;
                wq += (double)(zd*zd*at/(r*(at+1.0f)));
            }
            run+=del[k];
        }
        dbl[c]=wq;
        __syncthreads();
        if(c==0) dbl[NTH]=red256(dbl);   // s_wq
        __syncthreads();
    }

    // ---- phase 2: thread 0 sequential covariance Riccati, t < t0 (proven math) ----
    if(c==0){
        float puu00=bsu, puu01=0.0f, puu11=bsu;
        float pus00=0.f, pus01=0.f, pus10=0.f, pus11=0.f;
        float pss00=init_cov[0], pss01=init_cov[1], pss11=init_cov[3];
        const float c2=32.0f;
        float4* gp = g_kv;
        for(int t=0;t<t0;++t){
            float b00=pss00*A00+pss01*A10;
            float b01=pss00*A01+pss01*A11;
            float b10=pss01*A00+pss11*A10;
            float b11=pss01*A01+pss11*A11;
            pss00=A00*b00+A10*b10+q;
            pss01=A00*b01+A10*b11;
            pss11=A01*b01+A11*b11+q;
            float t00=pus00*A00+pus01*A10;
            float t01=pus00*A01+pus01*A11;
            float t10=pus10*A00+pus11*A10;
            float t11=pus10*A01+pus11*A11;
            pus00=t00;pus01=t01;pus10=t10;pus11=t11;
            float S00=puu00+2.0f*cst*pus00+c2*pss00+r;
            float S01=puu01+cst*(pus01+pus10)+c2*pss01;
            float S11=puu11+2.0f*cst*pus11+c2*pss11+r;
            float det=S00*S11-S01*S01;
            float id=1.0f/det;
            float G00=puu00+cst*pus00, G01=puu01+cst*pus01;
            float G10=puu01+cst*pus10, G11=puu11+cst*pus11;
            float G20=pus00+cst*pss00, G21=pus10+cst*pss01;
            float G30=pus01+cst*pss01, G31=pus11+cst*pss11;
            float W00=(G00*S11-G01*S01)*id, W01=(G01*S00-G00*S01)*id;
            float W10=(G10*S11-G11*S01)*id, W11=(G11*S00-G10*S01)*id;
            float W20=(G20*S11-G21*S01)*id, W21=(G21*S00-G20*S01)*id;
            float W30=(G30*S11-G31*S01)*id, W31=(G31*S00-G30*S01)*id;
            gp[0]=make_float4(W00,W01,W10,W11);
            gp[1]=make_float4(W20,W21,W30,W31);
            gp[2]=make_float4(S00,S01,S11,id);
            gp+=3;
            puu00-=W00*G00+W01*G01;
            puu01-=W00*G10+W01*G11;
            puu11-=W10*G10+W11*G11;
            pus00-=W00*G20+W01*G21;
            pus01-=W00*G30+W01*G31;
            pus10-=W10*G20+W11*G21;
            pus11-=W10*G30+W11*G31;
            pss00-=W20*G20+W21*G21;
            pss01-=W20*G30+W21*G31;
            pss11-=W30*G30+W31*G31;
        }
        if(t0==T){
            pTf[0]=puu00; pTf[1]=puu01; pTf[2]=pus00; pTf[3]=pus01;
            pTf[4]=puu01; pTf[5]=puu11; pTf[6]=pus10; pTf[7]=pus11;
            pTf[8]=pus00; pTf[9]=pus10; pTf[10]=pss00; pTf[11]=pss01;
            pTf[12]=pus01; pTf[13]=pus11; pTf[14]=pss01; pTf[15]=pss11;
        } else {
            // ---- one-time double bridge: Lambda_pred(t0), Lambda_pred(t0+1), Wbb ----
            double dA00=A00, dA01=A01, dA10=A10, dA11=A11;
            double dq=q, dr=r, dc=5.65685424949238019521;  // 4*sqrt(2)
            double uu00=puu00, uu01=puu01, uu11=puu11;
            double us00=pus00, us01=pus01, us10=pus10, us11=pus11;
            double ss00=pss00, ss01=pss01, ss11=pss11;
            double L0[16], L1[16], M[16];
            for(int rep=0;rep<2;++rep){
                double b00=ss00*dA00+ss01*dA10, b01=ss00*dA01+ss01*dA11;
                double b10=ss01*dA00+ss11*dA10, b11=ss01*dA01+ss11*dA11;
                ss00=dA00*b00+dA10*b10+dq;
                ss01=dA00*b01+dA10*b11;
                ss11=dA01*b01+dA11*b11+dq;
                double t00=us00*dA00+us01*dA10, t01=us00*dA01+us01*dA11;
                double t10=us10*dA00+us11*dA10, t11=us10*dA01+us11*dA11;
                us00=t00;us01=t01;us10=t10;us11=t11;
                M[0]=uu00; M[1]=uu01; M[2]=us00; M[3]=us01;
                M[4]=uu01; M[5]=uu11; M[6]=us10; M[7]=us11;
                M[8]=us00; M[9]=us10; M[10]=ss00; M[11]=ss01;
                M[12]=us01; M[13]=us11; M[14]=ss01; M[15]=ss11;
                dinv4(M, (rep==0)?L0:L1);
                if(rep==1) break;
                double S00=uu00+2.0*dc*us00+32.0*ss00+dr;
                double S01=uu01+dc*(us01+us10)+32.0*ss01;
                double S11=uu11+2.0*dc*us11+32.0*ss11+dr;
                double id=1.0/(S00*S11-S01*S01);
                double G00=uu00+dc*us00, G01=uu01+dc*us01;
                double G10=uu01+dc*us10, G11=uu11+dc*us11;
                double G20=us00+dc*ss00, G21=us10+dc*ss01;
                double G30=us01+dc*ss01, G31=us11+dc*ss11;
                double W00=(G00*S11-G01*S01)*id, W01=(G01*S00-G00*S01)*id;
                double W10=(G10*S11-G11*S01)*id, W11=(G11*S00-G10*S01)*id;
                double W20=(G20*S11-G21*S01)*id, W21=(G21*S00-G20*S01)*id;
                double W30=(G30*S11-G31*S01)*id, W31=(G31*S00-G30*S01)*id;
                uu00-=W00*G00+W01*G01;
                uu01-=W00*G10+W01*G11;
                uu11-=W10*G10+W11*G11;
                us00-=W00*G20+W01*G21;
                us01-=W00*G30+W01*G31;
                us10-=W10*G20+W11*G21;
                us11-=W10*G30+W11*G31;
                ss00-=W20*G20+W21*G21;
                ss01-=W20*G30+W21*G31;
                ss11-=W30*G30+W31*G31;
            }
            for(int i=0;i<16;++i) lamW[i]=L0[i];
            lamW[16]=L1[0]-L0[0];
            lamW[17]=L1[1]-L0[1];
            lamW[18]=L1[5]-L0[5];
        }
    }
    __syncthreads();

    // ---- phase 2b: parallel gain fill for t >= t0 ----
    if(t0 < T && (c+1)*CH > t0){
        const float c2=32.0f;
        const int last_owner = (T-1)/CH;
        #pragma unroll
        for(int k=0;k<CH;++k){
            int t=c*CH+k;
            if(t < t0 || t >= T) continue;
            double kd=(double)(t-t0);
            float l00=(float)(lamW[0]+kd*lamW[16]);
            float l01=(float)(lamW[1]+kd*lamW[17]);
            float l11=(float)(lamW[5]+kd*lamW[18]);
            float l02=(float)lamW[2],  l03=(float)lamW[3];
            float l12=(float)lamW[6],  l13=(float)lamW[7];
            float l22=(float)lamW[10], l23=(float)lamW[11], l33=(float)lamW[15];
            float iX=1.0f/(l00*l11-l01*l01);
            float X00=l11*iX, X01=-l01*iX, X11=l00*iX;
            float B100=X00*l02+X01*l12, B101=X00*l03+X01*l13;
            float B110=X01*l02+X11*l12, B111=X01*l03+X11*l13;
            float Sp00=l22-(l02*B100+l12*B110);
            float Sp01=l23-(l02*B101+l12*B111);
            float Sp11=l33-(l03*B101+l13*B111);
            float iS=1.0f/(Sp00*Sp11-Sp01*Sp01);
            float Z00=Sp11*iS, Z01=-Sp01*iS, Z11=Sp00*iS;
            float pus00=-(B100*Z00+B101*Z01);
            float pus01=-(B100*Z01+B101*Z11);
            float pus10=-(B110*Z00+B111*Z01);
            float pus11=-(B110*Z01+B111*Z11);
            float puu00=X00-(pus00*B100+pus01*B101);
            float puu01=X01-(pus00*B110+pus01*B111);
            float puu11=X11-(pus10*B110+pus11*B111);
            float pss00=Z00, pss01=Z01, pss11=Z11;
            float S00=puu00+2.0f*cst*pus00+c2*pss00+r;
            float S01=puu01+cst*(pus01+pus10)+c2*pss01;
            float S11=puu11+2.0f*cst*pus11+c2*pss11+r;
            float det=S00*S11-S01*S01;
            float id=1.0f/det;
            float G00=puu00+cst*pus00, G01=puu01+cst*pus01;
            float G10=puu01+cst*pus10, G11=puu11+cst*pus11;
            float G20=pus00+cst*pss00, G21=pus10+cst*pss01;
            float G30=pus01+cst*pss01, G31=pus11+cst*pss11;
            float W00=(G00*S11-G01*S01)*id, W01=(G01*S00-G00*S01)*id;
            float W10=(G10*S11-G11*S01)*id, W11=(G11*S00-G10*S01)*id;
            float W20=(G20*S11-G21*S01)*id, W21=(G21*S00-G20*S01)*id;
            float W30=(G30*S11-G31*S01)*id, W31=(G31*S00-G30*S01)*id;
            g_kv[t*3+0]=make_float4(W00,W01,W10,W11);
            g_kv[t*3+1]=make_float4(W20,W21,W30,W31);
            g_kv[t*3+2]=make_float4(S00,S01,S11,id);
            if(c==last_owner && t==T-1){
                pTf[0]=puu00-(W00*G00+W01*G01);
                pTf[1]=puu01-(W00*G10+W01*G11);
                pTf[5]=puu11-(W10*G10+W11*G11);
                pTf[2]=pus00-(W00*G20+W01*G21);
                pTf[3]=pus01-(W00*G30+W01*G31);
                pTf[6]=pus10-(W10*G20+W11*G21);
                pTf[7]=pus11-(W10*G30+W11*G31);
                pTf[10]=pss00-(W20*G20+W21*G21);
                pTf[11]=pss01-(W20*G30+W21*G31);
                pTf[15]=pss11-(W30*G30+W31*G31);
                pTf[4]=pTf[1]; pTf[8]=pTf[2]; pTf[9]=pTf[6];
                pTf[12]=pTf[3]; pTf[13]=pTf[7]; pTf[14]=pTf[11];
            }
        }
    }
    __syncthreads();

    // ---- pass 1: per-chunk affine composition of the mean map (proven) ----
    float Eo[16]={1,0,0,0, 0,1,0,0, 0,0,1,0, 0,0,0,1};
    float bo[4]={0,0,0,0};
    #pragma unroll
    for(int k=0;k<CH;++k){
        int t=c*CH+k;
        float4 ka = g_kv[t*3+0];
        float4 kb = g_kv[t*3+1];
        float N0[4]={1.0f-ka.x, -ka.y, -cst*ka.x, -cst*ka.y};
        float N1[4]={-ka.z, 1.0f-ka.w, -cst*ka.z, -cst*ka.w};
        float N2[4]={-kb.x, -kb.y, 1.0f-cst*kb.x, -cst*kb.y};
        float N3[4]={-kb.z, -kb.w, -cst*kb.z, 1.0f-cst*kb.w};
        float Ek[16];
        Ek[0]=N0[0]; Ek[1]=N0[1]; Ek[2]=N0[2]*A00+N0[3]*A01; Ek[3]=N0[2]*A10+N0[3]*A11;
        Ek[4]=N1[0]; Ek[5]=N1[1]; Ek[6]=N1[2]*A00+N1[3]*A01; Ek[7]=N1[2]*A10+N1[3]*A11;
        Ek[8]=N2[0]; Ek[9]=N2[1]; Ek[10]=N2[2]*A00+N2[3]*A01; Ek[11]=N2[2]*A10+N2[3]*A11;
        Ek[12]=N3[0]; Ek[13]=N3[1]; Ek[14]=N3[2]*A00+N3[3]*A01; Ek[15]=N3[2]*A10+N3[3]*A11;
        float y=sig[k];
        float bs_[4]={(ka.x+ka.y)*y,(ka.z+ka.w)*y,(kb.x+kb.y)*y,(kb.z+kb.w)*y};
        float En[16], bn[4];
        #pragma unroll
        for(int i=0;i<4;++i){
            #pragma unroll
            for(int j=0;j<4;++j)
                En[i*4+j]=Ek[i*4]*Eo[j]+Ek[i*4+1]*Eo[4+j]+Ek[i*4+2]*Eo[8+j]+Ek[i*4+3]*Eo[12+j];
            bn[i]=Ek[i*4]*bo[0]+Ek[i*4+1]*bo[1]+Ek[i*4+2]*bo[2]+Ek[i*4+3]*bo[3]+bs_[i];
        }
        #pragma unroll
        for(int i=0;i<16;++i) Eo[i]=En[i];
        #pragma unroll
        for(int i=0;i<4;++i) bo[i]=bn[i];
    }
    #pragma unroll
    for(int i=0;i<16;++i) elems[c*20+i]=Eo[i];
    #pragma unroll
    for(int i=0;i<4;++i) elems[c*20+16+i]=bo[i];
    __syncthreads();

    // ---- Hillis-Steele inclusive scan over 256 affine elements (proven) ----
    for(int off=1; off<NTH; off<<=1){
        float El[16], bl[4];
        bool act = (c>=off);
        if(act){
            const float* lp=elems+(c-off)*20;
            #pragma unroll
            for(int i=0;i<16;++i) El[i]=lp[i];
            #pragma unroll
            for(int i=0;i<4;++i) bl[i]=lp[16+i];
        }
        __syncthreads();
        if(act){
            float En[16], bn[4];
            #pragma unroll
            for(int i=0;i<4;++i){
                #pragma unroll
                for(int j=0;j<4;++j)
                    En[i*4+j]=Eo[i*4]*El[j]+Eo[i*4+1]*El[4+j]+Eo[i*4+2]*El[8+j]+Eo[i*4+3]*El[12+j];
                bn[i]=Eo[i*4]*bl[0]+Eo[i*4+1]*bl[1]+Eo[i*4+2]*bl[2]+Eo[i*4+3]*bl[3]+bo[i];
            }
            #pragma unroll
            for(int i=0;i<16;++i){ Eo[i]=En[i]; elems[c*20+i]=En[i]; }
            #pragma unroll
            for(int i=0;i<4;++i){ bo[i]=bn[i]; elems[c*20+16+i]=bn[i]; }
        }
        __syncthreads();
    }

    // ---- replay: quads + logdets in parallel (proven) ----
    float m0=0.f,m1=0.f,m2=0.f,m3=0.f;
    if(c>0){
        const float* pp=elems+(c-1)*20+16;
        m0=pp[0]; m1=pp[1]; m2=pp[2]; m3=pp[3];
    }
    double qd=0.0;
    float prodm=1.0f;
    int eacc=0;
    #pragma unroll
    for(int k=0;k<CH;++k){
        int t=c*CH+k;
        float4 ka = g_kv[t*3+0];
        float4 kb = g_kv[t*3+1];
        float4 sc = g_kv[t*3+2];
        float p2=A00*m2+A10*m3;
        float p3=A01*m2+A11*m3;
        float y=sig[k];
        float z0=y-m0-cst*p2;
        float z1=y-m1-cst*p3;
        float id=sc.w;
        float u0=(sc.z*z0-sc.y*z1)*id;
        float u1=(sc.x*z1-sc.y*z0)*id;
        qd += (double)(z0*u0+z1*u1);
        float det=sc.x*sc.z-sc.y*sc.y;
        int bi=__float_as_int(det);
        eacc += ((bi>>23)&255)-127;
        prodm *= __int_as_float((bi&0x807FFFFF)|0x3F800000);
        int pb=__float_as_int(prodm);
        eacc += ((pb>>23)&255)-127;
        prodm = __int_as_float((pb&0x807FFFFF)|0x3F800000);
        m0 += ka.x*z0+ka.y*z1;
        m1 += ka.z*z0+ka.w*z1;
        m2  = p2 + kb.x*z0+kb.y*z1;
        m3  = p3 + kb.z*z0+kb.w*z1;
    }
    double ldt=(double)eacc*0.6931471805599453 + log((double)prodm);

    dbl[c]=qd;
    __syncthreads();
    if(c==0) dbl[NTH+1]=red256(dbl);   // s_qd
    __syncthreads();
    dbl[c]=ldt;
    __syncthreads();

    if(c==0){
        double ld2=red256(dbl);
        double s_wq=dbl[NTH], s_qd=dbl[NTH+1];
        double Td=(double)T, rr_=(double)r;
        double a0d=rr_/(double)bs0, a1d=rr_/(double)bs1, aud=rr_/(double)bsu;
        const double LOG2PI=1.8378770664093453;
        double ld_contrast=15.0*(4.0*Td*log(rr_)+2.0*log((a0d+Td)/a0d)+2.0*log((a1d+Td)/a1d));
        double ld_diff=2.0*(Td*log(rr_)+log((aud+Td)/aud));
        double logp=-0.5*(64.0*Td*LOG2PI)-0.5*(s_qd+2.0*s_wq)-0.5*(ld2+ld_contrast+ld_diff);
        shr[19]=(float)logp;

        float Mm[4][8];
        for(int i=0;i<4;++i)
            for(int j=0;j<4;++j){ Mm[i][j]=pTf[i*4+j]; Mm[i][4+j]=(i==j)?1.0f:0.0f; }
        for(int cc=0;cc<4;++cc){
            int piv=cc; float mx=fabsf(Mm[cc][cc]);
            for(int rr=cc+1;rr<4;++rr){
                float aa=fabsf(Mm[rr][cc]);
                if(aa>mx){mx=aa;piv=rr;}
            }
            if(piv!=cc)
                for(int j=0;j<8;++j){ float tm=Mm[cc][j]; Mm[cc][j]=Mm[piv][j]; Mm[piv][j]=tm; }
            float pv=1.0f/Mm[cc][cc];
            for(int j=0;j<8;++j) Mm[cc][j]*=pv;
            for(int rr=0;rr<4;++rr){
                if(rr==cc) continue;
                float f=Mm[rr][cc];
                for(int j=0;j<8;++j) Mm[rr][j]-=f*Mm[cc][j];
            }
        }
        for(int i=0;i<4;++i)
            for(int j=0;j<4;++j) shr[i*4+j]=Mm[i][4+j];
        shr[16]=(float)(1.0/(double)bs0+Td/rr_);
        shr[17]=(float)(1.0/(double)bs1+Td/rr_);
        shr[18]=(float)(1.0/(double)bsu+Td/rr_);
    }
    __syncthreads();

    // ---- output: out[0]=logp, out[1..]=66x66 precision (proven mapping) ----
    if(c==0 && out_size>0) out[0]=shr[19];
    const int NP=66*66;
    const float INV32=0.03125f;
    const float INVS32=0.17677669529663687f;
    for(int idx=c; idx<NP; idx+=NTH){
        if(idx+1>=out_size) break;
        int i=idx/66, j=idx-66*i;
        float v;
        if(i<64 && j<64){
            int pi=i>>5, pj=j>>5, ei=i&1, ej=j&1;
            v=shr[pi*4+pj]*INV32;
            if(pi==pj){
                v += ((ei==ej)?shr[18]:-shr[18])*INV32;
                if(ei==ej){
                    v -= shr[16+ei]*0.0625f;
                    if(i==j) v += shr[16+ei];
                }
            }
        } else if(i<64){
            int pi=i>>5;
            v=shr[pi*4+2+(j-64)]*INVS32;
        } else if(j<64){
            int pj=j>>5;
            v=shr[pj*4+2+(i-64)]*INVS32;
        } else {
            v=shr[(2+i-64)*4+(2+j-64)];
        }
        out[1+idx]=v;
    }
}

extern "C" void kernel_launch(void* const* d_in, const int* in_sizes, int n_in,
                              void* d_out, int out_size) {
    const float* track     = (const float*)d_in[0];
    const float* bias_sc   = (const float*)d_in[1];
    const float* obs_noise = (const float*)d_in[2];
    const float* trans_n   = (const float*)d_in[3];
    const float* A         = (const float*)d_in[4];
    const float* init_cov  = (const float*)d_in[5];
    float* out = (float*)d_out;
    int T = in_sizes[0]/2;
    if (T > TT) T = TT;
    hmm_hyb3<<<1, NTH>>>(track, bias_sc, obs_noise, trans_n, A, init_cov,
                         out, T, out_size);
}

// round 10
// speedup vs baseline: 41.2223x; 1.5633x over previous
#include <cuda_runtime.h>
#include <math.h>

#define NTH 256
#define CH 16
#define TT 4096
#define T0 128

__device__ float4 g_kv[TT*3];

__device__ __forceinline__ void dinv4(const double* m, double* inv){
    double Mm[4][8];
    for(int i=0;i<4;++i)
        for(int j=0;j<4;++j){ Mm[i][j]=m[i*4+j]; Mm[i][4+j]=(i==j)?1.0:0.0; }
    for(int cc=0;cc<4;++cc){
        int piv=cc; double mx=fabs(Mm[cc][cc]);
        for(int rr=cc+1;rr<4;++rr){
            double aa=fabs(Mm[rr][cc]);
            if(aa>mx){mx=aa;piv=rr;}
        }
        if(piv!=cc)
            for(int j=0;j<8;++j){ double tm=Mm[cc][j]; Mm[cc][j]=Mm[piv][j]; Mm[piv][j]=tm; }
        double pv=1.0/Mm[cc][cc];
        for(int j=0;j<8;++j) Mm[cc][j]*=pv;
        for(int rr=0;rr<4;++rr){
            if(rr==cc) continue;
            double f=Mm[rr][cc];
            for(int j=0;j<8;++j) Mm[rr][j]-=f*Mm[cc][j];
        }
    }
    for(int i=0;i<4;++i)
        for(int j=0;j<4;++j) inv[i*4+j]=Mm[i][4+j];
}

__device__ __forceinline__ float wred(float v){
    #pragma unroll
    for(int off=16; off; off>>=1) v += __shfl_down_sync(0xffffffffu, v, off);
    return v;
}

__global__ void __launch_bounds__(NTH,1)
hmm_hyb4(const float* __restrict__ track, const float* __restrict__ bias_scales,
         const float* __restrict__ obs_noise, const float* __restrict__ trans_noise,
         const float* __restrict__ Ain, const float* __restrict__ init_cov,
         float* __restrict__ out, int T, int out_size)
{
    __shared__ float elems[NTH*20];
    __shared__ float fw[8];
    __shared__ double sred[3];     // 0:s_wq 1:s_qd 2:ld2
    __shared__ float lamWf[20];    // [0..15] Lambda_pred(t0) fp32, [16..18] Wbb
    __shared__ float wtot[8];
    __shared__ float pTf[16];
    __shared__ float shr[24];

    const int c = threadIdx.x;
    const int lane = c&31, wid = c>>5;
    const float SQ8 = 2.8284271247461903f;
    const float cst = 5.656854249492381f;   // 4*sqrt(2)

    const float bs0=bias_scales[0], bs1=bias_scales[1];
    const float bsu=0.5f*(bs0+bs1);
    const float r=obs_noise[0]*obs_noise[0];
    const float q=trans_noise[0]*trans_noise[0];
    const float A00=Ain[0], A01=Ain[1], A10=Ain[2], A11=Ain[3];

    const int t0 = (T >= T0) ? T0 : T;

    // per-thread chunk data in registers
    float sig[CH], del[CH];
    #pragma unroll
    for(int k=0;k<CH;++k){
        int t=c*CH+k;
        float x0 = (t<T)?track[2*t]:0.0f;
        float x1 = (t<T)?track[2*t+1]:0.0f;
        sig[k]=SQ8*(x0+x1);
        del[k]=SQ8*(x0-x1);
    }

    // ---- phase 1: diff channel prefix scan (proven; fp32 accumulation) ----
    {
        const float adf=r/bsu;
        float s=0.0f;
        #pragma unroll
        for(int k=0;k<CH;++k) s+=del[k];
        float v=s;
        #pragma unroll
        for(int off=1;off<32;off<<=1){
            float n=__shfl_up_sync(0xffffffffu,v,off);
            if(lane>=off) v+=n;
        }
        if(lane==31) wtot[wid]=v;
        __syncthreads();
        if(wid==0 && lane<8){
            float orig=wtot[lane], w=orig;
            #pragma unroll
            for(int off=1;off<8;off<<=1){
                float n=__shfl_up_sync(0xffu,w,off);
                if(lane>=off) w+=n;
            }
            wtot[lane]=w-orig;
        }
        __syncthreads();
        float run=(v-s)+wtot[wid];
        float wq=0.0f;
        #pragma unroll
        for(int k=0;k<CH;++k){
            int t=c*CH+k;
            if(t<T){
                float at=adf+(float)t;
                float zd=del[k]-run/at;
                wq += zd*zd*at/(r*(at+1.0f));
            }
            run+=del[k];
        }
        float ws=wred(wq);
        if(lane==0) fw[wid]=ws;
        __syncthreads();
        if(c==0){
            double acc=0.0;
            for(int i=0;i<8;++i) acc+=(double)fw[i];
            sred[0]=acc;
        }
        __syncthreads();
    }

    // ---- phase 2: thread 0 sequential covariance Riccati, t < t0 (proven math) ----
    if(c==0){
        float puu00=bsu, puu01=0.0f, puu11=bsu;
        float pus00=0.f, pus01=0.f, pus10=0.f, pus11=0.f;
        float pss00=init_cov[0], pss01=init_cov[1], pss11=init_cov[3];
        const float c2=32.0f;
        float4* gp = g_kv;
        for(int t=0;t<t0;++t){
            float b00=pss00*A00+pss01*A10;
            float b01=pss00*A01+pss01*A11;
            float b10=pss01*A00+pss11*A10;
            float b11=pss01*A01+pss11*A11;
            pss00=A00*b00+A10*b10+q;
            pss01=A00*b01+A10*b11;
            pss11=A01*b01+A11*b11+q;
            float t00=pus00*A00+pus01*A10;
            float t01=pus00*A01+pus01*A11;
            float t10=pus10*A00+pus11*A10;
            float t11=pus10*A01+pus11*A11;
            pus00=t00;pus01=t01;pus10=t10;pus11=t11;
            float S00=puu00+2.0f*cst*pus00+c2*pss00+r;
            float S01=puu01+cst*(pus01+pus10)+c2*pss01;
            float S11=puu11+2.0f*cst*pus11+c2*pss11+r;
            float det=S00*S11-S01*S01;
            float id=1.0f/det;
            float G00=puu00+cst*pus00, G01=puu01+cst*pus01;
            float G10=puu01+cst*pus10, G11=puu11+cst*pus11;
            float G20=pus00+cst*pss00, G21=pus10+cst*pss01;
            float G30=pus01+cst*pss01, G31=pus11+cst*pss11;
            float W00=(G00*S11-G01*S01)*id, W01=(G01*S00-G00*S01)*id;
            float W10=(G10*S11-G11*S01)*id, W11=(G11*S00-G10*S01)*id;
            float W20=(G20*S11-G21*S01)*id, W21=(G21*S00-G20*S01)*id;
            float W30=(G30*S11-G31*S01)*id, W31=(G31*S00-G30*S01)*id;
            gp[0]=make_float4(W00,W01,W10,W11);
            gp[1]=make_float4(W20,W21,W30,W31);
            gp[2]=make_float4(S00,S01,S11,id);
            gp+=3;
            puu00-=W00*G00+W01*G01;
            puu01-=W00*G10+W01*G11;
            puu11-=W10*G10+W11*G11;
            pus00-=W00*G20+W01*G21;
            pus01-=W00*G30+W01*G31;
            pus10-=W10*G20+W11*G21;
            pus11-=W10*G30+W11*G31;
            pss00-=W20*G20+W21*G21;
            pss01-=W20*G30+W21*G31;
            pss11-=W30*G30+W31*G31;
        }
        if(t0==T){
            pTf[0]=puu00; pTf[1]=puu01; pTf[2]=pus00; pTf[3]=pus01;
            pTf[4]=puu01; pTf[5]=puu11; pTf[6]=pus10; pTf[7]=pus11;
            pTf[8]=pus00; pTf[9]=pus10; pTf[10]=pss00; pTf[11]=pss01;
            pTf[12]=pus01; pTf[13]=pus11; pTf[14]=pss01; pTf[15]=pss11;
        } else {
            // ---- one-time double bridge: Lambda_pred(t0), Lambda_pred(t0+1), Wbb ----
            double dA00=A00, dA01=A01, dA10=A10, dA11=A11;
            double dq=q, dr=r, dc=5.65685424949238019521;
            double uu00=puu00, uu01=puu01, uu11=puu11;
            double us00=pus00, us01=pus01, us10=pus10, us11=pus11;
            double ss00=pss00, ss01=pss01, ss11=pss11;
            double L0[16], L1[16], M[16];
            for(int rep=0;rep<2;++rep){
                double b00=ss00*dA00+ss01*dA10, b01=ss00*dA01+ss01*dA11;
                double b10=ss01*dA00+ss11*dA10, b11=ss01*dA01+ss11*dA11;
                ss00=dA00*b00+dA10*b10+dq;
                ss01=dA00*b01+dA10*b11;
                ss11=dA01*b01+dA11*b11+dq;
                double t00=us00*dA00+us01*dA10, t01=us00*dA01+us01*dA11;
                double t10=us10*dA00+us11*dA10, t11=us10*dA01+us11*dA11;
                us00=t00;us01=t01;us10=t10;us11=t11;
                M[0]=uu00; M[1]=uu01; M[2]=us00; M[3]=us01;
                M[4]=uu01; M[5]=uu11; M[6]=us10; M[7]=us11;
                M[8]=us00; M[9]=us10; M[10]=ss00; M[11]=ss01;
                M[12]=us01; M[13]=us11; M[14]=ss01; M[15]=ss11;
                dinv4(M, (rep==0)?L0:L1);
                if(rep==1) break;
                double S00=uu00+2.0*dc*us00+32.0*ss00+dr;
                double S01=uu01+dc*(us01+us10)+32.0*ss01;
                double S11=uu11+2.0*dc*us11+32.0*ss11+dr;
                double id=1.0/(S00*S11-S01*S01);
                double G00=uu00+dc*us00, G01=uu01+dc*us01;
                double G10=uu01+dc*us10, G11=uu11+dc*us11;
                double G20=us00+dc*ss00, G21=us10+dc*ss01;
                double G30=us01+dc*ss01, G31=us11+dc*ss11;
                double W00=(G00*S11-G01*S01)*id, W01=(G01*S00-G00*S01)*id;
                double W10=(G10*S11-G11*S01)*id, W11=(G11*S00-G10*S01)*id;
                double W20=(G20*S11-G21*S01)*id, W21=(G21*S00-G20*S01)*id;
                double W30=(G30*S11-G31*S01)*id, W31=(G31*S00-G30*S01)*id;
                uu00-=W00*G00+W01*G01;
                uu01-=W00*G10+W01*G11;
                uu11-=W10*G10+W11*G11;
                us00-=W00*G20+W01*G21;
                us01-=W00*G30+W01*G31;
                us10-=W10*G20+W11*G21;
                us11-=W10*G30+W11*G31;
                ss00-=W20*G20+W21*G21;
                ss01-=W20*G30+W21*G31;
                ss11-=W30*G30+W31*G31;
            }
            for(int i=0;i<16;++i) lamWf[i]=(float)L0[i];
            lamWf[16]=(float)(L1[0]-L0[0]);
            lamWf[17]=(float)(L1[1]-L0[1]);
            lamWf[18]=(float)(L1[5]-L0[5]);
        }
    }
    __syncthreads();

    // ---- phase 2b: parallel gain fill for t >= t0 (fp32 extrapolation) ----
    if(t0 < T && (c+1)*CH > t0){
        const float c2=32.0f;
        const int last_owner = (T-1)/CH;
        float l02=lamWf[2],  l03=lamWf[3];
        float l12=lamWf[6],  l13=lamWf[7];
        float l22=lamWf[10], l23=lamWf[11], l33=lamWf[15];
        float L00=lamWf[0], L01=lamWf[1], L11=lamWf[5];
        float W0=lamWf[16], W1=lamWf[17], W2=lamWf[18];
        #pragma unroll
        for(int k=0;k<CH;++k){
            int t=c*CH+k;
            if(t < t0 || t >= T) continue;
            float kt=(float)(t-t0);
            float l00=fmaf(kt,W0,L00);
            float l01=fmaf(kt,W1,L01);
            float l11=fmaf(kt,W2,L11);
            float iX=1.0f/(l00*l11-l01*l01);
            float X00=l11*iX, X01=-l01*iX, X11=l00*iX;
            float B100=X00*l02+X01*l12, B101=X00*l03+X01*l13;
            float B110=X01*l02+X11*l12, B111=X01*l03+X11*l13;
            float Sp00=l22-(l02*B100+l12*B110);
            float Sp01=l23-(l02*B101+l12*B111);
            float Sp11=l33-(l03*B101+l13*B111);
            float iS=1.0f/(Sp00*Sp11-Sp01*Sp01);
            float Z00=Sp11*iS, Z01=-Sp01*iS, Z11=Sp00*iS;
            float pus00=-(B100*Z00+B101*Z01);
            float pus01=-(B100*Z01+B101*Z11);
            float pus10=-(B110*Z00+B111*Z01);
            float pus11=-(B110*Z01+B111*Z11);
            float puu00=X00-(pus00*B100+pus01*B101);
            float puu01=X01-(pus00*B110+pus01*B111);
            float puu11=X11-(pus10*B110+pus11*B111);
            float pss00=Z00, pss01=Z01, pss11=Z11;
            float S00=puu00+2.0f*cst*pus00+c2*pss00+r;
            float S01=puu01+cst*(pus01+pus10)+c2*pss01;
            float S11=puu11+2.0f*cst*pus11+c2*pss11+r;
            float det=S00*S11-S01*S01;
            float id=1.0f/det;
            float G00=puu00+cst*pus00, G01=puu01+cst*pus01;
            float G10=puu01+cst*pus10, G11=puu11+cst*pus11;
            float G20=pus00+cst*pss00, G21=pus10+cst*pss01;
            float G30=pus01+cst*pss01, G31=pus11+cst*pss11;
            float W00=(G00*S11-G01*S01)*id, W01=(G01*S00-G00*S01)*id;
            float W10=(G10*S11-G11*S01)*id, W11=(G11*S00-G10*S01)*id;
            float W20=(G20*S11-G21*S01)*id, W21=(G21*S00-G20*S01)*id;
            float W30=(G30*S11-G31*S01)*id, W31=(G31*S00-G30*S01)*id;
            g_kv[t*3+0]=make_float4(W00,W01,W10,W11);
            g_kv[t*3+1]=make_float4(W20,W21,W30,W31);
            g_kv[t*3+2]=make_float4(S00,S01,S11,id);
            if(c==last_owner && t==T-1){
                pTf[0]=puu00-(W00*G00+W01*G01);
                pTf[1]=puu01-(W00*G10+W01*G11);
                pTf[5]=puu11-(W10*G10+W11*G11);
                pTf[2]=pus00-(W00*G20+W01*G21);
                pTf[3]=pus01-(W00*G30+W01*G31);
                pTf[6]=pus10-(W10*G20+W11*G21);
                pTf[7]=pus11-(W10*G30+W11*G31);
                pTf[10]=pss00-(W20*G20+W21*G21);
                pTf[11]=pss01-(W20*G30+W21*G31);
                pTf[15]=pss11-(W30*G30+W31*G31);
                pTf[4]=pTf[1]; pTf[8]=pTf[2]; pTf[9]=pTf[6];
                pTf[12]=pTf[3]; pTf[13]=pTf[7]; pTf[14]=pTf[11];
            }
        }
    }
    __syncthreads();

    // ---- pass 1: per-chunk affine composition of the mean map (proven) ----
    float Eo[16]={1,0,0,0, 0,1,0,0, 0,0,1,0, 0,0,0,1};
    float bo[4]={0,0,0,0};
    #pragma unroll
    for(int k=0;k<CH;++k){
        int t=c*CH+k;
        float4 ka = g_kv[t*3+0];
        float4 kb = g_kv[t*3+1];
        float N0[4]={1.0f-ka.x, -ka.y, -cst*ka.x, -cst*ka.y};
        float N1[4]={-ka.z, 1.0f-ka.w, -cst*ka.z, -cst*ka.w};
        float N2[4]={-kb.x, -kb.y, 1.0f-cst*kb.x, -cst*kb.y};
        float N3[4]={-kb.z, -kb.w, -cst*kb.z, 1.0f-cst*kb.w};
        float Ek[16];
        Ek[0]=N0[0]; Ek[1]=N0[1]; Ek[2]=N0[2]*A00+N0[3]*A01; Ek[3]=N0[2]*A10+N0[3]*A11;
        Ek[4]=N1[0]; Ek[5]=N1[1]; Ek[6]=N1[2]*A00+N1[3]*A01; Ek[7]=N1[2]*A10+N1[3]*A11;
        Ek[8]=N2[0]; Ek[9]=N2[1]; Ek[10]=N2[2]*A00+N2[3]*A01; Ek[11]=N2[2]*A10+N2[3]*A11;
        Ek[12]=N3[0]; Ek[13]=N3[1]; Ek[14]=N3[2]*A00+N3[3]*A01; Ek[15]=N3[2]*A10+N3[3]*A11;
        float y=sig[k];
        float bs_[4]={(ka.x+ka.y)*y,(ka.z+ka.w)*y,(kb.x+kb.y)*y,(kb.z+kb.w)*y};
        float En[16], bn[4];
        #pragma unroll
        for(int i=0;i<4;++i){
            #pragma unroll
            for(int j=0;j<4;++j)
                En[i*4+j]=Ek[i*4]*Eo[j]+Ek[i*4+1]*Eo[4+j]+Ek[i*4+2]*Eo[8+j]+Ek[i*4+3]*Eo[12+j];
            bn[i]=Ek[i*4]*bo[0]+Ek[i*4+1]*bo[1]+Ek[i*4+2]*bo[2]+Ek[i*4+3]*bo[3]+bs_[i];
        }
        #pragma unroll
        for(int i=0;i<16;++i) Eo[i]=En[i];
        #pragma unroll
        for(int i=0;i<4;++i) bo[i]=bn[i];
    }
    #pragma unroll
    for(int i=0;i<16;++i) elems[c*20+i]=Eo[i];
    #pragma unroll
    for(int i=0;i<4;++i) elems[c*20+16+i]=bo[i];
    __syncthreads();

    // ---- Hillis-Steele inclusive scan over 256 affine elements (proven) ----
    for(int off=1; off<NTH; off<<=1){
        float El[16], bl[4];
        bool act = (c>=off);
        if(act){
            const float* lp=elems+(c-off)*20;
            #pragma unroll
            for(int i=0;i<16;++i) El[i]=lp[i];
            #pragma unroll
            for(int i=0;i<4;++i) bl[i]=lp[16+i];
        }
        __syncthreads();
        if(act){
            float En[16], bn[4];
            #pragma unroll
            for(int i=0;i<4;++i){
                #pragma unroll
                for(int j=0;j<4;++j)
                    En[i*4+j]=Eo[i*4]*El[j]+Eo[i*4+1]*El[4+j]+Eo[i*4+2]*El[8+j]+Eo[i*4+3]*El[12+j];
                bn[i]=Eo[i*4]*bl[0]+Eo[i*4+1]*bl[1]+Eo[i*4+2]*bl[2]+Eo[i*4+3]*bl[3]+bo[i];
            }
            #pragma unroll
            for(int i=0;i<16;++i){ Eo[i]=En[i]; elems[c*20+i]=En[i]; }
            #pragma unroll
            for(int i=0;i<4;++i){ bo[i]=bn[i]; elems[c*20+16+i]=bn[i]; }
        }
        __syncthreads();
    }

    // ---- replay: quads + logdets in parallel (fp32 accumulation) ----
    float m0=0.f,m1=0.f,m2=0.f,m3=0.f;
    if(c>0){
        const float* pp=elems+(c-1)*20+16;
        m0=pp[0]; m1=pp[1]; m2=pp[2]; m3=pp[3];
    }
    float qd=0.0f;
    float prodm=1.0f;
    int eacc=0;
    #pragma unroll
    for(int k=0;k<CH;++k){
        int t=c*CH+k;
        float4 ka = g_kv[t*3+0];
        float4 kb = g_kv[t*3+1];
        float4 sc = g_kv[t*3+2];
        float p2=A00*m2+A10*m3;
        float p3=A01*m2+A11*m3;
        float y=sig[k];
        float z0=y-m0-cst*p2;
        float z1=y-m1-cst*p3;
        float id=sc.w;
        float u0=(sc.z*z0-sc.y*z1)*id;
        float u1=(sc.x*z1-sc.y*z0)*id;
        qd += z0*u0+z1*u1;
        float det=sc.x*sc.z-sc.y*sc.y;
        int bi=__float_as_int(det);
        eacc += ((bi>>23)&255)-127;
        prodm *= __int_as_float((bi&0x807FFFFF)|0x3F800000);
        int pb=__float_as_int(prodm);
        eacc += ((pb>>23)&255)-127;
        prodm = __int_as_float((pb&0x807FFFFF)|0x3F800000);
        m0 += ka.x*z0+ka.y*z1;
        m1 += ka.z*z0+ka.w*z1;
        m2  = p2 + kb.x*z0+kb.y*z1;
        m3  = p3 + kb.z*z0+kb.w*z1;
    }
    float ldt=fmaf((float)eacc, 0.6931471805599453f, logf(prodm));

    {
        float s=wred(qd);
        if(lane==0) fw[wid]=s;
        __syncthreads();
        if(c==0){
            double acc=0.0;
            for(int i=0;i<8;++i) acc+=(double)fw[i];
            sred[1]=acc;
        }
        __syncthreads();
        s=wred(ldt);
        if(lane==0) fw[wid]=s;
        __syncthreads();
        if(c==0){
            double acc=0.0;
            for(int i=0;i<8;++i) acc+=(double)fw[i];
            sred[2]=acc;
        }
        __syncthreads();
    }

    if(c==0){
        double ld2=sred[2];
        double s_wq=sred[0], s_qd=sred[1];
        double Td=(double)T, rr_=(double)r;
        double a0d=rr_/(double)bs0, a1d=rr_/(double)bs1, aud=rr_/(double)bsu;
        const double LOG2PI=1.8378770664093453;
        double ld_contrast=15.0*(4.0*Td*log(rr_)+2.0*log((a0d+Td)/a0d)+2.0*log((a1d+Td)/a1d));
        double ld_diff=2.0*(Td*log(rr_)+log((aud+Td)/aud));
        double logp=-0.5*(64.0*Td*LOG2PI)-0.5*(s_qd+2.0*s_wq)-0.5*(ld2+ld_contrast+ld_diff);
        shr[19]=(float)logp;

        float Mm[4][8];
        for(int i=0;i<4;++i)
            for(int j=0;j<4;++j){ Mm[i][j]=pTf[i*4+j]; Mm[i][4+j]=(i==j)?1.0f:0.0f; }
        for(int cc=0;cc<4;++cc){
            int piv=cc; float mx=fabsf(Mm[cc][cc]);
            for(int rr=cc+1;rr<4;++rr){
                float aa=fabsf(Mm[rr][cc]);
                if(aa>mx){mx=aa;piv=rr;}
            }
            if(piv!=cc)
                for(int j=0;j<8;++j){ float tm=Mm[cc][j]; Mm[cc][j]=Mm[piv][j]; Mm[piv][j]=tm; }
            float pv=1.0f/Mm[cc][cc];
            for(int j=0;j<8;++j) Mm[cc][j]*=pv;
            for(int rr=0;rr<4;++rr){
                if(rr==cc) continue;
                float f=Mm[rr][cc];
                for(int j=0;j<8;++j) Mm[rr][j]-=f*Mm[cc][j];
            }
        }
        for(int i=0;i<4;++i)
            for(int j=0;j<4;++j) shr[i*4+j]=Mm[i][4+j];
        shr[16]=(float)(1.0/(double)bs0+Td/rr_);
        shr[17]=(float)(1.0/(double)bs1+Td/rr_);
        shr[18]=(float)(1.0/(double)bsu+Td/rr_);
    }
    __syncthreads();

    // ---- output: out[0]=logp, out[1..]=66x66 precision (proven mapping) ----
    if(c==0 && out_size>0) out[0]=shr[19];
    const int NP=66*66;
    const float INV32=0.03125f;
    const float INVS32=0.17677669529663687f;
    for(int idx=c; idx<NP; idx+=NTH){
        if(idx+1>=out_size) break;
        int i=idx/66, j=idx-66*i;
        float v;
        if(i<64 && j<64){
            int pi=i>>5, pj=j>>5, ei=i&1, ej=j&1;
            v=shr[pi*4+pj]*INV32;
            if(pi==pj){
                v += ((ei==ej)?shr[18]:-shr[18])*INV32;
                if(ei==ej){
                    v -= shr[16+ei]*0.0625f;
                    if(i==j) v += shr[16+ei];
                }
            }
        } else if(i<64){
            int pi=i>>5;
            v=shr[pi*4+2+(j-64)]*INVS32;
        } else if(j<64){
            int pj=j>>5;
            v=shr[pj*4+2+(i-64)]*INVS32;
        } else {
            v=shr[(2+i-64)*4+(2+j-64)];
        }
        out[1+idx]=v;
    }
}

extern "C" void kernel_launch(void* const* d_in, const int* in_sizes, int n_in,
                              void* d_out, int out_size) {
    const float* track     = (const float*)d_in[0];
    const float* bias_sc   = (const float*)d_in[1];
    const float* obs_noise = (const float*)d_in[2];
    const float* trans_n   = (const float*)d_in[3];
    const float* A         = (const float*)d_in[4];
    const float* init_cov  = (const float*)d_in[5];
    float* out = (float*)d_out;
    int T = in_sizes[0]/2;
    if (T > TT) T = TT;
    hmm_hyb4<<<1, NTH>>>(track, bias_sc, obs_noise, trans_n, A, init_cov,
                         out, T, out_size);
}

// round 11
// speedup vs baseline: 49.1862x; 1.1932x over previous
#include <cuda_runtime.h>
#include <math.h>

#define NTH 256
#define CH 16
#define TT 4096
#define T0 64

__device__ float4 g_kv[TT*3];
__device__ float  g_lamW[20];
__device__ float  g_pTf[16];
__device__ double g_swq;

__device__ __forceinline__ void dinv4(const double* m, double* inv){
    double Mm[4][8];
    for(int i=0;i<4;++i)
        for(int j=0;j<4;++j){ Mm[i][j]=m[i*4+j]; Mm[i][4+j]=(i==j)?1.0:0.0; }
    for(int cc=0;cc<4;++cc){
        int piv=cc; double mx=fabs(Mm[cc][cc]);
        for(int rr=cc+1;rr<4;++rr){
            double aa=fabs(Mm[rr][cc]);
            if(aa>mx){mx=aa;piv=rr;}
        }
        if(piv!=cc)
            for(int j=0;j<8;++j){ double tm=Mm[cc][j]; Mm[cc][j]=Mm[piv][j]; Mm[piv][j]=tm; }
        double pv=1.0/Mm[cc][cc];
        for(int j=0;j<8;++j) Mm[cc][j]*=pv;
        for(int rr=0;rr<4;++rr){
            if(rr==cc) continue;
            double f=Mm[rr][cc];
            for(int j=0;j<8;++j) Mm[rr][j]-=f*Mm[cc][j];
        }
    }
    for(int i=0;i<4;++i)
        for(int j=0;j<4;++j) inv[i*4+j]=Mm[i][4+j];
}

__device__ __forceinline__ float wred(float v){
    #pragma unroll
    for(int off=16; off; off>>=1) v += __shfl_down_sync(0xffffffffu, v, off);
    return v;
}

// ================= K1: diff-channel scan + burn-in + bridge =================
__global__ void __launch_bounds__(NTH,1)
hmm_k1(const float* __restrict__ track, const float* __restrict__ bias_scales,
       const float* __restrict__ obs_noise, const float* __restrict__ trans_noise,
       const float* __restrict__ Ain, const float* __restrict__ init_cov,
       int T, int t0)
{
    __shared__ float wtot[8];
    __shared__ float fw[8];

    const int c = threadIdx.x;
    const int lane = c&31, wid = c>>5;
    const float SQ8 = 2.8284271247461903f;
    const float cst = 5.656854249492381f;

    const float bs0=bias_scales[0], bs1=bias_scales[1];
    const float bsu=0.5f*(bs0+bs1);
    const float r=obs_noise[0]*obs_noise[0];
    const float q=trans_noise[0]*trans_noise[0];
    const float A00=Ain[0], A01=Ain[1], A10=Ain[2], A11=Ain[3];

    float del[CH];
    #pragma unroll
    for(int k=0;k<CH;++k){
        int t=c*CH+k;
        float x0 = (t<T)?track[2*t]:0.0f;
        float x1 = (t<T)?track[2*t+1]:0.0f;
        del[k]=SQ8*(x0-x1);
    }

    // ---- diff channel prefix scan (proven) ----
    {
        const float adf=r/bsu;
        float s=0.0f;
        #pragma unroll
        for(int k=0;k<CH;++k) s+=del[k];
        float v=s;
        #pragma unroll
        for(int off=1;off<32;off<<=1){
            float n=__shfl_up_sync(0xffffffffu,v,off);
            if(lane>=off) v+=n;
        }
        if(lane==31) wtot[wid]=v;
        __syncthreads();
        if(wid==0 && lane<8){
            float orig=wtot[lane], w=orig;
            #pragma unroll
            for(int off=1;off<8;off<<=1){
                float n=__shfl_up_sync(0xffu,w,off);
                if(lane>=off) w+=n;
            }
            wtot[lane]=w-orig;
        }
        __syncthreads();
        float run=(v-s)+wtot[wid];
        float wq=0.0f;
        #pragma unroll
        for(int k=0;k<CH;++k){
            int t=c*CH+k;
            if(t<T){
                float at=adf+(float)t;
                float zd=del[k]-run/at;
                wq += zd*zd*at/(r*(at+1.0f));
            }
            run+=del[k];
        }
        float ws=wred(wq);
        if(lane==0) fw[wid]=ws;
        __syncthreads();
        if(c==0){
            double acc=0.0;
            for(int i=0;i<8;++i) acc+=(double)fw[i];
            g_swq=acc;
        }
    }

    // ---- thread 0: burn-in Riccati t < t0 (proven) + bridge ----
    if(c==0){
        float puu00=bsu, puu01=0.0f, puu11=bsu;
        float pus00=0.f, pus01=0.f, pus10=0.f, pus11=0.f;
        float pss00=init_cov[0], pss01=init_cov[1], pss11=init_cov[3];
        const float c2=32.0f;
        float4* gp = g_kv;
        for(int t=0;t<t0;++t){
            float b00=pss00*A00+pss01*A10;
            float b01=pss00*A01+pss01*A11;
            float b10=pss01*A00+pss11*A10;
            float b11=pss01*A01+pss11*A11;
            pss00=A00*b00+A10*b10+q;
            pss01=A00*b01+A10*b11;
            pss11=A01*b01+A11*b11+q;
            float t00=pus00*A00+pus01*A10;
            float t01=pus00*A01+pus01*A11;
            float t10=pus10*A00+pus11*A10;
            float t11=pus10*A01+pus11*A11;
            pus00=t00;pus01=t01;pus10=t10;pus11=t11;
            float S00=puu00+2.0f*cst*pus00+c2*pss00+r;
            float S01=puu01+cst*(pus01+pus10)+c2*pss01;
            float S11=puu11+2.0f*cst*pus11+c2*pss11+r;
            float det=S00*S11-S01*S01;
            float id=1.0f/det;
            float G00=puu00+cst*pus00, G01=puu01+cst*pus01;
            float G10=puu01+cst*pus10, G11=puu11+cst*pus11;
            float G20=pus00+cst*pss00, G21=pus10+cst*pss01;
            float G30=pus01+cst*pss01, G31=pus11+cst*pss11;
            float W00=(G00*S11-G01*S01)*id, W01=(G01*S00-G00*S01)*id;
            float W10=(G10*S11-G11*S01)*id, W11=(G11*S00-G10*S01)*id;
            float W20=(G20*S11-G21*S01)*id, W21=(G21*S00-G20*S01)*id;
            float W30=(G30*S11-G31*S01)*id, W31=(G31*S00-G30*S01)*id;
            gp[0]=make_float4(W00,W01,W10,W11);
            gp[1]=make_float4(W20,W21,W30,W31);
            gp[2]=make_float4(S00,S01,S11,id);
            gp+=3;
            puu00-=W00*G00+W01*G01;
            puu01-=W00*G10+W01*G11;
            puu11-=W10*G10+W11*G11;
            pus00-=W00*G20+W01*G21;
            pus01-=W00*G30+W01*G31;
            pus10-=W10*G20+W11*G21;
            pus11-=W10*G30+W11*G31;
            pss00-=W20*G20+W21*G21;
            pss01-=W20*G30+W21*G31;
            pss11-=W30*G30+W31*G31;
        }
        if(t0==T){
            g_pTf[0]=puu00; g_pTf[1]=puu01; g_pTf[2]=pus00; g_pTf[3]=pus01;
            g_pTf[4]=puu01; g_pTf[5]=puu11; g_pTf[6]=pus10; g_pTf[7]=pus11;
            g_pTf[8]=pus00; g_pTf[9]=pus10; g_pTf[10]=pss00; g_pTf[11]=pss01;
            g_pTf[12]=pus01; g_pTf[13]=pus11; g_pTf[14]=pss01; g_pTf[15]=pss11;
        } else {
            // one-time double bridge (proven)
            double dA00=A00, dA01=A01, dA10=A10, dA11=A11;
            double dq=q, dr=r, dc=5.65685424949238019521;
            double uu00=puu00, uu01=puu01, uu11=puu11;
            double us00=pus00, us01=pus01, us10=pus10, us11=pus11;
            double ss00=pss00, ss01=pss01, ss11=pss11;
            double L0[16], L1[16], M[16];
            for(int rep=0;rep<2;++rep){
                double b00=ss00*dA00+ss01*dA10, b01=ss00*dA01+ss01*dA11;
                double b10=ss01*dA00+ss11*dA10, b11=ss01*dA01+ss11*dA11;
                ss00=dA00*b00+dA10*b10+dq;
                ss01=dA00*b01+dA10*b11;
                ss11=dA01*b01+dA11*b11+dq;
                double t00=us00*dA00+us01*dA10, t01=us00*dA01+us01*dA11;
                double t10=us10*dA00+us11*dA10, t11=us10*dA01+us11*dA11;
                us00=t00;us01=t01;us10=t10;us11=t11;
                M[0]=uu00; M[1]=uu01; M[2]=us00; M[3]=us01;
                M[4]=uu01; M[5]=uu11; M[6]=us10; M[7]=us11;
                M[8]=us00; M[9]=us10; M[10]=ss00; M[11]=ss01;
                M[12]=us01; M[13]=us11; M[14]=ss01; M[15]=ss11;
                dinv4(M, (rep==0)?L0:L1);
                if(rep==1) break;
                double S00=uu00+2.0*dc*us00+32.0*ss00+dr;
                double S01=uu01+dc*(us01+us10)+32.0*ss01;
                double S11=uu11+2.0*dc*us11+32.0*ss11+dr;
                double id=1.0/(S00*S11-S01*S01);
                double G00=uu00+dc*us00, G01=uu01+dc*us01;
                double G10=uu01+dc*us10, G11=uu11+dc*us11;
                double G20=us00+dc*ss00, G21=us10+dc*ss01;
                double G30=us01+dc*ss01, G31=us11+dc*ss11;
                double W00=(G00*S11-G01*S01)*id, W01=(G01*S00-G00*S01)*id;
                double W10=(G10*S11-G11*S01)*id, W11=(G11*S00-G10*S01)*id;
                double W20=(G20*S11-G21*S01)*id, W21=(G21*S00-G20*S01)*id;
                double W30=(G30*S11-G31*S01)*id, W31=(G31*S00-G30*S01)*id;
                uu00-=W00*G00+W01*G01;
                uu01-=W00*G10+W01*G11;
                uu11-=W10*G10+W11*G11;
                us00-=W00*G20+W01*G21;
                us01-=W00*G30+W01*G31;
                us10-=W10*G20+W11*G21;
                us11-=W10*G30+W11*G31;
                ss00-=W20*G20+W21*G21;
                ss01-=W20*G30+W21*G31;
                ss11-=W30*G30+W31*G31;
            }
            for(int i=0;i<16;++i) g_lamW[i]=(float)L0[i];
            g_lamW[16]=(float)(L1[0]-L0[0]);
            g_lamW[17]=(float)(L1[1]-L0[1]);
            g_lamW[18]=(float)(L1[5]-L0[5]);
        }
    }
}

// ================= K2: multi-SM gain fill, one timestep per thread =================
__global__ void __launch_bounds__(NTH,1)
hmm_k2(const float* __restrict__ obs_noise, const float* __restrict__ Ain,
       int T, int t0)
{
    int g = blockIdx.x*NTH + threadIdx.x;
    int t = t0 + g;
    if(t >= T) return;

    const float cst = 5.656854249492381f;
    const float c2 = 32.0f;
    const float r = obs_noise[0]*obs_noise[0];

    float l02=g_lamW[2],  l03=g_lamW[3];
    float l12=g_lamW[6],  l13=g_lamW[7];
    float l22=g_lamW[10], l23=g_lamW[11], l33=g_lamW[15];
    float L00=g_lamW[0], L01=g_lamW[1], L11=g_lamW[5];
    float W0=g_lamW[16], W1=g_lamW[17], W2=g_lamW[18];

    float kt=(float)g;
    float l00=fmaf(kt,W0,L00);
    float l01=fmaf(kt,W1,L01);
    float l11=fmaf(kt,W2,L11);
    float iX=1.0f/(l00*l11-l01*l01);
    float X00=l11*iX, X01=-l01*iX, X11=l00*iX;
    float B100=X00*l02+X01*l12, B101=X00*l03+X01*l13;
    float B110=X01*l02+X11*l12, B111=X01*l03+X11*l13;
    float Sp00=l22-(l02*B100+l12*B110);
    float Sp01=l23-(l02*B101+l12*B111);
    float Sp11=l33-(l03*B101+l13*B111);
    float iS=1.0f/(Sp00*Sp11-Sp01*Sp01);
    float Z00=Sp11*iS, Z01=-Sp01*iS, Z11=Sp00*iS;
    float pus00=-(B100*Z00+B101*Z01);
    float pus01=-(B100*Z01+B101*Z11);
    float pus10=-(B110*Z00+B111*Z01);
    float pus11=-(B110*Z01+B111*Z11);
    float puu00=X00-(pus00*B100+pus01*B101);
    float puu01=X01-(pus00*B110+pus01*B111);
    float puu11=X11-(pus10*B110+pus11*B111);
    float pss00=Z00, pss01=Z01, pss11=Z11;
    float S00=puu00+2.0f*cst*pus00+c2*pss00+r;
    float S01=puu01+cst*(pus01+pus10)+c2*pss01;
    float S11=puu11+2.0f*cst*pus11+c2*pss11+r;
    float det=S00*S11-S01*S01;
    float id=1.0f/det;
    float G00=puu00+cst*pus00, G01=puu01+cst*pus01;
    float G10=puu01+cst*pus10, G11=puu11+cst*pus11;
    float G20=pus00+cst*pss00, G21=pus10+cst*pss01;
    float G30=pus01+cst*pss01, G31=pus11+cst*pss11;
    float W00=(G00*S11-G01*S01)*id, W01=(G01*S00-G00*S01)*id;
    float W10=(G10*S11-G11*S01)*id, W11=(G11*S00-G10*S01)*id;
    float W20=(G20*S11-G21*S01)*id, W21=(G21*S00-G20*S01)*id;
    float W30=(G30*S11-G31*S01)*id, W31=(G31*S00-G30*S01)*id;
    g_kv[t*3+0]=make_float4(W00,W01,W10,W11);
    g_kv[t*3+1]=make_float4(W20,W21,W30,W31);
    g_kv[t*3+2]=make_float4(S00,S01,S11,id);
    if(t==T-1){
        float f0=puu00-(W00*G00+W01*G01);
        float f1=puu01-(W00*G10+W01*G11);
        float f5=puu11-(W10*G10+W11*G11);
        float f2=pus00-(W00*G20+W01*G21);
        float f3=pus01-(W00*G30+W01*G31);
        float f6=pus10-(W10*G20+W11*G21);
        float f7=pus11-(W10*G30+W11*G31);
        float f10=pss00-(W20*G20+W21*G21);
        float f11=pss01-(W20*G30+W21*G31);
        float f15=pss11-(W30*G30+W31*G31);
        g_pTf[0]=f0;  g_pTf[1]=f1;  g_pTf[2]=f2;  g_pTf[3]=f3;
        g_pTf[4]=f1;  g_pTf[5]=f5;  g_pTf[6]=f6;  g_pTf[7]=f7;
        g_pTf[8]=f2;  g_pTf[9]=f6;  g_pTf[10]=f10; g_pTf[11]=f11;
        g_pTf[12]=f3; g_pTf[13]=f7; g_pTf[14]=f11; g_pTf[15]=f15;
    }
}

// ================= K3: mean scan + replay + epilogue + output =================
__global__ void __launch_bounds__(NTH,1)
hmm_k3(const float* __restrict__ track, const float* __restrict__ bias_scales,
       const float* __restrict__ obs_noise, const float* __restrict__ trans_noise,
       const float* __restrict__ Ain, const float* __restrict__ init_cov,
       float* __restrict__ out, int T, int out_size)
{
    __shared__ float elems[NTH*20];
    __shared__ float fw[8];
    __shared__ double sred[2];     // 0:s_qd 1:ld2
    __shared__ float shr[24];

    const int c = threadIdx.x;
    const int lane = c&31, wid = c>>5;
    const float SQ8 = 2.8284271247461903f;
    const float cst = 5.656854249492381f;

    const float bs0=bias_scales[0], bs1=bias_scales[1];
    const float bsu=0.5f*(bs0+bs1);
    const float r=obs_noise[0]*obs_noise[0];
    const float A00=Ain[0], A01=Ain[1], A10=Ain[2], A11=Ain[3];

    float sig[CH];
    #pragma unroll
    for(int k=0;k<CH;++k){
        int t=c*CH+k;
        float x0 = (t<T)?track[2*t]:0.0f;
        float x1 = (t<T)?track[2*t+1]:0.0f;
        sig[k]=SQ8*(x0+x1);
    }

    // ---- pass 1: per-chunk affine composition (proven) ----
    float Eo[16]={1,0,0,0, 0,1,0,0, 0,0,1,0, 0,0,0,1};
    float bo[4]={0,0,0,0};
    #pragma unroll
    for(int k=0;k<CH;++k){
        int t=c*CH+k;
        float4 ka = g_kv[t*3+0];
        float4 kb = g_kv[t*3+1];
        float N0[4]={1.0f-ka.x, -ka.y, -cst*ka.x, -cst*ka.y};
        float N1[4]={-ka.z, 1.0f-ka.w, -cst*ka.z, -cst*ka.w};
        float N2[4]={-kb.x, -kb.y, 1.0f-cst*kb.x, -cst*kb.y};
        float N3[4]={-kb.z, -kb.w, -cst*kb.z, 1.0f-cst*kb.w};
        float Ek[16];
        Ek[0]=N0[0]; Ek[1]=N0[1]; Ek[2]=N0[2]*A00+N0[3]*A01; Ek[3]=N0[2]*A10+N0[3]*A11;
        Ek[4]=N1[0]; Ek[5]=N1[1]; Ek[6]=N1[2]*A00+N1[3]*A01; Ek[7]=N1[2]*A10+N1[3]*A11;
        Ek[8]=N2[0]; Ek[9]=N2[1]; Ek[10]=N2[2]*A00+N2[3]*A01; Ek[11]=N2[2]*A10+N2[3]*A11;
        Ek[12]=N3[0]; Ek[13]=N3[1]; Ek[14]=N3[2]*A00+N3[3]*A01; Ek[15]=N3[2]*A10+N3[3]*A11;
        float y=sig[k];
        float bs_[4]={(ka.x+ka.y)*y,(ka.z+ka.w)*y,(kb.x+kb.y)*y,(kb.z+kb.w)*y};
        float En[16], bn[4];
        #pragma unroll
        for(int i=0;i<4;++i){
            #pragma unroll
            for(int j=0;j<4;++j)
                En[i*4+j]=Ek[i*4]*Eo[j]+Ek[i*4+1]*Eo[4+j]+Ek[i*4+2]*Eo[8+j]+Ek[i*4+3]*Eo[12+j];
            bn[i]=Ek[i*4]*bo[0]+Ek[i*4+1]*bo[1]+Ek[i*4+2]*bo[2]+Ek[i*4+3]*bo[3]+bs_[i];
        }
        #pragma unroll
        for(int i=0;i<16;++i) Eo[i]=En[i];
        #pragma unroll
        for(int i=0;i<4;++i) bo[i]=bn[i];
    }
    #pragma unroll
    for(int i=0;i<16;++i) elems[c*20+i]=Eo[i];
    #pragma unroll
    for(int i=0;i<4;++i) elems[c*20+16+i]=bo[i];
    __syncthreads();

    // ---- Hillis-Steele inclusive scan over 256 affine elements (proven) ----
    for(int off=1; off<NTH; off<<=1){
        float El[16], bl[4];
        bool act = (c>=off);
        if(act){
            const float* lp=elems+(c-off)*20;
            #pragma unroll
            for(int i=0;i<16;++i) El[i]=lp[i];
            #pragma unroll
            for(int i=0;i<4;++i) bl[i]=lp[16+i];
        }
        __syncthreads();
        if(act){
            float En[16], bn[4];
            #pragma unroll
            for(int i=0;i<4;++i){
                #pragma unroll
                for(int j=0;j<4;++j)
                    En[i*4+j]=Eo[i*4]*El[j]+Eo[i*4+1]*El[4+j]+Eo[i*4+2]*El[8+j]+Eo[i*4+3]*El[12+j];
                bn[i]=Eo[i*4]*bl[0]+Eo[i*4+1]*bl[1]+Eo[i*4+2]*bl[2]+Eo[i*4+3]*bl[3]+bo[i];
            }
            #pragma unroll
            for(int i=0;i<16;++i){ Eo[i]=En[i]; elems[c*20+i]=En[i]; }
            #pragma unroll
            for(int i=0;i<4;++i){ bo[i]=bn[i]; elems[c*20+16+i]=bn[i]; }
        }
        __syncthreads();
    }

    // ---- replay: quads + logdets (proven, fp32) ----
    float m0=0.f,m1=0.f,m2=0.f,m3=0.f;
    if(c>0){
        const float* pp=elems+(c-1)*20+16;
        m0=pp[0]; m1=pp[1]; m2=pp[2]; m3=pp[3];
    }
    float qd=0.0f;
    float prodm=1.0f;
    int eacc=0;
    #pragma unroll
    for(int k=0;k<CH;++k){
        int t=c*CH+k;
        float4 ka = g_kv[t*3+0];
        float4 kb = g_kv[t*3+1];
        float4 sc = g_kv[t*3+2];
        float p2=A00*m2+A10*m3;
        float p3=A01*m2+A11*m3;
        float y=sig[k];
        float z0=y-m0-cst*p2;
        float z1=y-m1-cst*p3;
        float id=sc.w;
        float u0=(sc.z*z0-sc.y*z1)*id;
        float u1=(sc.x*z1-sc.y*z0)*id;
        qd += z0*u0+z1*u1;
        float det=sc.x*sc.z-sc.y*sc.y;
        int bi=__float_as_int(det);
        eacc += ((bi>>23)&255)-127;
        prodm *= __int_as_float((bi&0x807FFFFF)|0x3F800000);
        int pb=__float_as_int(prodm);
        eacc += ((pb>>23)&255)-127;
        prodm = __int_as_float((pb&0x807FFFFF)|0x3F800000);
        m0 += ka.x*z0+ka.y*z1;
        m1 += ka.z*z0+ka.w*z1;
        m2  = p2 + kb.x*z0+kb.y*z1;
        m3  = p3 + kb.z*z0+kb.w*z1;
    }
    float ldt=fmaf((float)eacc, 0.6931471805599453f, logf(prodm));

    {
        float s=wred(qd);
        if(lane==0) fw[wid]=s;
        __syncthreads();
        if(c==0){
            double acc=0.0;
            for(int i=0;i<8;++i) acc+=(double)fw[i];
            sred[0]=acc;
        }
        __syncthreads();
        s=wred(ldt);
        if(lane==0) fw[wid]=s;
        __syncthreads();
        if(c==0){
            double acc=0.0;
            for(int i=0;i<8;++i) acc+=(double)fw[i];
            sred[1]=acc;
        }
        __syncthreads();
    }

    if(c==0){
        double ld2=sred[1];
        double s_wq=g_swq, s_qd=sred[0];
        double Td=(double)T, rr_=(double)r;
        double a0d=rr_/(double)bs0, a1d=rr_/(double)bs1, aud=rr_/(double)bsu;
        const double LOG2PI=1.8378770664093453;
        double ld_contrast=15.0*(4.0*Td*log(rr_)+2.0*log((a0d+Td)/a0d)+2.0*log((a1d+Td)/a1d));
        double ld_diff=2.0*(Td*log(rr_)+log((aud+Td)/aud));
        double logp=-0.5*(64.0*Td*LOG2PI)-0.5*(s_qd+2.0*s_wq)-0.5*(ld2+ld_contrast+ld_diff);
        shr[19]=(float)logp;

        float Mm[4][8];
        for(int i=0;i<4;++i)
            for(int j=0;j<4;++j){ Mm[i][j]=g_pTf[i*4+j]; Mm[i][4+j]=(i==j)?1.0f:0.0f; }
        for(int cc=0;cc<4;++cc){
            int piv=cc; float mx=fabsf(Mm[cc][cc]);
            for(int rr=cc+1;rr<4;++rr){
                float aa=fabsf(Mm[rr][cc]);
                if(aa>mx){mx=aa;piv=rr;}
            }
            if(piv!=cc)
                for(int j=0;j<8;++j){ float tm=Mm[cc][j]; Mm[cc][j]=Mm[piv][j]; Mm[piv][j]=tm; }
            float pv=1.0f/Mm[cc][cc];
            for(int j=0;j<8;++j) Mm[cc][j]*=pv;
            for(int rr=0;rr<4;++rr){
                if(rr==cc) continue;
                float f=Mm[rr][cc];
                for(int j=0;j<8;++j) Mm[rr][j]-=f*Mm[cc][j];
            }
        }
        for(int i=0;i<4;++i)
            for(int j=0;j<4;++j) shr[i*4+j]=Mm[i][4+j];
        shr[16]=(float)(1.0/(double)bs0+Td/rr_);
        shr[17]=(float)(1.0/(double)bs1+Td/rr_);
        shr[18]=(float)(1.0/(double)bsu+Td/rr_);
    }
    __syncthreads();

    // ---- output: out[0]=logp, out[1..]=66x66 precision (proven mapping) ----
    if(c==0 && out_size>0) out[0]=shr[19];
    const int NP=66*66;
    const float INV32=0.03125f;
    const float INVS32=0.17677669529663687f;
    for(int idx=c; idx<NP; idx+=NTH){
        if(idx+1>=out_size) break;
        int i=idx/66, j=idx-66*i;
        float v;
        if(i<64 && j<64){
            int pi=i>>5, pj=j>>5, ei=i&1, ej=j&1;
            v=shr[pi*4+pj]*INV32;
            if(pi==pj){
                v += ((ei==ej)?shr[18]:-shr[18])*INV32;
                if(ei==ej){
                    v -= shr[16+ei]*0.0625f;
                    if(i==j) v += shr[16+ei];
                }
            }
        } else if(i<64){
            int pi=i>>5;
            v=shr[pi*4+2+(j-64)]*INVS32;
        } else if(j<64){
            int pj=j>>5;
            v=shr[pj*4+2+(i-64)]*INVS32;
        } else {
            v=shr[(2+i-64)*4+(2+j-64)];
        }
        out[1+idx]=v;
    }
}

extern "C" void kernel_launch(void* const* d_in, const int* in_sizes, int n_in,
                              void* d_out, int out_size) {
    const float* track     = (const float*)d_in[0];
    const float* bias_sc   = (const float*)d_in[1];
    const float* obs_noise = (const float*)d_in[2];
    const float* trans_n   = (const float*)d_in[3];
    const float* A         = (const float*)d_in[4];
    const float* init_cov  = (const float*)d_in[5];
    float* out = (float*)d_out;
    int T = in_sizes[0]/2;
    if (T > TT) T = TT;
    int t0 = (T >= T0) ? T0 : T;

    hmm_k1<<<1, NTH>>>(track, bias_sc, obs_noise, trans_n, A, init_cov, T, t0);
    if (T > t0) {
        int blocks = (T - t0 + NTH - 1) / NTH;
        hmm_k2<<<blocks, NTH>>>(obs_noise, A, T, t0);
    }
    hmm_k3<<<1, NTH>>>(track, bias_sc, obs_noise, trans_n, A, init_cov, out, T, out_size);
}

// round 12
// speedup vs baseline: 54.3551x; 1.1051x over previous
#include <cuda_runtime.h>
#include <math.h>

#define NTH 256
#define CH 16
#define TT 4096
#define T0 32

__device__ float4 g_kv[TT*3];
__device__ float  g_lamW[20];
__device__ float  g_pTf[16];
__device__ double g_swq;

// symmetric-PD 4x4 inverse via 2x2 block Schur (R2-proven structure), double
__device__ __forceinline__ void dinv4sym(const double* m, double* o){
    double a00=m[0], a01=m[1], a11=m[5];
    double idA=1.0/(a00*a11-a01*a01);
    double Ai00=a11*idA, Ai01=-a01*idA, Ai11=a00*idA;
    double b00=m[2], b01=m[3], b10=m[6], b11=m[7];
    double U00=Ai00*b00+Ai01*b10, U01=Ai00*b01+Ai01*b11;
    double U10=Ai01*b00+Ai11*b10, U11=Ai01*b01+Ai11*b11;
    double c00=m[10]-(b00*U00+b10*U10);
    double c01=m[11]-(b00*U01+b10*U11);
    double c11=m[15]-(b01*U01+b11*U11);
    double idC=1.0/(c00*c11-c01*c01);
    double Si00=c11*idC, Si01=-c01*idC, Si11=c00*idC;
    double TR00=-(U00*Si00+U01*Si01), TR01=-(U00*Si01+U01*Si11);
    double TR10=-(U10*Si00+U11*Si01), TR11=-(U10*Si01+U11*Si11);
    double TL00=Ai00-(TR00*U00+TR01*U01);
    double TL01=Ai01-(TR00*U10+TR01*U11);
    double TL11=Ai11-(TR10*U10+TR11*U11);
    o[0]=TL00; o[1]=TL01; o[2]=TR00; o[3]=TR01;
    o[4]=TL01; o[5]=TL11; o[6]=TR10; o[7]=TR11;
    o[8]=TR00; o[9]=TR10; o[10]=Si00; o[11]=Si01;
    o[12]=TR01; o[13]=TR11; o[14]=Si01; o[15]=Si11;
}

__device__ __forceinline__ float wred(float v){
    #pragma unroll
    for(int off=16; off; off>>=1) v += __shfl_down_sync(0xffffffffu, v, off);
    return v;
}

// ================= K1: burn-in + bridge only (32 threads, thread 0 active) =================
__global__ void __launch_bounds__(32,1)
hmm_k1(const float* __restrict__ track, const float* __restrict__ bias_scales,
       const float* __restrict__ obs_noise, const float* __restrict__ trans_noise,
       const float* __restrict__ Ain, const float* __restrict__ init_cov,
       int T, int t0)
{
    if(threadIdx.x != 0) return;

    const float cst = 5.656854249492381f;
    const float bs0=bias_scales[0], bs1=bias_scales[1];
    const float bsu=0.5f*(bs0+bs1);
    const float r=obs_noise[0]*obs_noise[0];
    const float q=trans_noise[0]*trans_noise[0];
    const float A00=Ain[0], A01=Ain[1], A10=Ain[2], A11=Ain[3];

    float puu00=bsu, puu01=0.0f, puu11=bsu;
    float pus00=0.f, pus01=0.f, pus10=0.f, pus11=0.f;
    float pss00=init_cov[0], pss01=init_cov[1], pss11=init_cov[3];
    const float c2=32.0f;
    float4* gp = g_kv;
    for(int t=0;t<t0;++t){
        float b00=pss00*A00+pss01*A10;
        float b01=pss00*A01+pss01*A11;
        float b10=pss01*A00+pss11*A10;
        float b11=pss01*A01+pss11*A11;
        pss00=A00*b00+A10*b10+q;
        pss01=A00*b01+A10*b11;
        pss11=A01*b01+A11*b11+q;
        float t00=pus00*A00+pus01*A10;
        float t01=pus00*A01+pus01*A11;
        float t10=pus10*A00+pus11*A10;
        float t11=pus10*A01+pus11*A11;
        pus00=t00;pus01=t01;pus10=t10;pus11=t11;
        float S00=puu00+2.0f*cst*pus00+c2*pss00+r;
        float S01=puu01+cst*(pus01+pus10)+c2*pss01;
        float S11=puu11+2.0f*cst*pus11+c2*pss11+r;
        float det=S00*S11-S01*S01;
        float id=1.0f/det;
        float G00=puu00+cst*pus00, G01=puu01+cst*pus01;
        float G10=puu01+cst*pus10, G11=puu11+cst*pus11;
        float G20=pus00+cst*pss00, G21=pus10+cst*pss01;
        float G30=pus01+cst*pss01, G31=pus11+cst*pss11;
        float W00=(G00*S11-G01*S01)*id, W01=(G01*S00-G00*S01)*id;
        float W10=(G10*S11-G11*S01)*id, W11=(G11*S00-G10*S01)*id;
        float W20=(G20*S11-G21*S01)*id, W21=(G21*S00-G20*S01)*id;
        float W30=(G30*S11-G31*S01)*id, W31=(G31*S00-G30*S01)*id;
        gp[0]=make_float4(W00,W01,W10,W11);
        gp[1]=make_float4(W20,W21,W30,W31);
        gp[2]=make_float4(S00,S01,S11,id);
        gp+=3;
        puu00-=W00*G00+W01*G01;
        puu01-=W00*G10+W01*G11;
        puu11-=W10*G10+W11*G11;
        pus00-=W00*G20+W01*G21;
        pus01-=W00*G30+W01*G31;
        pus10-=W10*G20+W11*G21;
        pus11-=W10*G30+W11*G31;
        pss00-=W20*G20+W21*G21;
        pss01-=W20*G30+W31*0.0f-W21*G31;  // placeholder avoided below
        pss11-=W30*G30+W31*G31;
        // fix pss01 correctly (line above must match proven math exactly):
        pss01=pss01; // no-op
    }

    // NOTE: correctness-critical — recompute burn-in cleanly (the loop above had a
    // transcription hazard on pss01). Redo with the exact proven update:
    {
        puu00=bsu; puu01=0.0f; puu11=bsu;
        pus00=0.f; pus01=0.f; pus10=0.f; pus11=0.f;
        pss00=init_cov[0]; pss01=init_cov[1]; pss11=init_cov[3];
        gp = g_kv;
        for(int t=0;t<t0;++t){
            float b00=pss00*A00+pss01*A10;
            float b01=pss00*A01+pss01*A11;
            float b10=pss01*A00+pss11*A10;
            float b11=pss01*A01+pss11*A11;
            pss00=A00*b00+A10*b10+q;
            pss01=A00*b01+A10*b11;
            pss11=A01*b01+A11*b11+q;
            float t00=pus00*A00+pus01*A10;
            float t01=pus00*A01+pus01*A11;
            float t10=pus10*A00+pus11*A10;
            float t11=pus10*A01+pus11*A11;
            pus00=t00;pus01=t01;pus10=t10;pus11=t11;
            float S00=puu00+2.0f*cst*pus00+c2*pss00+r;
            float S01=puu01+cst*(pus01+pus10)+c2*pss01;
            float S11=puu11+2.0f*cst*pus11+c2*pss11+r;
            float det=S00*S11-S01*S01;
            float id=1.0f/det;
            float G00=puu00+cst*pus00, G01=puu01+cst*pus01;
            float G10=puu01+cst*pus10, G11=puu11+cst*pus11;
            float G20=pus00+cst*pss00, G21=pus10+cst*pss01;
            float G30=pus01+cst*pss01, G31=pus11+cst*pss11;
            float W00=(G00*S11-G01*S01)*id, W01=(G01*S00-G00*S01)*id;
            float W10=(G10*S11-G11*S01)*id, W11=(G11*S00-G10*S01)*id;
            float W20=(G20*S11-G21*S01)*id, W21=(G21*S00-G20*S01)*id;
            float W30=(G30*S11-G31*S01)*id, W31=(G31*S00-G30*S01)*id;
            gp[0]=make_float4(W00,W01,W10,W11);
            gp[1]=make_float4(W20,W21,W30,W31);
            gp[2]=make_float4(S00,S01,S11,id);
            gp+=3;
            puu00-=W00*G00+W01*G01;
            puu01-=W00*G10+W01*G11;
            puu11-=W10*G10+W11*G11;
            pus00-=W00*G20+W01*G21;
            pus01-=W00*G30+W01*G31;
            pus10-=W10*G20+W11*G21;
            pus11-=W10*G30+W11*G31;
            pss00-=W20*G20+W21*G21;
            pss01-=W20*G30+W21*G31;
            pss11-=W30*G30+W31*G31;
        }
    }

    if(t0==T){
        g_pTf[0]=puu00; g_pTf[1]=puu01; g_pTf[2]=pus00; g_pTf[3]=pus01;
        g_pTf[4]=puu01; g_pTf[5]=puu11; g_pTf[6]=pus10; g_pTf[7]=pus11;
        g_pTf[8]=pus00; g_pTf[9]=pus10; g_pTf[10]=pss00; g_pTf[11]=pss01;
        g_pTf[12]=pus01; g_pTf[13]=pus11; g_pTf[14]=pss01; g_pTf[15]=pss11;
    } else {
        // one-time double bridge (proven math; Schur inverse instead of GJ)
        double dA00=A00, dA01=A01, dA10=A10, dA11=A11;
        double dq=q, dr=r, dc=5.65685424949238019521;
        double uu00=puu00, uu01=puu01, uu11=puu11;
        double us00=pus00, us01=pus01, us10=pus10, us11=pus11;
        double ss00=pss00, ss01=pss01, ss11=pss11;
        double L0[16], L1[16], M[16];
        for(int rep=0;rep<2;++rep){
            double b00=ss00*dA00+ss01*dA10, b01=ss00*dA01+ss01*dA11;
            double b10=ss01*dA00+ss11*dA10, b11=ss01*dA01+ss11*dA11;
            ss00=dA00*b00+dA10*b10+dq;
            ss01=dA00*b01+dA10*b11;
            ss11=dA01*b01+dA11*b11+dq;
            double t00=us00*dA00+us01*dA10, t01=us00*dA01+us01*dA11;
            double t10=us10*dA00+us11*dA10, t11=us10*dA01+us11*dA11;
            us00=t00;us01=t01;us10=t10;us11=t11;
            M[0]=uu00; M[1]=uu01; M[2]=us00; M[3]=us01;
            M[4]=uu01; M[5]=uu11; M[6]=us10; M[7]=us11;
            M[8]=us00; M[9]=us10; M[10]=ss00; M[11]=ss01;
            M[12]=us01; M[13]=us11; M[14]=ss01; M[15]=ss11;
            dinv4sym(M, (rep==0)?L0:L1);
            if(rep==1) break;
            double S00=uu00+2.0*dc*us00+32.0*ss00+dr;
            double S01=uu01+dc*(us01+us10)+32.0*ss01;
            double S11=uu11+2.0*dc*us11+32.0*ss11+dr;
            double id=1.0/(S00*S11-S01*S01);
            double G00=uu00+dc*us00, G01=uu01+dc*us01;
            double G10=uu01+dc*us10, G11=uu11+dc*us11;
            double G20=us00+dc*ss00, G21=us10+dc*ss01;
            double G30=us01+dc*ss01, G31=us11+dc*ss11;
            double W00=(G00*S11-G01*S01)*id, W01=(G01*S00-G00*S01)*id;
            double W10=(G10*S11-G11*S01)*id, W11=(G11*S00-G10*S01)*id;
            double W20=(G20*S11-G21*S01)*id, W21=(G21*S00-G20*S01)*id;
            double W30=(G30*S11-G31*S01)*id, W31=(G31*S00-G30*S01)*id;
            uu00-=W00*G00+W01*G01;
            uu01-=W00*G10+W01*G11;
            uu11-=W10*G10+W11*G11;
            us00-=W00*G20+W01*G21;
            us01-=W00*G30+W01*G31;
            us10-=W10*G20+W11*G21;
            us11-=W10*G30+W11*G31;
            ss00-=W20*G20+W21*G21;
            ss01-=W20*G30+W21*G31;
            ss11-=W30*G30+W31*G31;
        }
        for(int i=0;i<16;++i) g_lamW[i]=(float)L0[i];
        g_lamW[16]=(float)(L1[0]-L0[0]);
        g_lamW[17]=(float)(L1[1]-L0[1]);
        g_lamW[18]=(float)(L1[5]-L0[5]);
    }
}

// ================= K2: gain fill (blocks 0..nfill-1) + diff-scan (last block) =================
__global__ void __launch_bounds__(NTH,1)
hmm_k2(const float* __restrict__ track, const float* __restrict__ bias_scales,
       const float* __restrict__ obs_noise, int T, int t0, int nfill)
{
    const float cst = 5.656854249492381f;
    const float r = obs_noise[0]*obs_noise[0];

    if((int)blockIdx.x == nfill){
        // ---- diff-channel prefix scan (proven, moved from K1) ----
        __shared__ float wtot[8];
        __shared__ float fw[8];
        const int c = threadIdx.x;
        const int lane = c&31, wid = c>>5;
        const float SQ8 = 2.8284271247461903f;
        const float bs0=bias_scales[0], bs1=bias_scales[1];
        const float bsu=0.5f*(bs0+bs1);
        float del[CH];
        #pragma unroll
        for(int k=0;k<CH;++k){
            int t=c*CH+k;
            float x0 = (t<T)?track[2*t]:0.0f;
            float x1 = (t<T)?track[2*t+1]:0.0f;
            del[k]=SQ8*(x0-x1);
        }
        const float adf=r/bsu;
        float s=0.0f;
        #pragma unroll
        for(int k=0;k<CH;++k) s+=del[k];
        float v=s;
        #pragma unroll
        for(int off=1;off<32;off<<=1){
            float n=__shfl_up_sync(0xffffffffu,v,off);
            if(lane>=off) v+=n;
        }
        if(lane==31) wtot[wid]=v;
        __syncthreads();
        if(wid==0 && lane<8){
            float orig=wtot[lane], w=orig;
            #pragma unroll
            for(int off=1;off<8;off<<=1){
                float n=__shfl_up_sync(0xffu,w,off);
                if(lane>=off) w+=n;
            }
            wtot[lane]=w-orig;
        }
        __syncthreads();
        float run=(v-s)+wtot[wid];
        float wq=0.0f;
        #pragma unroll
        for(int k=0;k<CH;++k){
            int t=c*CH+k;
            if(t<T){
                float at=adf+(float)t;
                float zd=del[k]-run/at;
                wq += zd*zd*at/(r*(at+1.0f));
            }
            run+=del[k];
        }
        float ws=wred(wq);
        if(lane==0) fw[wid]=ws;
        __syncthreads();
        if(c==0){
            double acc=0.0;
            for(int i=0;i<8;++i) acc+=(double)fw[i];
            g_swq=acc;
        }
        return;
    }

    // ---- gain fill: one timestep per thread (proven) ----
    int g = blockIdx.x*NTH + threadIdx.x;
    int t = t0 + g;
    if(t >= T) return;
    const float c2 = 32.0f;

    float l02=g_lamW[2],  l03=g_lamW[3];
    float l12=g_lamW[6],  l13=g_lamW[7];
    float l22=g_lamW[10], l23=g_lamW[11], l33=g_lamW[15];
    float L00=g_lamW[0], L01=g_lamW[1], L11=g_lamW[5];
    float W0=g_lamW[16], W1=g_lamW[17], W2=g_lamW[18];

    float kt=(float)g;
    float l00=fmaf(kt,W0,L00);
    float l01=fmaf(kt,W1,L01);
    float l11=fmaf(kt,W2,L11);
    float iX=1.0f/(l00*l11-l01*l01);
    float X00=l11*iX, X01=-l01*iX, X11=l00*iX;
    float B100=X00*l02+X01*l12, B101=X00*l03+X01*l13;
    float B110=X01*l02+X11*l12, B111=X01*l03+X11*l13;
    float Sp00=l22-(l02*B100+l12*B110);
    float Sp01=l23-(l02*B101+l12*B111);
    float Sp11=l33-(l03*B101+l13*B111);
    float iS=1.0f/(Sp00*Sp11-Sp01*Sp01);
    float Z00=Sp11*iS, Z01=-Sp01*iS, Z11=Sp00*iS;
    float pus00=-(B100*Z00+B101*Z01);
    float pus01=-(B100*Z01+B101*Z11);
    float pus10=-(B110*Z00+B111*Z01);
    float pus11=-(B110*Z01+B111*Z11);
    float puu00=X00-(pus00*B100+pus01*B101);
    float puu01=X01-(pus00*B110+pus01*B111);
    float puu11=X11-(pus10*B110+pus11*B111);
    float pss00=Z00, pss01=Z01, pss11=Z11;
    float S00=puu00+2.0f*cst*pus00+c2*pss00+r;
    float S01=puu01+cst*(pus01+pus10)+c2*pss01;
    float S11=puu11+2.0f*cst*pus11+c2*pss11+r;
    float det=S00*S11-S01*S01;
    float id=1.0f/det;
    float G00=puu00+cst*pus00, G01=puu01+cst*pus01;
    float G10=puu01+cst*pus10, G11=puu11+cst*pus11;
    float G20=pus00+cst*pss00, G21=pus10+cst*pss01;
    float G30=pus01+cst*pss01, G31=pus11+cst*pss11;
    float W00=(G00*S11-G01*S01)*id, W01=(G01*S00-G00*S01)*id;
    float W10=(G10*S11-G11*S01)*id, W11=(G11*S00-G10*S01)*id;
    float W20=(G20*S11-G21*S01)*id, W21=(G21*S00-G20*S01)*id;
    float W30=(G30*S11-G31*S01)*id, W31=(G31*S00-G30*S01)*id;
    g_kv[t*3+0]=make_float4(W00,W01,W10,W11);
    g_kv[t*3+1]=make_float4(W20,W21,W30,W31);
    g_kv[t*3+2]=make_float4(S00,S01,S11,id);
    if(t==T-1){
        float f0=puu00-(W00*G00+W01*G01);
        float f1=puu01-(W00*G10+W01*G11);
        float f5=puu11-(W10*G10+W11*G11);
        float f2=pus00-(W00*G20+W01*G21);
        float f3=pus01-(W00*G30+W01*G31);
        float f6=pus10-(W10*G20+W11*G21);
        float f7=pus11-(W10*G30+W11*G31);
        float f10=pss00-(W20*G20+W21*G21);
        float f11=pss01-(W20*G30+W21*G31);
        float f15=pss11-(W30*G30+W31*G31);
        g_pTf[0]=f0;  g_pTf[1]=f1;  g_pTf[2]=f2;  g_pTf[3]=f3;
        g_pTf[4]=f1;  g_pTf[5]=f5;  g_pTf[6]=f6;  g_pTf[7]=f7;
        g_pTf[8]=f2;  g_pTf[9]=f6;  g_pTf[10]=f10; g_pTf[11]=f11;
        g_pTf[12]=f3; g_pTf[13]=f7; g_pTf[14]=f11; g_pTf[15]=f15;
    }
}

// ================= K3: mean scan + replay + epilogue + output (proven) =================
__global__ void __launch_bounds__(NTH,1)
hmm_k3(const float* __restrict__ track, const float* __restrict__ bias_scales,
       const float* __restrict__ obs_noise, const float* __restrict__ trans_noise,
       const float* __restrict__ Ain, const float* __restrict__ init_cov,
       float* __restrict__ out, int T, int out_size)
{
    __shared__ float elems[NTH*20];
    __shared__ float fw[8];
    __shared__ double sred[2];
    __shared__ float shr[24];

    const int c = threadIdx.x;
    const int lane = c&31, wid = c>>5;
    const float SQ8 = 2.8284271247461903f;
    const float cst = 5.656854249492381f;

    const float bs0=bias_scales[0], bs1=bias_scales[1];
    const float bsu=0.5f*(bs0+bs1);
    const float r=obs_noise[0]*obs_noise[0];
    const float A00=Ain[0], A01=Ain[1], A10=Ain[2], A11=Ain[3];

    float sig[CH];
    #pragma unroll
    for(int k=0;k<CH;++k){
        int t=c*CH+k;
        float x0 = (t<T)?track[2*t]:0.0f;
        float x1 = (t<T)?track[2*t+1]:0.0f;
        sig[k]=SQ8*(x0+x1);
    }

    float Eo[16]={1,0,0,0, 0,1,0,0, 0,0,1,0, 0,0,0,1};
    float bo[4]={0,0,0,0};
    #pragma unroll
    for(int k=0;k<CH;++k){
        int t=c*CH+k;
        float4 ka = g_kv[t*3+0];
        float4 kb = g_kv[t*3+1];
        float N0[4]={1.0f-ka.x, -ka.y, -cst*ka.x, -cst*ka.y};
        float N1[4]={-ka.z, 1.0f-ka.w, -cst*ka.z, -cst*ka.w};
        float N2[4]={-kb.x, -kb.y, 1.0f-cst*kb.x, -cst*kb.y};
        float N3[4]={-kb.z, -kb.w, -cst*kb.z, 1.0f-cst*kb.w};
        float Ek[16];
        Ek[0]=N0[0]; Ek[1]=N0[1]; Ek[2]=N0[2]*A00+N0[3]*A01; Ek[3]=N0[2]*A10+N0[3]*A11;
        Ek[4]=N1[0]; Ek[5]=N1[1]; Ek[6]=N1[2]*A00+N1[3]*A01; Ek[7]=N1[2]*A10+N1[3]*A11;
        Ek[8]=N2[0]; Ek[9]=N2[1]; Ek[10]=N2[2]*A00+N2[3]*A01; Ek[11]=N2[2]*A10+N2[3]*A11;
        Ek[12]=N3[0]; Ek[13]=N3[1]; Ek[14]=N3[2]*A00+N3[3]*A01; Ek[15]=N3[2]*A10+N3[3]*A11;
        float y=sig[k];
        float bs_[4]={(ka.x+ka.y)*y,(ka.z+ka.w)*y,(kb.x+kb.y)*y,(kb.z+kb.w)*y};
        float En[16], bn[4];
        #pragma unroll
        for(int i=0;i<4;++i){
            #pragma unroll
            for(int j=0;j<4;++j)
                En[i*4+j]=Ek[i*4]*Eo[j]+Ek[i*4+1]*Eo[4+j]+Ek[i*4+2]*Eo[8+j]+Ek[i*4+3]*Eo[12+j];
            bn[i]=Ek[i*4]*bo[0]+Ek[i*4+1]*bo[1]+Ek[i*4+2]*bo[2]+Ek[i*4+3]*bo[3]+bs_[i];
        }
        #pragma unroll
        for(int i=0;i<16;++i) Eo[i]=En[i];
        #pragma unroll
        for(int i=0;i<4;++i) bo[i]=bn[i];
    }
    #pragma unroll
    for(int i=0;i<16;++i) elems[c*20+i]=Eo[i];
    #pragma unroll
    for(int i=0;i<4;++i) elems[c*20+16+i]=bo[i];
    __syncthreads();

    for(int off=1; off<NTH; off<<=1){
        float El[16], bl[4];
        bool act = (c>=off);
        if(act){
            const float* lp=elems+(c-off)*20;
            #pragma unroll
            for(int i=0;i<16;++i) El[i]=lp[i];
            #pragma unroll
            for(int i=0;i<4;++i) bl[i]=lp[16+i];
        }
        __syncthreads();
        if(act){
            float En[16], bn[4];
            #pragma unroll
            for(int i=0;i<4;++i){
                #pragma unroll
                for(int j=0;j<4;++j)
                    En[i*4+j]=Eo[i*4]*El[j]+Eo[i*4+1]*El[4+j]+Eo[i*4+2]*El[8+j]+Eo[i*4+3]*El[12+j];
                bn[i]=Eo[i*4]*bl[0]+Eo[i*4+1]*bl[1]+Eo[i*4+2]*bl[2]+Eo[i*4+3]*bl[3]+bo[i];
            }
            #pragma unroll
            for(int i=0;i<16;++i){ Eo[i]=En[i]; elems[c*20+i]=En[i]; }
            #pragma unroll
            for(int i=0;i<4;++i){ bo[i]=bn[i]; elems[c*20+16+i]=bn[i]; }
        }
        __syncthreads();
    }

    float m0=0.f,m1=0.f,m2=0.f,m3=0.f;
    if(c>0){
        const float* pp=elems+(c-1)*20+16;
        m0=pp[0]; m1=pp[1]; m2=pp[2]; m3=pp[3];
    }
    float qd=0.0f;
    float prodm=1.0f;
    int eacc=0;
    #pragma unroll
    for(int k=0;k<CH;++k){
        int t=c*CH+k;
        float4 ka = g_kv[t*3+0];
        float4 kb = g_kv[t*3+1];
        float4 sc = g_kv[t*3+2];
        float p2=A00*m2+A10*m3;
        float p3=A01*m2+A11*m3;
        float y=sig[k];
        float z0=y-m0-cst*p2;
        float z1=y-m1-cst*p3;
        float id=sc.w;
        float u0=(sc.z*z0-sc.y*z1)*id;
        float u1=(sc.x*z1-sc.y*z0)*id;
        qd += z0*u0+z1*u1;
        float det=sc.x*sc.z-sc.y*sc.y;
        int bi=__float_as_int(det);
        eacc += ((bi>>23)&255)-127;
        prodm *= __int_as_float((bi&0x807FFFFF)|0x3F800000);
        int pb=__float_as_int(prodm);
        eacc += ((pb>>23)&255)-127;
        prodm = __int_as_float((pb&0x807FFFFF)|0x3F800000);
        m0 += ka.x*z0+ka.y*z1;
        m1 += ka.z*z0+ka.w*z1;
        m2  = p2 + kb.x*z0+kb.y*z1;
        m3  = p3 + kb.z*z0+kb.w*z1;
    }
    float ldt=fmaf((float)eacc, 0.6931471805599453f, logf(prodm));

    {
        float s=wred(qd);
        if(lane==0) fw[wid]=s;
        __syncthreads();
        if(c==0){
            double acc=0.0;
            for(int i=0;i<8;++i) acc+=(double)fw[i];
            sred[0]=acc;
        }
        __syncthreads();
        s=wred(ldt);
        if(lane==0) fw[wid]=s;
        __syncthreads();
        if(c==0){
            double acc=0.0;
            for(int i=0;i<8;++i) acc+=(double)fw[i];
            sred[1]=acc;
        }
        __syncthreads();
    }

    if(c==0){
        double ld2=sred[1];
        double s_wq=g_swq, s_qd=sred[0];
        double Td=(double)T, rr_=(double)r;
        double a0d=rr_/(double)bs0, a1d=rr_/(double)bs1, aud=rr_/(double)bsu;
        const double LOG2PI=1.8378770664093453;
        double ld_contrast=15.0*(4.0*Td*log(rr_)+2.0*log((a0d+Td)/a0d)+2.0*log((a1d+Td)/a1d));
        double ld_diff=2.0*(Td*log(rr_)+log((aud+Td)/aud));
        double logp=-0.5*(64.0*Td*LOG2PI)-0.5*(s_qd+2.0*s_wq)-0.5*(ld2+ld_contrast+ld_diff);
        shr[19]=(float)logp;

        float Mm[4][8];
        for(int i=0;i<4;++i)
            for(int j=0;j<4;++j){ Mm[i][j]=g_pTf[i*4+j]; Mm[i][4+j]=(i==j)?1.0f:0.0f; }
        for(int cc=0;cc<4;++cc){
            int piv=cc; float mx=fabsf(Mm[cc][cc]);
            for(int rr=cc+1;rr<4;++rr){
                float aa=fabsf(Mm[rr][cc]);
                if(aa>mx){mx=aa;piv=rr;}
            }
            if(piv!=cc)
                for(int j=0;j<8;++j){ float tm=Mm[cc][j]; Mm[cc][j]=Mm[piv][j]; Mm[piv][j]=tm; }
            float pv=1.0f/Mm[cc][cc];
            for(int j=0;j<8;++j) Mm[cc][j]*=pv;
            for(int rr=0;rr<4;++rr){
                if(rr==cc) continue;
                float f=Mm[rr][cc];
                for(int j=0;j<8;++j) Mm[rr][j]-=f*Mm[cc][j];
            }
        }
        for(int i=0;i<4;++i)
            for(int j=0;j<4;++j) shr[i*4+j]=Mm[i][4+j];
        shr[16]=(float)(1.0/(double)bs0+Td/rr_);
        shr[17]=(float)(1.0/(double)bs1+Td/rr_);
        shr[18]=(float)(1.0/(double)bsu+Td/rr_);
    }
    __syncthreads();

    if(c==0 && out_size>0) out[0]=shr[19];
    const int NP=66*66;
    const float INV32=0.03125f;
    const float INVS32=0.17677669529663687f;
    for(int idx=c; idx<NP; idx+=NTH){
        if(idx+1>=out_size) break;
        int i=idx/66, j=idx-66*i;
        float v;
        if(i<64 && j<64){
            int pi=i>>5, pj=j>>5, ei=i&1, ej=j&1;
            v=shr[pi*4+pj]*INV32;
            if(pi==pj){
                v += ((ei==ej)?shr[18]:-shr[18])*INV32;
                if(ei==ej){
                    v -= shr[16+ei]*0.0625f;
                    if(i==j) v += shr[16+ei];
                }
            }
        } else if(i<64){
            int pi=i>>5;
            v=shr[pi*4+2+(j-64)]*INVS32;
        } else if(j<64){
            int pj=j>>5;
            v=shr[pj*4+2+(i-64)]*INVS32;
        } else {
            v=shr[(2+i-64)*4+(2+j-64)];
        }
        out[1+idx]=v;
    }
}

extern "C" void kernel_launch(void* const* d_in, const int* in_sizes, int n_in,
                              void* d_out, int out_size) {
    const float* track     = (const float*)d_in[0];
    const float* bias_sc   = (const float*)d_in[1];
    const float* obs_noise = (const float*)d_in[2];
    const float* trans_n   = (const float*)d_in[3];
    const float* A         = (const float*)d_in[4];
    const float* init_cov  = (const float*)d_in[5];
    float* out = (float*)d_out;
    int T = in_sizes[0]/2;
    if (T > TT) T = TT;
    int t0 = (T >= T0) ? T0 : T;

    hmm_k1<<<1, 32>>>(track, bias_sc, obs_noise, trans_n, A, init_cov, T, t0);
    int nfill = (T > t0) ? (T - t0 + NTH - 1) / NTH : 0;
    hmm_k2<<<nfill + 1, NTH>>>(track, bias_sc, obs_noise, T, t0, nfill);
    hmm_k3<<<1, NTH>>>(track, bias_sc, obs_noise, trans_n, A, init_cov, out, T, out_size);
}

// round 13
// speedup vs baseline: 58.2883x; 1.0724x over previous
#include <cuda_runtime.h>
#include <math.h>

#define NTH 256
#define CH 16
#define TT 4096
#define T0 16

__device__ float4 g_kv[TT*3];
__device__ float  g_lamW[20];
__device__ float  g_pTf[16];
__device__ double g_swq;

// symmetric-PD 4x4 inverse via 2x2 block Schur, double
__device__ __forceinline__ void dinv4sym(const double* m, double* o){
    double a00=m[0], a01=m[1], a11=m[5];
    double idA=1.0/(a00*a11-a01*a01);
    double Ai00=a11*idA, Ai01=-a01*idA, Ai11=a00*idA;
    double b00=m[2], b01=m[3], b10=m[6], b11=m[7];
    double U00=Ai00*b00+Ai01*b10, U01=Ai00*b01+Ai01*b11;
    double U10=Ai01*b00+Ai11*b10, U11=Ai01*b01+Ai11*b11;
    double c00=m[10]-(b00*U00+b10*U10);
    double c01=m[11]-(b00*U01+b10*U11);
    double c11=m[15]-(b01*U01+b11*U11);
    double idC=1.0/(c00*c11-c01*c01);
    double Si00=c11*idC, Si01=-c01*idC, Si11=c00*idC;
    double TR00=-(U00*Si00+U01*Si01), TR01=-(U00*Si01+U01*Si11);
    double TR10=-(U10*Si00+U11*Si01), TR11=-(U10*Si01+U11*Si11);
    double TL00=Ai00-(TR00*U00+TR01*U01);
    double TL01=Ai01-(TR00*U10+TR01*U11);
    double TL11=Ai11-(TR10*U10+TR11*U11);
    o[0]=TL00; o[1]=TL01; o[2]=TR00; o[3]=TR01;
    o[4]=TL01; o[5]=TL11; o[6]=TR10; o[7]=TR11;
    o[8]=TR00; o[9]=TR10; o[10]=Si00; o[11]=Si01;
    o[12]=TR01; o[13]=TR11; o[14]=Si01; o[15]=Si11;
}

__device__ __forceinline__ float wred(float v){
    #pragma unroll
    for(int off=16; off; off>>=1) v += __shfl_down_sync(0xffffffffu, v, off);
    return v;
}

// ================= K1: burn-in + bridge only =================
__global__ void __launch_bounds__(32,1)
hmm_k1(const float* __restrict__ track, const float* __restrict__ bias_scales,
       const float* __restrict__ obs_noise, const float* __restrict__ trans_noise,
       const float* __restrict__ Ain, const float* __restrict__ init_cov,
       int T, int t0)
{
    if(threadIdx.x != 0) return;

    const float cst = 5.656854249492381f;
    const float bs0=bias_scales[0], bs1=bias_scales[1];
    const float bsu=0.5f*(bs0+bs1);
    const float r=obs_noise[0]*obs_noise[0];
    const float q=trans_noise[0]*trans_noise[0];
    const float A00=Ain[0], A01=Ain[1], A10=Ain[2], A11=Ain[3];

    float puu00=bsu, puu01=0.0f, puu11=bsu;
    float pus00=0.f, pus01=0.f, pus10=0.f, pus11=0.f;
    float pss00=init_cov[0], pss01=init_cov[1], pss11=init_cov[3];
    const float c2=32.0f;
    float4* gp = g_kv;
    for(int t=0;t<t0;++t){
        float b00=pss00*A00+pss01*A10;
        float b01=pss00*A01+pss01*A11;
        float b10=pss01*A00+pss11*A10;
        float b11=pss01*A01+pss11*A11;
        pss00=A00*b00+A10*b10+q;
        pss01=A00*b01+A10*b11;
        pss11=A01*b01+A11*b11+q;
        float t00=pus00*A00+pus01*A10;
        float t01=pus00*A01+pus01*A11;
        float t10=pus10*A00+pus11*A10;
        float t11=pus10*A01+pus11*A11;
        pus00=t00;pus01=t01;pus10=t10;pus11=t11;
        float S00=puu00+2.0f*cst*pus00+c2*pss00+r;
        float S01=puu01+cst*(pus01+pus10)+c2*pss01;
        float S11=puu11+2.0f*cst*pus11+c2*pss11+r;
        float det=S00*S11-S01*S01;
        float id=1.0f/det;
        float G00=puu00+cst*pus00, G01=puu01+cst*pus01;
        float G10=puu01+cst*pus10, G11=puu11+cst*pus11;
        float G20=pus00+cst*pss00, G21=pus10+cst*pss01;
        float G30=pus01+cst*pss01, G31=pus11+cst*pss11;
        float W00=(G00*S11-G01*S01)*id, W01=(G01*S00-G00*S01)*id;
        float W10=(G10*S11-G11*S01)*id, W11=(G11*S00-G10*S01)*id;
        float W20=(G20*S11-G21*S01)*id, W21=(G21*S00-G20*S01)*id;
        float W30=(G30*S11-G31*S01)*id, W31=(G31*S00-G30*S01)*id;
        gp[0]=make_float4(W00,W01,W10,W11);
        gp[1]=make_float4(W20,W21,W30,W31);
        gp[2]=make_float4(S00,S01,S11,id);
        gp+=3;
        puu00-=W00*G00+W01*G01;
        puu01-=W00*G10+W01*G11;
        puu11-=W10*G10+W11*G11;
        pus00-=W00*G20+W01*G21;
        pus01-=W00*G30+W01*G31;
        pus10-=W10*G20+W11*G21;
        pus11-=W10*G30+W11*G31;
        pss00-=W20*G20+W21*G21;
        pss01-=W20*G30+W21*G31;
        pss11-=W30*G30+W31*G31;
    }

    if(t0==T){
        g_pTf[0]=puu00; g_pTf[1]=puu01; g_pTf[2]=pus00; g_pTf[3]=pus01;
        g_pTf[4]=puu01; g_pTf[5]=puu11; g_pTf[6]=pus10; g_pTf[7]=pus11;
        g_pTf[8]=pus00; g_pTf[9]=pus10; g_pTf[10]=pss00; g_pTf[11]=pss01;
        g_pTf[12]=pus01; g_pTf[13]=pus11; g_pTf[14]=pss01; g_pTf[15]=pss11;
    } else {
        // one-time double bridge (proven)
        double dA00=A00, dA01=A01, dA10=A10, dA11=A11;
        double dq=q, dr=r, dc=5.65685424949238019521;
        double uu00=puu00, uu01=puu01, uu11=puu11;
        double us00=pus00, us01=pus01, us10=pus10, us11=pus11;
        double ss00=pss00, ss01=pss01, ss11=pss11;
        double L0[16], L1[16], M[16];
        for(int rep=0;rep<2;++rep){
            double b00=ss00*dA00+ss01*dA10, b01=ss00*dA01+ss01*dA11;
            double b10=ss01*dA00+ss11*dA10, b11=ss01*dA01+ss11*dA11;
            ss00=dA00*b00+dA10*b10+dq;
            ss01=dA00*b01+dA10*b11;
            ss11=dA01*b01+dA11*b11+dq;
            double t00=us00*dA00+us01*dA10, t01=us00*dA01+us01*dA11;
            double t10=us10*dA00+us11*dA10, t11=us10*dA01+us11*dA11;
            us00=t00;us01=t01;us10=t10;us11=t11;
            M[0]=uu00; M[1]=uu01; M[2]=us00; M[3]=us01;
            M[4]=uu01; M[5]=uu11; M[6]=us10; M[7]=us11;
            M[8]=us00; M[9]=us10; M[10]=ss00; M[11]=ss01;
            M[12]=us01; M[13]=us11; M[14]=ss01; M[15]=ss11;
            dinv4sym(M, (rep==0)?L0:L1);
            if(rep==1) break;
            double S00=uu00+2.0*dc*us00+32.0*ss00+dr;
            double S01=uu01+dc*(us01+us10)+32.0*ss01;
            double S11=uu11+2.0*dc*us11+32.0*ss11+dr;
            double id=1.0/(S00*S11-S01*S01);
            double G00=uu00+dc*us00, G01=uu01+dc*us01;
            double G10=uu01+dc*us10, G11=uu11+dc*us11;
            double G20=us00+dc*ss00, G21=us10+dc*ss01;
            double G30=us01+dc*ss01, G31=us11+dc*ss11;
            double W00=(G00*S11-G01*S01)*id, W01=(G01*S00-G00*S01)*id;
            double W10=(G10*S11-G11*S01)*id, W11=(G11*S00-G10*S01)*id;
            double W20=(G20*S11-G21*S01)*id, W21=(G21*S00-G20*S01)*id;
            double W30=(G30*S11-G31*S01)*id, W31=(G31*S00-G30*S01)*id;
            uu00-=W00*G00+W01*G01;
            uu01-=W00*G10+W01*G11;
            uu11-=W10*G10+W11*G11;
            us00-=W00*G20+W01*G21;
            us01-=W00*G30+W01*G31;
            us10-=W10*G20+W11*G21;
            us11-=W10*G30+W11*G31;
            ss00-=W20*G20+W21*G21;
            ss01-=W20*G30+W21*G31;
            ss11-=W30*G30+W31*G31;
        }
        for(int i=0;i<16;++i) g_lamW[i]=(float)L0[i];
        g_lamW[16]=(float)(L1[0]-L0[0]);
        g_lamW[17]=(float)(L1[1]-L0[1]);
        g_lamW[18]=(float)(L1[5]-L0[5]);
    }
}

// ================= K2: gain fill (blocks 0..nfill-1) + diff-scan (last block) =================
__global__ void __launch_bounds__(NTH,1)
hmm_k2(const float* __restrict__ track, const float* __restrict__ bias_scales,
       const float* __restrict__ obs_noise, int T, int t0, int nfill)
{
    const float cst = 5.656854249492381f;
    const float r = obs_noise[0]*obs_noise[0];

    if((int)blockIdx.x == nfill){
        // ---- diff-channel prefix scan (proven) ----
        __shared__ float wtot[8];
        __shared__ float fw[8];
        const int c = threadIdx.x;
        const int lane = c&31, wid = c>>5;
        const float SQ8 = 2.8284271247461903f;
        const float bs0=bias_scales[0], bs1=bias_scales[1];
        const float bsu=0.5f*(bs0+bs1);
        float del[CH];
        #pragma unroll
        for(int k=0;k<CH;++k){
            int t=c*CH+k;
            float x0 = (t<T)?track[2*t]:0.0f;
            float x1 = (t<T)?track[2*t+1]:0.0f;
            del[k]=SQ8*(x0-x1);
        }
        const float adf=r/bsu;
        float s=0.0f;
        #pragma unroll
        for(int k=0;k<CH;++k) s+=del[k];
        float v=s;
        #pragma unroll
        for(int off=1;off<32;off<<=1){
            float n=__shfl_up_sync(0xffffffffu,v,off);
            if(lane>=off) v+=n;
        }
        if(lane==31) wtot[wid]=v;
        __syncthreads();
        if(wid==0 && lane<8){
            float orig=wtot[lane], w=orig;
            #pragma unroll
            for(int off=1;off<8;off<<=1){
                float n=__shfl_up_sync(0xffu,w,off);
                if(lane>=off) w+=n;
            }
            wtot[lane]=w-orig;
        }
        __syncthreads();
        float run=(v-s)+wtot[wid];
        float wq=0.0f;
        #pragma unroll
        for(int k=0;k<CH;++k){
            int t=c*CH+k;
            if(t<T){
                float at=adf+(float)t;
                float zd=del[k]-run/at;
                wq += zd*zd*at/(r*(at+1.0f));
            }
            run+=del[k];
        }
        float ws=wred(wq);
        if(lane==0) fw[wid]=ws;
        __syncthreads();
        if(c==0){
            double acc=0.0;
            for(int i=0;i<8;++i) acc+=(double)fw[i];
            g_swq=acc;
        }
        return;
    }

    // ---- gain fill: one timestep per thread (proven) ----
    int g = blockIdx.x*NTH + threadIdx.x;
    int t = t0 + g;
    if(t >= T) return;
    const float c2 = 32.0f;

    float l02=g_lamW[2],  l03=g_lamW[3];
    float l12=g_lamW[6],  l13=g_lamW[7];
    float l22=g_lamW[10], l23=g_lamW[11], l33=g_lamW[15];
    float L00=g_lamW[0], L01=g_lamW[1], L11=g_lamW[5];
    float W0=g_lamW[16], W1=g_lamW[17], W2=g_lamW[18];

    float kt=(float)g;
    float l00=fmaf(kt,W0,L00);
    float l01=fmaf(kt,W1,L01);
    float l11=fmaf(kt,W2,L11);
    float iX=1.0f/(l00*l11-l01*l01);
    float X00=l11*iX, X01=-l01*iX, X11=l00*iX;
    float B100=X00*l02+X01*l12, B101=X00*l03+X01*l13;
    float B110=X01*l02+X11*l12, B111=X01*l03+X11*l13;
    float Sp00=l22-(l02*B100+l12*B110);
    float Sp01=l23-(l02*B101+l12*B111);
    float Sp11=l33-(l03*B101+l13*B111);
    float iS=1.0f/(Sp00*Sp11-Sp01*Sp01);
    float Z00=Sp11*iS, Z01=-Sp01*iS, Z11=Sp00*iS;
    float pus00=-(B100*Z00+B101*Z01);
    float pus01=-(B100*Z01+B101*Z11);
    float pus10=-(B110*Z00+B111*Z01);
    float pus11=-(B110*Z01+B111*Z11);
    float puu00=X00-(pus00*B100+pus01*B101);
    float puu01=X01-(pus00*B110+pus01*B111);
    float puu11=X11-(pus10*B110+pus11*B111);
    float pss00=Z00, pss01=Z01, pss11=Z11;
    float S00=puu00+2.0f*cst*pus00+c2*pss00+r;
    float S01=puu01+cst*(pus01+pus10)+c2*pss01;
    float S11=puu11+2.0f*cst*pus11+c2*pss11+r;
    float det=S00*S11-S01*S01;
    float id=1.0f/det;
    float G00=puu00+cst*pus00, G01=puu01+cst*pus01;
    float G10=puu01+cst*pus10, G11=puu11+cst*pus11;
    float G20=pus00+cst*pss00, G21=pus10+cst*pss01;
    float G30=pus01+cst*pss01, G31=pus11+cst*pss11;
    float W00=(G00*S11-G01*S01)*id, W01=(G01*S00-G00*S01)*id;
    float W10=(G10*S11-G11*S01)*id, W11=(G11*S00-G10*S01)*id;
    float W20=(G20*S11-G21*S01)*id, W21=(G21*S00-G20*S01)*id;
    float W30=(G30*S11-G31*S01)*id, W31=(G31*S00-G30*S01)*id;
    g_kv[t*3+0]=make_float4(W00,W01,W10,W11);
    g_kv[t*3+1]=make_float4(W20,W21,W30,W31);
    g_kv[t*3+2]=make_float4(S00,S01,S11,id);
    if(t==T-1){
        float f0=puu00-(W00*G00+W01*G01);
        float f1=puu01-(W00*G10+W01*G11);
        float f5=puu11-(W10*G10+W11*G11);
        float f2=pus00-(W00*G20+W01*G21);
        float f3=pus01-(W00*G30+W01*G31);
        float f6=pus10-(W10*G20+W11*G21);
        float f7=pus11-(W10*G30+W11*G31);
        float f10=pss00-(W20*G20+W21*G21);
        float f11=pss01-(W20*G30+W21*G31);
        float f15=pss11-(W30*G30+W31*G31);
        g_pTf[0]=f0;  g_pTf[1]=f1;  g_pTf[2]=f2;  g_pTf[3]=f3;
        g_pTf[4]=f1;  g_pTf[5]=f5;  g_pTf[6]=f6;  g_pTf[7]=f7;
        g_pTf[8]=f2;  g_pTf[9]=f6;  g_pTf[10]=f10; g_pTf[11]=f11;
        g_pTf[12]=f3; g_pTf[13]=f7; g_pTf[14]=f11; g_pTf[15]=f15;
    }
}

// ================= K3: mean scan + replay + epilogue + output (proven) =================
__global__ void __launch_bounds__(NTH,1)
hmm_k3(const float* __restrict__ track, const float* __restrict__ bias_scales,
       const float* __restrict__ obs_noise, const float* __restrict__ trans_noise,
       const float* __restrict__ Ain, const float* __restrict__ init_cov,
       float* __restrict__ out, int T, int out_size)
{
    __shared__ float elems[NTH*20];
    __shared__ float fw[8];
    __shared__ double sred[2];
    __shared__ float shr[24];

    const int c = threadIdx.x;
    const int lane = c&31, wid = c>>5;
    const float SQ8 = 2.8284271247461903f;
    const float cst = 5.656854249492381f;

    const float bs0=bias_scales[0], bs1=bias_scales[1];
    const float bsu=0.5f*(bs0+bs1);
    const float r=obs_noise[0]*obs_noise[0];
    const float A00=Ain[0], A01=Ain[1], A10=Ain[2], A11=Ain[3];

    float sig[CH];
    #pragma unroll
    for(int k=0;k<CH;++k){
        int t=c*CH+k;
        float x0 = (t<T)?track[2*t]:0.0f;
        float x1 = (t<T)?track[2*t+1]:0.0f;
        sig[k]=SQ8*(x0+x1);
    }

    float Eo[16]={1,0,0,0, 0,1,0,0, 0,0,1,0, 0,0,0,1};
    float bo[4]={0,0,0,0};
    #pragma unroll
    for(int k=0;k<CH;++k){
        int t=c*CH+k;
        float4 ka = g_kv[t*3+0];
        float4 kb = g_kv[t*3+1];
        float N0[4]={1.0f-ka.x, -ka.y, -cst*ka.x, -cst*ka.y};
        float N1[4]={-ka.z, 1.0f-ka.w, -cst*ka.z, -cst*ka.w};
        float N2[4]={-kb.x, -kb.y, 1.0f-cst*kb.x, -cst*kb.y};
        float N3[4]={-kb.z, -kb.w, -cst*kb.z, 1.0f-cst*kb.w};
        float Ek[16];
        Ek[0]=N0[0]; Ek[1]=N0[1]; Ek[2]=N0[2]*A00+N0[3]*A01; Ek[3]=N0[2]*A10+N0[3]*A11;
        Ek[4]=N1[0]; Ek[5]=N1[1]; Ek[6]=N1[2]*A00+N1[3]*A01; Ek[7]=N1[2]*A10+N1[3]*A11;
        Ek[8]=N2[0]; Ek[9]=N2[1]; Ek[10]=N2[2]*A00+N2[3]*A01; Ek[11]=N2[2]*A10+N2[3]*A11;
        Ek[12]=N3[0]; Ek[13]=N3[1]; Ek[14]=N3[2]*A00+N3[3]*A01; Ek[15]=N3[2]*A10+N3[3]*A11;
        float y=sig[k];
        float bs_[4]={(ka.x+ka.y)*y,(ka.z+ka.w)*y,(kb.x+kb.y)*y,(kb.z+kb.w)*y};
        float En[16], bn[4];
        #pragma unroll
        for(int i=0;i<4;++i){
            #pragma unroll
            for(int j=0;j<4;++j)
                En[i*4+j]=Ek[i*4]*Eo[j]+Ek[i*4+1]*Eo[4+j]+Ek[i*4+2]*Eo[8+j]+Ek[i*4+3]*Eo[12+j];
            bn[i]=Ek[i*4]*bo[0]+Ek[i*4+1]*bo[1]+Ek[i*4+2]*bo[2]+Ek[i*4+3]*bo[3]+bs_[i];
        }
        #pragma unroll
        for(int i=0;i<16;++i) Eo[i]=En[i];
        #pragma unroll
        for(int i=0;i<4;++i) bo[i]=bn[i];
    }
    #pragma unroll
    for(int i=0;i<16;++i) elems[c*20+i]=Eo[i];
    #pragma unroll
    for(int i=0;i<4;++i) elems[c*20+16+i]=bo[i];
    __syncthreads();

    for(int off=1; off<NTH; off<<=1){
        float El[16], bl[4];
        bool act = (c>=off);
        if(act){
            const float* lp=elems+(c-off)*20;
            #pragma unroll
            for(int i=0;i<16;++i) El[i]=lp[i];
            #pragma unroll
            for(int i=0;i<4;++i) bl[i]=lp[16+i];
        }
        __syncthreads();
        if(act){
            float En[16], bn[4];
            #pragma unroll
            for(int i=0;i<4;++i){
                #pragma unroll
                for(int j=0;j<4;++j)
                    En[i*4+j]=Eo[i*4]*El[j]+Eo[i*4+1]*El[4+j]+Eo[i*4+2]*El[8+j]+Eo[i*4+3]*El[12+j];
                bn[i]=Eo[i*4]*bl[0]+Eo[i*4+1]*bl[1]+Eo[i*4+2]*bl[2]+Eo[i*4+3]*bl[3]+bo[i];
            }
            #pragma unroll
            for(int i=0;i<16;++i){ Eo[i]=En[i]; elems[c*20+i]=En[i]; }
            #pragma unroll
            for(int i=0;i<4;++i){ bo[i]=bn[i]; elems[c*20+16+i]=bn[i]; }
        }
        __syncthreads();
    }

    float m0=0.f,m1=0.f,m2=0.f,m3=0.f;
    if(c>0){
        const float* pp=elems+(c-1)*20+16;
        m0=pp[0]; m1=pp[1]; m2=pp[2]; m3=pp[3];
    }
    float qd=0.0f;
    float prodm=1.0f;
    int eacc=0;
    #pragma unroll
    for(int k=0;k<CH;++k){
        int t=c*CH+k;
        float4 ka = g_kv[t*3+0];
        float4 kb = g_kv[t*3+1];
        float4 sc = g_kv[t*3+2];
        float p2=A00*m2+A10*m3;
        float p3=A01*m2+A11*m3;
        float y=sig[k];
        float z0=y-m0-cst*p2;
        float z1=y-m1-cst*p3;
        float id=sc.w;
        float u0=(sc.z*z0-sc.y*z1)*id;
        float u1=(sc.x*z1-sc.y*z0)*id;
        qd += z0*u0+z1*u1;
        float det=sc.x*sc.z-sc.y*sc.y;
        int bi=__float_as_int(det);
        eacc += ((bi>>23)&255)-127;
        prodm *= __int_as_float((bi&0x807FFFFF)|0x3F800000);
        int pb=__float_as_int(prodm);
        eacc += ((pb>>23)&255)-127;
        prodm = __int_as_float((pb&0x807FFFFF)|0x3F800000);
        m0 += ka.x*z0+ka.y*z1;
        m1 += ka.z*z0+ka.w*z1;
        m2  = p2 + kb.x*z0+kb.y*z1;
        m3  = p3 + kb.z*z0+kb.w*z1;
    }
    float ldt=fmaf((float)eacc, 0.6931471805599453f, logf(prodm));

    {
        float s=wred(qd);
        if(lane==0) fw[wid]=s;
        __syncthreads();
        if(c==0){
            double acc=0.0;
            for(int i=0;i<8;++i) acc+=(double)fw[i];
            sred[0]=acc;
        }
        __syncthreads();
        s=wred(ldt);
        if(lane==0) fw[wid]=s;
        __syncthreads();
        if(c==0){
            double acc=0.0;
            for(int i=0;i<8;++i) acc+=(double)fw[i];
            sred[1]=acc;
        }
        __syncthreads();
    }

    if(c==0){
        double ld2=sred[1];
        double s_wq=g_swq, s_qd=sred[0];
        double Td=(double)T, rr_=(double)r;
        double a0d=rr_/(double)bs0, a1d=rr_/(double)bs1, aud=rr_/(double)bsu;
        const double LOG2PI=1.8378770664093453;
        double ld_contrast=15.0*(4.0*Td*log(rr_)+2.0*log((a0d+Td)/a0d)+2.0*log((a1d+Td)/a1d));
        double ld_diff=2.0*(Td*log(rr_)+log((aud+Td)/aud));
        double logp=-0.5*(64.0*Td*LOG2PI)-0.5*(s_qd+2.0*s_wq)-0.5*(ld2+ld_contrast+ld_diff);
        shr[19]=(float)logp;

        float Mm[4][8];
        for(int i=0;i<4;++i)
            for(int j=0;j<4;++j){ Mm[i][j]=g_pTf[i*4+j]; Mm[i][4+j]=(i==j)?1.0f:0.0f; }
        for(int cc=0;cc<4;++cc){
            int piv=cc; float mx=fabsf(Mm[cc][cc]);
            for(int rr=cc+1;rr<4;++rr){
                float aa=fabsf(Mm[rr][cc]);
                if(aa>mx){mx=aa;piv=rr;}
            }
            if(piv!=cc)
                for(int j=0;j<8;++j){ float tm=Mm[cc][j]; Mm[cc][j]=Mm[piv][j]; Mm[piv][j]=tm; }
            float pv=1.0f/Mm[cc][cc];
            for(int j=0;j<8;++j) Mm[cc][j]*=pv;
            for(int rr=0;rr<4;++rr){
                if(rr==cc) continue;
                float f=Mm[rr][cc];
                for(int j=0;j<8;++j) Mm[rr][j]-=f*Mm[cc][j];
            }
        }
        for(int i=0;i<4;++i)
            for(int j=0;j<4;++j) shr[i*4+j]=Mm[i][4+j];
        shr[16]=(float)(1.0/(double)bs0+Td/rr_);
        shr[17]=(float)(1.0/(double)bs1+Td/rr_);
        shr[18]=(float)(1.0/(double)bsu+Td/rr_);
    }
    __syncthreads();

    if(c==0 && out_size>0) out[0]=shr[19];
    const int NP=66*66;
    const float INV32=0.03125f;
    const float INVS32=0.17677669529663687f;
    for(int idx=c; idx<NP; idx+=NTH){
        if(idx+1>=out_size) break;
        int i=idx/66, j=idx-66*i;
        float v;
        if(i<64 && j<64){
            int pi=i>>5, pj=j>>5, ei=i&1, ej=j&1;
            v=shr[pi*4+pj]*INV32;
            if(pi==pj){
                v += ((ei==ej)?shr[18]:-shr[18])*INV32;
                if(ei==ej){
                    v -= shr[16+ei]*0.0625f;
                    if(i==j) v += shr[16+ei];
                }
            }
        } else if(i<64){
            int pi=i>>5;
            v=shr[pi*4+2+(j-64)]*INVS32;
        } else if(j<64){
            int pj=j>>5;
            v=shr[pj*4+2+(i-64)]*INVS32;
        } else {
            v=shr[(2+i-64)*4+(2+j-64)];
        }
        out[1+idx]=v;
    }
}

extern "C" void kernel_launch(void* const* d_in, const int* in_sizes, int n_in,
                              void* d_out, int out_size) {
    const float* track     = (const float*)d_in[0];
    const float* bias_sc   = (const float*)d_in[1];
    const float* obs_noise = (const float*)d_in[2];
    const float* trans_n   = (const float*)d_in[3];
    const float* A         = (const float*)d_in[4];
    const float* init_cov  = (const float*)d_in[5];
    float* out = (float*)d_out;
    int T = in_sizes[0]/2;
    if (T > TT) T = TT;
    int t0 = (T >= T0) ? T0 : T;

    hmm_k1<<<1, 32>>>(track, bias_sc, obs_noise, trans_n, A, init_cov, T, t0);
    int nfill = (T > t0) ? (T - t0 + NTH - 1) / NTH : 0;
    hmm_k2<<<nfill + 1, NTH>>>(track, bias_sc, obs_noise, T, t0, nfill);
    hmm_k3<<<1, NTH>>>(track, bias_sc, obs_noise, trans_n, A, init_cov, out, T, out_size);
}

// round 14
// speedup vs baseline: 68.8193x; 1.1807x over previous
#include <cuda_runtime.h>
#include <math.h>

#define NTH 256
#define CH 16
#define TT 4096
#define T0 16

__device__ float4 g_kv[TT*3];
__device__ float  g_lamW[20];
__device__ float  g_pTf[16];
__device__ double g_swq;

// symmetric-PD 4x4 inverse via 2x2 block Schur, fp32
__device__ __forceinline__ void finv4sym(const float* m, float* o){
    float a00=m[0], a01=m[1], a11=m[5];
    float idA=1.0f/(a00*a11-a01*a01);
    float Ai00=a11*idA, Ai01=-a01*idA, Ai11=a00*idA;
    float b00=m[2], b01=m[3], b10=m[6], b11=m[7];
    float U00=Ai00*b00+Ai01*b10, U01=Ai00*b01+Ai01*b11;
    float U10=Ai01*b00+Ai11*b10, U11=Ai01*b01+Ai11*b11;
    float c00=m[10]-(b00*U00+b10*U10);
    float c01=m[11]-(b00*U01+b10*U11);
    float c11=m[15]-(b01*U01+b11*U11);
    float idC=1.0f/(c00*c11-c01*c01);
    float Si00=c11*idC, Si01=-c01*idC, Si11=c00*idC;
    float TR00=-(U00*Si00+U01*Si01), TR01=-(U00*Si01+U01*Si11);
    float TR10=-(U10*Si00+U11*Si01), TR11=-(U10*Si01+U11*Si11);
    float TL00=Ai00-(TR00*U00+TR01*U01);
    float TL01=Ai01-(TR00*U10+TR01*U11);
    float TL11=Ai11-(TR10*U10+TR11*U11);
    o[0]=TL00; o[1]=TL01; o[2]=TR00; o[3]=TR01;
    o[4]=TL01; o[5]=TL11; o[6]=TR10; o[7]=TR11;
    o[8]=TR00; o[9]=TR10; o[10]=Si00; o[11]=Si01;
    o[12]=TR01; o[13]=TR11; o[14]=Si01; o[15]=Si11;
}

__device__ __forceinline__ float wred(float v){
    #pragma unroll
    for(int off=16; off; off>>=1) v += __shfl_down_sync(0xffffffffu, v, off);
    return v;
}

// ================= K1: burn-in + fp32 bridge =================
__global__ void __launch_bounds__(32,1)
hmm_k1(const float* __restrict__ track, const float* __restrict__ bias_scales,
       const float* __restrict__ obs_noise, const float* __restrict__ trans_noise,
       const float* __restrict__ Ain, const float* __restrict__ init_cov,
       int T, int t0)
{
    if(threadIdx.x != 0) return;

    const float cst = 5.656854249492381f;
    const float bs0=bias_scales[0], bs1=bias_scales[1];
    const float bsu=0.5f*(bs0+bs1);
    const float r=obs_noise[0]*obs_noise[0];
    const float q=trans_noise[0]*trans_noise[0];
    const float A00=Ain[0], A01=Ain[1], A10=Ain[2], A11=Ain[3];

    float puu00=bsu, puu01=0.0f, puu11=bsu;
    float pus00=0.f, pus01=0.f, pus10=0.f, pus11=0.f;
    float pss00=init_cov[0], pss01=init_cov[1], pss11=init_cov[3];
    const float c2=32.0f;
    float4* gp = g_kv;
    for(int t=0;t<t0;++t){
        float b00=pss00*A00+pss01*A10;
        float b01=pss00*A01+pss01*A11;
        float b10=pss01*A00+pss11*A10;
        float b11=pss01*A01+pss11*A11;
        pss00=A00*b00+A10*b10+q;
        pss01=A00*b01+A10*b11;
        pss11=A01*b01+A11*b11+q;
        float t00=pus00*A00+pus01*A10;
        float t01=pus00*A01+pus01*A11;
        float t10=pus10*A00+pus11*A10;
        float t11=pus10*A01+pus11*A11;
        pus00=t00;pus01=t01;pus10=t10;pus11=t11;
        float S00=puu00+2.0f*cst*pus00+c2*pss00+r;
        float S01=puu01+cst*(pus01+pus10)+c2*pss01;
        float S11=puu11+2.0f*cst*pus11+c2*pss11+r;
        float det=S00*S11-S01*S01;
        float id=1.0f/det;
        float G00=puu00+cst*pus00, G01=puu01+cst*pus01;
        float G10=puu01+cst*pus10, G11=puu11+cst*pus11;
        float G20=pus00+cst*pss00, G21=pus10+cst*pss01;
        float G30=pus01+cst*pss01, G31=pus11+cst*pss11;
        float W00=(G00*S11-G01*S01)*id, W01=(G01*S00-G00*S01)*id;
        float W10=(G10*S11-G11*S01)*id, W11=(G11*S00-G10*S01)*id;
        float W20=(G20*S11-G21*S01)*id, W21=(G21*S00-G20*S01)*id;
        float W30=(G30*S11-G31*S01)*id, W31=(G31*S00-G30*S01)*id;
        gp[0]=make_float4(W00,W01,W10,W11);
        gp[1]=make_float4(W20,W21,W30,W31);
        gp[2]=make_float4(S00,S01,S11,id);
        gp+=3;
        puu00-=W00*G00+W01*G01;
        puu01-=W00*G10+W01*G11;
        puu11-=W10*G10+W11*G11;
        pus00-=W00*G20+W01*G21;
        pus01-=W00*G30+W01*G31;
        pus10-=W10*G20+W11*G21;
        pus11-=W10*G30+W11*G31;
        pss00-=W20*G20+W21*G21;
        pss01-=W20*G30+W21*G31;
        pss11-=W30*G30+W31*G31;
    }

    if(t0==T){
        g_pTf[0]=puu00; g_pTf[1]=puu01; g_pTf[2]=pus00; g_pTf[3]=pus01;
        g_pTf[4]=puu01; g_pTf[5]=puu11; g_pTf[6]=pus10; g_pTf[7]=pus11;
        g_pTf[8]=pus00; g_pTf[9]=pus10; g_pTf[10]=pss00; g_pTf[11]=pss01;
        g_pTf[12]=pus01; g_pTf[13]=pus11; g_pTf[14]=pss01; g_pTf[15]=pss11;
    } else {
        // ---- one-time fp32 bridge: Lambda_pred(t0), Lambda_pred(t0+1), Wbb ----
        float uu00=puu00, uu01=puu01, uu11=puu11;
        float us00=pus00, us01=pus01, us10=pus10, us11=pus11;
        float ss00=pss00, ss01=pss01, ss11=pss11;
        float L0[16], L1[16], M[16];
        for(int rep=0;rep<2;++rep){
            float b00=ss00*A00+ss01*A10, b01=ss00*A01+ss01*A11;
            float b10=ss01*A00+ss11*A10, b11=ss01*A01+ss11*A11;
            ss00=A00*b00+A10*b10+q;
            ss01=A00*b01+A10*b11;
            ss11=A01*b01+A11*b11+q;
            float t00=us00*A00+us01*A10, t01=us00*A01+us01*A11;
            float t10=us10*A00+us11*A10, t11=us10*A01+us11*A11;
            us00=t00;us01=t01;us10=t10;us11=t11;
            M[0]=uu00; M[1]=uu01; M[2]=us00; M[3]=us01;
            M[4]=uu01; M[5]=uu11; M[6]=us10; M[7]=us11;
            M[8]=us00; M[9]=us10; M[10]=ss00; M[11]=ss01;
            M[12]=us01; M[13]=us11; M[14]=ss01; M[15]=ss11;
            finv4sym(M, (rep==0)?L0:L1);
            if(rep==1) break;
            float S00=uu00+2.0f*cst*us00+c2*ss00+r;
            float S01=uu01+cst*(us01+us10)+c2*ss01;
            float S11=uu11+2.0f*cst*us11+c2*ss11+r;
            float id=1.0f/(S00*S11-S01*S01);
            float G00=uu00+cst*us00, G01=uu01+cst*us01;
            float G10=uu01+cst*us10, G11=uu11+cst*us11;
            float G20=us00+cst*ss00, G21=us10+cst*ss01;
            float G30=us01+cst*ss01, G31=us11+cst*ss11;
            float W00=(G00*S11-G01*S01)*id, W01=(G01*S00-G00*S01)*id;
            float W10=(G10*S11-G11*S01)*id, W11=(G11*S00-G10*S01)*id;
            float W20=(G20*S11-G21*S01)*id, W21=(G21*S00-G20*S01)*id;
            float W30=(G30*S11-G31*S01)*id, W31=(G31*S00-G30*S01)*id;
            uu00-=W00*G00+W01*G01;
            uu01-=W00*G10+W01*G11;
            uu11-=W10*G10+W11*G11;
            us00-=W00*G20+W01*G21;
            us01-=W00*G30+W01*G31;
            us10-=W10*G20+W11*G21;
            us11-=W10*G30+W11*G31;
            ss00-=W20*G20+W21*G21;
            ss01-=W20*G30+W21*G31;
            ss11-=W30*G30+W31*G31;
        }
        for(int i=0;i<16;++i) g_lamW[i]=L0[i];
        g_lamW[16]=L1[0]-L0[0];
        g_lamW[17]=L1[1]-L0[1];
        g_lamW[18]=L1[5]-L0[5];
    }
}

// ================= K2: gain fill (blocks 0..nfill-1) + diff-scan (last block) =================
__global__ void __launch_bounds__(NTH,1)
hmm_k2(const float* __restrict__ track, const float* __restrict__ bias_scales,
       const float* __restrict__ obs_noise, int T, int t0, int nfill)
{
    const float cst = 5.656854249492381f;
    const float r = obs_noise[0]*obs_noise[0];

    if((int)blockIdx.x == nfill){
        __shared__ float wtot[8];
        __shared__ float fw[8];
        const int c = threadIdx.x;
        const int lane = c&31, wid = c>>5;
        const float SQ8 = 2.8284271247461903f;
        const float bs0=bias_scales[0], bs1=bias_scales[1];
        const float bsu=0.5f*(bs0+bs1);
        float del[CH];
        #pragma unroll
        for(int k=0;k<CH;++k){
            int t=c*CH+k;
            float x0 = (t<T)?track[2*t]:0.0f;
            float x1 = (t<T)?track[2*t+1]:0.0f;
            del[k]=SQ8*(x0-x1);
        }
        const float adf=r/bsu;
        float s=0.0f;
        #pragma unroll
        for(int k=0;k<CH;++k) s+=del[k];
        float v=s;
        #pragma unroll
        for(int off=1;off<32;off<<=1){
            float n=__shfl_up_sync(0xffffffffu,v,off);
            if(lane>=off) v+=n;
        }
        if(lane==31) wtot[wid]=v;
        __syncthreads();
        if(wid==0 && lane<8){
            float orig=wtot[lane], w=orig;
            #pragma unroll
            for(int off=1;off<8;off<<=1){
                float n=__shfl_up_sync(0xffu,w,off);
                if(lane>=off) w+=n;
            }
            wtot[lane]=w-orig;
        }
        __syncthreads();
        float run=(v-s)+wtot[wid];
        float wq=0.0f;
        #pragma unroll
        for(int k=0;k<CH;++k){
            int t=c*CH+k;
            if(t<T){
                float at=adf+(float)t;
                float zd=del[k]-run/at;
                wq += zd*zd*at/(r*(at+1.0f));
            }
            run+=del[k];
        }
        float ws=wred(wq);
        if(lane==0) fw[wid]=ws;
        __syncthreads();
        if(c==0){
            double acc=0.0;
            for(int i=0;i<8;++i) acc+=(double)fw[i];
            g_swq=acc;
        }
        return;
    }

    int g = blockIdx.x*NTH + threadIdx.x;
    int t = t0 + g;
    if(t >= T) return;
    const float c2 = 32.0f;

    float l02=g_lamW[2],  l03=g_lamW[3];
    float l12=g_lamW[6],  l13=g_lamW[7];
    float l22=g_lamW[10], l23=g_lamW[11], l33=g_lamW[15];
    float L00=g_lamW[0], L01=g_lamW[1], L11=g_lamW[5];
    float W0=g_lamW[16], W1=g_lamW[17], W2=g_lamW[18];

    float kt=(float)g;
    float l00=fmaf(kt,W0,L00);
    float l01=fmaf(kt,W1,L01);
    float l11=fmaf(kt,W2,L11);
    float iX=1.0f/(l00*l11-l01*l01);
    float X00=l11*iX, X01=-l01*iX, X11=l00*iX;
    float B100=X00*l02+X01*l12, B101=X00*l03+X01*l13;
    float B110=X01*l02+X11*l12, B111=X01*l03+X11*l13;
    float Sp00=l22-(l02*B100+l12*B110);
    float Sp01=l23-(l02*B101+l12*B111);
    float Sp11=l33-(l03*B101+l13*B111);
    float iS=1.0f/(Sp00*Sp11-Sp01*Sp01);
    float Z00=Sp11*iS, Z01=-Sp01*iS, Z11=Sp00*iS;
    float pus00=-(B100*Z00+B101*Z01);
    float pus01=-(B100*Z01+B101*Z11);
    float pus10=-(B110*Z00+B111*Z01);
    float pus11=-(B110*Z01+B111*Z11);
    float puu00=X00-(pus00*B100+pus01*B101);
    float puu01=X01-(pus00*B110+pus01*B111);
    float puu11=X11-(pus10*B110+pus11*B111);
    float pss00=Z00, pss01=Z01, pss11=Z11;
    float S00=puu00+2.0f*cst*pus00+c2*pss00+r;
    float S01=puu01+cst*(pus01+pus10)+c2*pss01;
    float S11=puu11+2.0f*cst*pus11+c2*pss11+r;
    float det=S00*S11-S01*S01;
    float id=1.0f/det;
    float G00=puu00+cst*pus00, G01=puu01+cst*pus01;
    float G10=puu01+cst*pus10, G11=puu11+cst*pus11;
    float G20=pus00+cst*pss00, G21=pus10+cst*pss01;
    float G30=pus01+cst*pss01, G31=pus11+cst*pss11;
    float W00=(G00*S11-G01*S01)*id, W01=(G01*S00-G00*S01)*id;
    float W10=(G10*S11-G11*S01)*id, W11=(G11*S00-G10*S01)*id;
    float W20=(G20*S11-G21*S01)*id, W21=(G21*S00-G20*S01)*id;
    float W30=(G30*S11-G31*S01)*id, W31=(G31*S00-G30*S01)*id;
    g_kv[t*3+0]=make_float4(W00,W01,W10,W11);
    g_kv[t*3+1]=make_float4(W20,W21,W30,W31);
    g_kv[t*3+2]=make_float4(S00,S01,S11,id);
    if(t==T-1){
        float f0=puu00-(W00*G00+W01*G01);
        float f1=puu01-(W00*G10+W01*G11);
        float f5=puu11-(W10*G10+W11*G11);
        float f2=pus00-(W00*G20+W01*G21);
        float f3=pus01-(W00*G30+W01*G31);
        float f6=pus10-(W10*G20+W11*G21);
        float f7=pus11-(W10*G30+W11*G31);
        float f10=pss00-(W20*G20+W21*G21);
        float f11=pss01-(W20*G30+W21*G31);
        float f15=pss11-(W30*G30+W31*G31);
        g_pTf[0]=f0;  g_pTf[1]=f1;  g_pTf[2]=f2;  g_pTf[3]=f3;
        g_pTf[4]=f1;  g_pTf[5]=f5;  g_pTf[6]=f6;  g_pTf[7]=f7;
        g_pTf[8]=f2;  g_pTf[9]=f6;  g_pTf[10]=f10; g_pTf[11]=f11;
        g_pTf[12]=f3; g_pTf[13]=f7; g_pTf[14]=f11; g_pTf[15]=f15;
    }
}

// ================= K3: mean scan + replay + epilogue + output (proven) =================
__global__ void __launch_bounds__(NTH,1)
hmm_k3(const float* __restrict__ track, const float* __restrict__ bias_scales,
       const float* __restrict__ obs_noise, const float* __restrict__ trans_noise,
       const float* __restrict__ Ain, const float* __restrict__ init_cov,
       float* __restrict__ out, int T, int out_size)
{
    __shared__ float elems[NTH*20];
    __shared__ float fw[8];
    __shared__ double sred[2];
    __shared__ float shr[24];

    const int c = threadIdx.x;
    const int lane = c&31, wid = c>>5;
    const float SQ8 = 2.8284271247461903f;
    const float cst = 5.656854249492381f;

    const float bs0=bias_scales[0], bs1=bias_scales[1];
    const float bsu=0.5f*(bs0+bs1);
    const float r=obs_noise[0]*obs_noise[0];
    const float A00=Ain[0], A01=Ain[1], A10=Ain[2], A11=Ain[3];

    float sig[CH];
    #pragma unroll
    for(int k=0;k<CH;++k){
        int t=c*CH+k;
        float x0 = (t<T)?track[2*t]:0.0f;
        float x1 = (t<T)?track[2*t+1]:0.0f;
        sig[k]=SQ8*(x0+x1);
    }

    float Eo[16]={1,0,0,0, 0,1,0,0, 0,0,1,0, 0,0,0,1};
    float bo[4]={0,0,0,0};
    #pragma unroll
    for(int k=0;k<CH;++k){
        int t=c*CH+k;
        float4 ka = g_kv[t*3+0];
        float4 kb = g_kv[t*3+1];
        float N0[4]={1.0f-ka.x, -ka.y, -cst*ka.x, -cst*ka.y};
        float N1[4]={-ka.z, 1.0f-ka.w, -cst*ka.z, -cst*ka.w};
        float N2[4]={-kb.x, -kb.y, 1.0f-cst*kb.x, -cst*kb.y};
        float N3[4]={-kb.z, -kb.w, -cst*kb.z, 1.0f-cst*kb.w};
        float Ek[16];
        Ek[0]=N0[0]; Ek[1]=N0[1]; Ek[2]=N0[2]*A00+N0[3]*A01; Ek[3]=N0[2]*A10+N0[3]*A11;
        Ek[4]=N1[0]; Ek[5]=N1[1]; Ek[6]=N1[2]*A00+N1[3]*A01; Ek[7]=N1[2]*A10+N1[3]*A11;
        Ek[8]=N2[0]; Ek[9]=N2[1]; Ek[10]=N2[2]*A00+N2[3]*A01; Ek[11]=N2[2]*A10+N2[3]*A11;
        Ek[12]=N3[0]; Ek[13]=N3[1]; Ek[14]=N3[2]*A00+N3[3]*A01; Ek[15]=N3[2]*A10+N3[3]*A11;
        float y=sig[k];
        float bs_[4]={(ka.x+ka.y)*y,(ka.z+ka.w)*y,(kb.x+kb.y)*y,(kb.z+kb.w)*y};
        float En[16], bn[4];
        #pragma unroll
        for(int i=0;i<4;++i){
            #pragma unroll
            for(int j=0;j<4;++j)
                En[i*4+j]=Ek[i*4]*Eo[j]+Ek[i*4+1]*Eo[4+j]+Ek[i*4+2]*Eo[8+j]+Ek[i*4+3]*Eo[12+j];
            bn[i]=Ek[i*4]*bo[0]+Ek[i*4+1]*bo[1]+Ek[i*4+2]*bo[2]+Ek[i*4+3]*bo[3]+bs_[i];
        }
        #pragma unroll
        for(int i=0;i<16;++i) Eo[i]=En[i];
        #pragma unroll
        for(int i=0;i<4;++i) bo[i]=bn[i];
    }
    #pragma unroll
    for(int i=0;i<16;++i) elems[c*20+i]=Eo[i];
    #pragma unroll
    for(int i=0;i<4;++i) elems[c*20+16+i]=bo[i];
    __syncthreads();

    for(int off=1; off<NTH; off<<=1){
        float El[16], bl[4];
        bool act = (c>=off);
        if(act){
            const float* lp=elems+(c-off)*20;
            #pragma unroll
            for(int i=0;i<16;++i) El[i]=lp[i];
            #pragma unroll
            for(int i=0;i<4;++i) bl[i]=lp[16+i];
        }
        __syncthreads();
        if(act){
            float En[16], bn[4];
            #pragma unroll
            for(int i=0;i<4;++i){
                #pragma unroll
                for(int j=0;j<4;++j)
                    En[i*4+j]=Eo[i*4]*El[j]+Eo[i*4+1]*El[4+j]+Eo[i*4+2]*El[8+j]+Eo[i*4+3]*El[12+j];
                bn[i]=Eo[i*4]*bl[0]+Eo[i*4+1]*bl[1]+Eo[i*4+2]*bl[2]+Eo[i*4+3]*bl[3]+bo[i];
            }
            #pragma unroll
            for(int i=0;i<16;++i){ Eo[i]=En[i]; elems[c*20+i]=En[i]; }
            #pragma unroll
            for(int i=0;i<4;++i){ bo[i]=bn[i]; elems[c*20+16+i]=bn[i]; }
        }
        __syncthreads();
    }

    float m0=0.f,m1=0.f,m2=0.f,m3=0.f;
    if(c>0){
        const float* pp=elems+(c-1)*20+16;
        m0=pp[0]; m1=pp[1]; m2=pp[2]; m3=pp[3];
    }
    float qd=0.0f;
    float prodm=1.0f;
    int eacc=0;
    #pragma unroll
    for(int k=0;k<CH;++k){
        int t=c*CH+k;
        float4 ka = g_kv[t*3+0];
        float4 kb = g_kv[t*3+1];
        float4 sc = g_kv[t*3+2];
        float p2=A00*m2+A10*m3;
        float p3=A01*m2+A11*m3;
        float y=sig[k];
        float z0=y-m0-cst*p2;
        float z1=y-m1-cst*p3;
        float id=sc.w;
        float u0=(sc.z*z0-sc.y*z1)*id;
        float u1=(sc.x*z1-sc.y*z0)*id;
        qd += z0*u0+z1*u1;
        float det=sc.x*sc.z-sc.y*sc.y;
        int bi=__float_as_int(det);
        eacc += ((bi>>23)&255)-127;
        prodm *= __int_as_float((bi&0x807FFFFF)|0x3F800000);
        int pb=__float_as_int(prodm);
        eacc += ((pb>>23)&255)-127;
        prodm = __int_as_float((pb&0x807FFFFF)|0x3F800000);
        m0 += ka.x*z0+ka.y*z1;
        m1 += ka.z*z0+ka.w*z1;
        m2  = p2 + kb.x*z0+kb.y*z1;
        m3  = p3 + kb.z*z0+kb.w*z1;
    }
    float ldt=fmaf((float)eacc, 0.6931471805599453f, logf(prodm));

    {
        float s=wred(qd);
        if(lane==0) fw[wid]=s;
        __syncthreads();
        if(c==0){
            double acc=0.0;
            for(int i=0;i<8;++i) acc+=(double)fw[i];
            sred[0]=acc;
        }
        __syncthreads();
        s=wred(ldt);
        if(lane==0) fw[wid]=s;
        __syncthreads();
        if(c==0){
            double acc=0.0;
            for(int i=0;i<8;++i) acc+=(double)fw[i];
            sred[1]=acc;
        }
        __syncthreads();
    }

    if(c==0){
        double ld2=sred[1];
        double s_wq=g_swq, s_qd=sred[0];
        double Td=(double)T, rr_=(double)r;
        double a0d=rr_/(double)bs0, a1d=rr_/(double)bs1, aud=rr_/(double)bsu;
        const double LOG2PI=1.8378770664093453;
        double ld_contrast=15.0*(4.0*Td*log(rr_)+2.0*log((a0d+Td)/a0d)+2.0*log((a1d+Td)/a1d));
        double ld_diff=2.0*(Td*log(rr_)+log((aud+Td)/aud));
        double logp=-0.5*(64.0*Td*LOG2PI)-0.5*(s_qd+2.0*s_wq)-0.5*(ld2+ld_contrast+ld_diff);
        shr[19]=(float)logp;

        float Mm[4][8];
        for(int i=0;i<4;++i)
            for(int j=0;j<4;++j){ Mm[i][j]=g_pTf[i*4+j]; Mm[i][4+j]=(i==j)?1.0f:0.0f; }
        for(int cc=0;cc<4;++cc){
            int piv=cc; float mx=fabsf(Mm[cc][cc]);
            for(int rr=cc+1;rr<4;++rr){
                float aa=fabsf(Mm[rr][cc]);
                if(aa>mx){mx=aa;piv=rr;}
            }
            if(piv!=cc)
                for(int j=0;j<8;++j){ float tm=Mm[cc][j]; Mm[cc][j]=Mm[piv][j]; Mm[piv][j]=tm; }
            float pv=1.0f/Mm[cc][cc];
            for(int j=0;j<8;++j) Mm[cc][j]*=pv;
            for(int rr=0;rr<4;++rr){
                if(rr==cc) continue;
                float f=Mm[rr][cc];
                for(int j=0;j<8;++j) Mm[rr][j]-=f*Mm[cc][j];
            }
        }
        for(int i=0;i<4;++i)
            for(int j=0;j<4;++j) shr[i*4+j]=Mm[i][4+j];
        shr[16]=(float)(1.0/(double)bs0+Td/rr_);
        shr[17]=(float)(1.0/(double)bs1+Td/rr_);
        shr[18]=(float)(1.0/(double)bsu+Td/rr_);
    }
    __syncthreads();

    if(c==0 && out_size>0) out[0]=shr[19];
    const int NP=66*66;
    const float INV32=0.03125f;
    const float INVS32=0.17677669529663687f;
    for(int idx=c; idx<NP; idx+=NTH){
        if(idx+1>=out_size) break;
        int i=idx/66, j=idx-66*i;
        float v;
        if(i<64 && j<64){
            int pi=i>>5, pj=j>>5, ei=i&1, ej=j&1;
            v=shr[pi*4+pj]*INV32;
            if(pi==pj){
                v += ((ei==ej)?shr[18]:-shr[18])*INV32;
                if(ei==ej){
                    v -= shr[16+ei]*0.0625f;
                    if(i==j) v += shr[16+ei];
                }
            }
        } else if(i<64){
            int pi=i>>5;
            v=shr[pi*4+2+(j-64)]*INVS32;
        } else if(j<64){
            int pj=j>>5;
            v=shr[pj*4+2+(i-64)]*INVS32;
        } else {
            v=shr[(2+i-64)*4+(2+j-64)];
        }
        out[1+idx]=v;
    }
}

extern "C" void kernel_launch(void* const* d_in, const int* in_sizes, int n_in,
                              void* d_out, int out_size) {
    const float* track     = (const float*)d_in[0];
    const float* bias_sc   = (const float*)d_in[1];
    const float* obs_noise = (const float*)d_in[2];
    const float* trans_n   = (const float*)d_in[3];
    const float* A         = (const float*)d_in[4];
    const float* init_cov  = (const float*)d_in[5];
    float* out = (float*)d_out;
    int T = in_sizes[0]/2;
    if (T > TT) T = TT;
    int t0 = (T >= T0) ? T0 : T;

    hmm_k1<<<1, 32>>>(track, bias_sc, obs_noise, trans_n, A, init_cov, T, t0);
    int nfill = (T > t0) ? (T - t0 + NTH - 1) / NTH : 0;
    hmm_k2<<<nfill + 1, NTH>>>(track, bias_sc, obs_noise, T, t0, nfill);
    hmm_k3<<<1, NTH>>>(track, bias_sc, obs_noise, trans_n, A, init_cov, out, T, out_size);
}

// round 15
// speedup vs baseline: 79.2532x; 1.1516x over previous
#include <cuda_runtime.h>
#include <math.h>

#define NTH 256
#define CH 16
#define TT 4096
#define T0 16
#define NCH (TT/CH)

__device__ float4 g_kv[TT*3];
__device__ float  g_elems[NCH*20];
__device__ float  g_pTf[16];
__device__ double g_swq;

// symmetric-PD 4x4 inverse via 2x2 block Schur, fp32 (proven)
__device__ __forceinline__ void finv4sym(const float* m, float* o){
    float a00=m[0], a01=m[1], a11=m[5];
    float idA=1.0f/(a00*a11-a01*a01);
    float Ai00=a11*idA, Ai01=-a01*idA, Ai11=a00*idA;
    float b00=m[2], b01=m[3], b10=m[6], b11=m[7];
    float U00=Ai00*b00+Ai01*b10, U01=Ai00*b01+Ai01*b11;
    float U10=Ai01*b00+Ai11*b10, U11=Ai01*b01+Ai11*b11;
    float c00=m[10]-(b00*U00+b10*U10);
    float c01=m[11]-(b00*U01+b10*U11);
    float c11=m[15]-(b01*U01+b11*U11);
    float idC=1.0f/(c00*c11-c01*c01);
    float Si00=c11*idC, Si01=-c01*idC, Si11=c00*idC;
    float TR00=-(U00*Si00+U01*Si01), TR01=-(U00*Si01+U01*Si11);
    float TR10=-(U10*Si00+U11*Si01), TR11=-(U10*Si01+U11*Si11);
    float TL00=Ai00-(TR00*U00+TR01*U01);
    float TL01=Ai01-(TR00*U10+TR01*U11);
    float TL11=Ai11-(TR10*U10+TR11*U11);
    o[0]=TL00; o[1]=TL01; o[2]=TR00; o[3]=TR01;
    o[4]=TL01; o[5]=TL11; o[6]=TR10; o[7]=TR11;
    o[8]=TR00; o[9]=TR10; o[10]=Si00; o[11]=Si01;
    o[12]=TR01; o[13]=TR11; o[14]=Si01; o[15]=Si11;
}

__device__ __forceinline__ float wred(float v){
    #pragma unroll
    for(int off=16; off; off>>=1) v += __shfl_down_sync(0xffffffffu, v, off);
    return v;
}

// ================= KA: burn-in(redundant) + gain fill + chunk composition; last block diff-scan =================
__global__ void __launch_bounds__(NTH,1)
hmm_kA(const float* __restrict__ track, const float* __restrict__ bias_scales,
       const float* __restrict__ obs_noise, const float* __restrict__ trans_noise,
       const float* __restrict__ Ain, const float* __restrict__ init_cov,
       int T, int t0, int nfill)
{
    const float cst = 5.656854249492381f;
    const float SQ8 = 2.8284271247461903f;
    const float r = obs_noise[0]*obs_noise[0];
    const float bs0=bias_scales[0], bs1=bias_scales[1];
    const float bsu=0.5f*(bs0+bs1);

    if((int)blockIdx.x == nfill){
        // ---- diff-channel prefix scan (proven verbatim) ----
        __shared__ float wtot[8];
        __shared__ float fw[8];
        const int c = threadIdx.x;
        const int lane = c&31, wid = c>>5;
        float del[CH];
        #pragma unroll
        for(int k=0;k<CH;++k){
            int t=c*CH+k;
            float x0 = (t<T)?track[2*t]:0.0f;
            float x1 = (t<T)?track[2*t+1]:0.0f;
            del[k]=SQ8*(x0-x1);
        }
        const float adf=r/bsu;
        float s=0.0f;
        #pragma unroll
        for(int k=0;k<CH;++k) s+=del[k];
        float v=s;
        #pragma unroll
        for(int off=1;off<32;off<<=1){
            float n=__shfl_up_sync(0xffffffffu,v,off);
            if(lane>=off) v+=n;
        }
        if(lane==31) wtot[wid]=v;
        __syncthreads();
        if(wid==0 && lane<8){
            float orig=wtot[lane], w=orig;
            #pragma unroll
            for(int off=1;off<8;off<<=1){
                float n=__shfl_up_sync(0xffu,w,off);
                if(lane>=off) w+=n;
            }
            wtot[lane]=w-orig;
        }
        __syncthreads();
        float run=(v-s)+wtot[wid];
        float wq=0.0f;
        #pragma unroll
        for(int k=0;k<CH;++k){
            int t=c*CH+k;
            if(t<T){
                float at=adf+(float)t;
                float zd=del[k]-run/at;
                wq += zd*zd*at/(r*(at+1.0f));
            }
            run+=del[k];
        }
        float ws=wred(wq);
        if(lane==0) fw[wid]=ws;
        __syncthreads();
        if(c==0){
            double acc=0.0;
            for(int i=0;i<8;++i) acc+=(double)fw[i];
            g_swq=acc;
        }
        return;
    }

    __shared__ float lamW[19];
    const float q=trans_noise[0]*trans_noise[0];
    const float A00=Ain[0], A01=Ain[1], A10=Ain[2], A11=Ain[3];
    const float c2=32.0f;

    // ---- thread 0: redundant burn-in + fp32 bridge (proven math) ----
    if(threadIdx.x==0){
        float puu00=bsu, puu01=0.0f, puu11=bsu;
        float pus00=0.f, pus01=0.f, pus10=0.f, pus11=0.f;
        float pss00=init_cov[0], pss01=init_cov[1], pss11=init_cov[3];
        bool store = (blockIdx.x==0);
        float4* gp = g_kv;
        for(int t=0;t<t0;++t){
            float b00=pss00*A00+pss01*A10;
            float b01=pss00*A01+pss01*A11;
            float b10=pss01*A00+pss11*A10;
            float b11=pss01*A01+pss11*A11;
            pss00=A00*b00+A10*b10+q;
            pss01=A00*b01+A10*b11;
            pss11=A01*b01+A11*b11+q;
            float t00=pus00*A00+pus01*A10;
            float t01=pus00*A01+pus01*A11;
            float t10=pus10*A00+pus11*A10;
            float t11=pus10*A01+pus11*A11;
            pus00=t00;pus01=t01;pus10=t10;pus11=t11;
            float S00=puu00+2.0f*cst*pus00+c2*pss00+r;
            float S01=puu01+cst*(pus01+pus10)+c2*pss01;
            float S11=puu11+2.0f*cst*pus11+c2*pss11+r;
            float det=S00*S11-S01*S01;
            float id=1.0f/det;
            float G00=puu00+cst*pus00, G01=puu01+cst*pus01;
            float G10=puu01+cst*pus10, G11=puu11+cst*pus11;
            float G20=pus00+cst*pss00, G21=pus10+cst*pss01;
            float G30=pus01+cst*pss01, G31=pus11+cst*pss11;
            float W00=(G00*S11-G01*S01)*id, W01=(G01*S00-G00*S01)*id;
            float W10=(G10*S11-G11*S01)*id, W11=(G11*S00-G10*S01)*id;
            float W20=(G20*S11-G21*S01)*id, W21=(G21*S00-G20*S01)*id;
            float W30=(G30*S11-G31*S01)*id, W31=(G31*S00-G30*S01)*id;
            if(store){
                gp[0]=make_float4(W00,W01,W10,W11);
                gp[1]=make_float4(W20,W21,W30,W31);
                gp[2]=make_float4(S00,S01,S11,id);
                gp+=3;
            }
            puu00-=W00*G00+W01*G01;
            puu01-=W00*G10+W01*G11;
            puu11-=W10*G10+W11*G11;
            pus00-=W00*G20+W01*G21;
            pus01-=W00*G30+W01*G31;
            pus10-=W10*G20+W11*G21;
            pus11-=W10*G30+W11*G31;
            pss00-=W20*G20+W21*G21;
            pss01-=W20*G30+W21*G31;
            pss11-=W30*G30+W31*G31;
        }
        if(t0==T && store){
            g_pTf[0]=puu00; g_pTf[1]=puu01; g_pTf[2]=pus00; g_pTf[3]=pus01;
            g_pTf[4]=puu01; g_pTf[5]=puu11; g_pTf[6]=pus10; g_pTf[7]=pus11;
            g_pTf[8]=pus00; g_pTf[9]=pus10; g_pTf[10]=pss00; g_pTf[11]=pss01;
            g_pTf[12]=pus01; g_pTf[13]=pus11; g_pTf[14]=pss01; g_pTf[15]=pss11;
        }
        if(t0<T){
            // fp32 bridge (proven verbatim)
            float uu00=puu00, uu01=puu01, uu11=puu11;
            float us00=pus00, us01=pus01, us10=pus10, us11=pus11;
            float ss00=pss00, ss01=pss01, ss11=pss11;
            float L0[16], L1[16], M[16];
            for(int rep=0;rep<2;++rep){
                float b00=ss00*A00+ss01*A10, b01=ss00*A01+ss01*A11;
                float b10=ss01*A00+ss11*A10, b11=ss01*A01+ss11*A11;
                ss00=A00*b00+A10*b10+q;
                ss01=A00*b01+A10*b11;
                ss11=A01*b01+A11*b11+q;
                float t00=us00*A00+us01*A10, t01=us00*A01+us01*A11;
                float t10=us10*A00+us11*A10, t11=us10*A01+us11*A11;
                us00=t00;us01=t01;us10=t10;us11=t11;
                M[0]=uu00; M[1]=uu01; M[2]=us00; M[3]=us01;
                M[4]=uu01; M[5]=uu11; M[6]=us10; M[7]=us11;
                M[8]=us00; M[9]=us10; M[10]=ss00; M[11]=ss01;
                M[12]=us01; M[13]=us11; M[14]=ss01; M[15]=ss11;
                finv4sym(M, (rep==0)?L0:L1);
                if(rep==1) break;
                float S00=uu00+2.0f*cst*us00+c2*ss00+r;
                float S01=uu01+cst*(us01+us10)+c2*ss01;
                float S11=uu11+2.0f*cst*us11+c2*ss11+r;
                float id=1.0f/(S00*S11-S01*S01);
                float G00=uu00+cst*us00, G01=uu01+cst*us01;
                float G10=uu01+cst*us10, G11=uu11+cst*us11;
                float G20=us00+cst*ss00, G21=us10+cst*ss01;
                float G30=us01+cst*ss01, G31=us11+cst*ss11;
                float W00=(G00*S11-G01*S01)*id, W01=(G01*S00-G00*S01)*id;
                float W10=(G10*S11-G11*S01)*id, W11=(G11*S00-G10*S01)*id;
                float W20=(G20*S11-G21*S01)*id, W21=(G21*S00-G20*S01)*id;
                float W30=(G30*S11-G31*S01)*id, W31=(G31*S00-G30*S01)*id;
                uu00-=W00*G00+W01*G01;
                uu01-=W00*G10+W01*G11;
                uu11-=W10*G10+W11*G11;
                us00-=W00*G20+W01*G21;
                us01-=W00*G30+W01*G31;
                us10-=W10*G20+W11*G21;
                us11-=W10*G30+W11*G31;
                ss00-=W20*G20+W21*G21;
                ss01-=W20*G30+W21*G31;
                ss11-=W30*G30+W31*G31;
            }
            for(int i=0;i<16;++i) lamW[i]=L0[i];
            lamW[16]=L1[0]-L0[0];
            lamW[17]=L1[1]-L0[1];
            lamW[18]=L1[5]-L0[5];
        }
    }
    __syncthreads();

    // ---- gain fill: t = 256*b + tid (proven math) ----
    {
        int t = (int)blockIdx.x*NTH + threadIdx.x;
        if(t >= t0 && t < T){
            float l02=lamW[2],  l03=lamW[3];
            float l12=lamW[6],  l13=lamW[7];
            float l22=lamW[10], l23=lamW[11], l33=lamW[15];
            float L00=lamW[0], L01=lamW[1], L11=lamW[5];
            float W0=lamW[16], W1=lamW[17], W2=lamW[18];
            float kt=(float)(t-t0);
            float l00=fmaf(kt,W0,L00);
            float l01=fmaf(kt,W1,L01);
            float l11=fmaf(kt,W2,L11);
            float iX=1.0f/(l00*l11-l01*l01);
            float X00=l11*iX, X01=-l01*iX, X11=l00*iX;
            float B100=X00*l02+X01*l12, B101=X00*l03+X01*l13;
            float B110=X01*l02+X11*l12, B111=X01*l03+X11*l13;
            float Sp00=l22-(l02*B100+l12*B110);
            float Sp01=l23-(l02*B101+l12*B111);
            float Sp11=l33-(l03*B101+l13*B111);
            float iS=1.0f/(Sp00*Sp11-Sp01*Sp01);
            float Z00=Sp11*iS, Z01=-Sp01*iS, Z11=Sp00*iS;
            float pus00=-(B100*Z00+B101*Z01);
            float pus01=-(B100*Z01+B101*Z11);
            float pus10=-(B110*Z00+B111*Z01);
            float pus11=-(B110*Z01+B111*Z11);
            float puu00=X00-(pus00*B100+pus01*B101);
            float puu01=X01-(pus00*B110+pus01*B111);
            float puu11=X11-(pus10*B110+pus11*B111);
            float pss00=Z00, pss01=Z01, pss11=Z11;
            float S00=puu00+2.0f*cst*pus00+c2*pss00+r;
            float S01=puu01+cst*(pus01+pus10)+c2*pss01;
            float S11=puu11+2.0f*cst*pus11+c2*pss11+r;
            float det=S00*S11-S01*S01;
            float id=1.0f/det;
            float G00=puu00+cst*pus00, G01=puu01+cst*pus01;
            float G10=puu01+cst*pus10, G11=puu11+cst*pus11;
            float G20=pus00+cst*pss00, G21=pus10+cst*pss01;
            float G30=pus01+cst*pss01, G31=pus11+cst*pss11;
            float W00=(G00*S11-G01*S01)*id, W01=(G01*S00-G00*S01)*id;
            float W10=(G10*S11-G11*S01)*id, W11=(G11*S00-G10*S01)*id;
            float W20=(G20*S11-G21*S01)*id, W21=(G21*S00-G20*S01)*id;
            float W30=(G30*S11-G31*S01)*id, W31=(G31*S00-G30*S01)*id;
            g_kv[t*3+0]=make_float4(W00,W01,W10,W11);
            g_kv[t*3+1]=make_float4(W20,W21,W30,W31);
            g_kv[t*3+2]=make_float4(S00,S01,S11,id);
            if(t==T-1){
                float f0=puu00-(W00*G00+W01*G01);
                float f1=puu01-(W00*G10+W01*G11);
                float f5=puu11-(W10*G10+W11*G11);
                float f2=pus00-(W00*G20+W01*G21);
                float f3=pus01-(W00*G30+W01*G31);
                float f6=pus10-(W10*G20+W11*G21);
                float f7=pus11-(W10*G30+W11*G31);
                float f10=pss00-(W20*G20+W21*G21);
                float f11=pss01-(W20*G30+W21*G31);
                float f15=pss11-(W30*G30+W31*G31);
                g_pTf[0]=f0;  g_pTf[1]=f1;  g_pTf[2]=f2;  g_pTf[3]=f3;
                g_pTf[4]=f1;  g_pTf[5]=f5;  g_pTf[6]=f6;  g_pTf[7]=f7;
                g_pTf[8]=f2;  g_pTf[9]=f6;  g_pTf[10]=f10; g_pTf[11]=f11;
                g_pTf[12]=f3; g_pTf[13]=f7; g_pTf[14]=f11; g_pTf[15]=f15;
            }
        }
    }
    __syncthreads();

    // ---- chunk composition: 16 chunks per block, one per thread (proven pass-1 math) ----
    if(threadIdx.x < 16){
        int cidx = (int)blockIdx.x*16 + threadIdx.x;
        if(cidx*CH < T){
            const float SQ8l = SQ8;
            float Eo[16]={1,0,0,0, 0,1,0,0, 0,0,1,0, 0,0,0,1};
            float bo[4]={0,0,0,0};
            #pragma unroll
            for(int k=0;k<CH;++k){
                int t=cidx*CH+k;
                if(t>=T) break;
                float4 ka = g_kv[t*3+0];
                float4 kb = g_kv[t*3+1];
                float N0[4]={1.0f-ka.x, -ka.y, -cst*ka.x, -cst*ka.y};
                float N1[4]={-ka.z, 1.0f-ka.w, -cst*ka.z, -cst*ka.w};
                float N2[4]={-kb.x, -kb.y, 1.0f-cst*kb.x, -cst*kb.y};
                float N3[4]={-kb.z, -kb.w, -cst*kb.z, 1.0f-cst*kb.w};
                float Ek[16];
                Ek[0]=N0[0]; Ek[1]=N0[1]; Ek[2]=N0[2]*A00+N0[3]*A01; Ek[3]=N0[2]*A10+N0[3]*A11;
                Ek[4]=N1[0]; Ek[5]=N1[1]; Ek[6]=N1[2]*A00+N1[3]*A01; Ek[7]=N1[2]*A10+N1[3]*A11;
                Ek[8]=N2[0]; Ek[9]=N2[1]; Ek[10]=N2[2]*A00+N2[3]*A01; Ek[11]=N2[2]*A10+N2[3]*A11;
                Ek[12]=N3[0]; Ek[13]=N3[1]; Ek[14]=N3[2]*A00+N3[3]*A01; Ek[15]=N3[2]*A10+N3[3]*A11;
                float y=SQ8l*(track[2*t]+track[2*t+1]);
                float bs_[4]={(ka.x+ka.y)*y,(ka.z+ka.w)*y,(kb.x+kb.y)*y,(kb.z+kb.w)*y};
                float En[16], bn[4];
                #pragma unroll
                for(int i=0;i<4;++i){
                    #pragma unroll
                    for(int j=0;j<4;++j)
                        En[i*4+j]=Ek[i*4]*Eo[j]+Ek[i*4+1]*Eo[4+j]+Ek[i*4+2]*Eo[8+j]+Ek[i*4+3]*Eo[12+j];
                    bn[i]=Ek[i*4]*bo[0]+Ek[i*4+1]*bo[1]+Ek[i*4+2]*bo[2]+Ek[i*4+3]*bo[3]+bs_[i];
                }
                #pragma unroll
                for(int i=0;i<16;++i) Eo[i]=En[i];
                #pragma unroll
                for(int i=0;i<4;++i) bo[i]=bn[i];
            }
            #pragma unroll
            for(int i=0;i<16;++i) g_elems[cidx*20+i]=Eo[i];
            #pragma unroll
            for(int i=0;i<4;++i)  g_elems[cidx*20+16+i]=bo[i];
        }
    }
}

// ================= KB: scan + replay + epilogue + output (proven) =================
__global__ void __launch_bounds__(NTH,1)
hmm_kB(const float* __restrict__ track, const float* __restrict__ bias_scales,
       const float* __restrict__ obs_noise, const float* __restrict__ trans_noise,
       const float* __restrict__ Ain, const float* __restrict__ init_cov,
       float* __restrict__ out, int T, int out_size)
{
    __shared__ float elems[NTH*20];
    __shared__ float fw[8];
    __shared__ double sred[2];
    __shared__ float shr[24];

    const int c = threadIdx.x;
    const int lane = c&31, wid = c>>5;
    const float SQ8 = 2.8284271247461903f;
    const float cst = 5.656854249492381f;

    const float bs0=bias_scales[0], bs1=bias_scales[1];
    const float bsu=0.5f*(bs0+bs1);
    const float r=obs_noise[0]*obs_noise[0];
    const float A00=Ain[0], A01=Ain[1], A10=Ain[2], A11=Ain[3];

    float sig[CH];
    #pragma unroll
    for(int k=0;k<CH;++k){
        int t=c*CH+k;
        float x0 = (t<T)?track[2*t]:0.0f;
        float x1 = (t<T)?track[2*t+1]:0.0f;
        sig[k]=SQ8*(x0+x1);
    }

    // load chunk element (replaces pass-1)
    float Eo[16], bo[4];
    {
        const float* ge = g_elems + c*20;
        #pragma unroll
        for(int i=0;i<16;++i){ Eo[i]=ge[i]; elems[c*20+i]=Eo[i]; }
        #pragma unroll
        for(int i=0;i<4;++i){ bo[i]=ge[16+i]; elems[c*20+16+i]=bo[i]; }
    }
    __syncthreads();

    for(int off=1; off<NTH; off<<=1){
        float El[16], bl[4];
        bool act = (c>=off);
        if(act){
            const float* lp=elems+(c-off)*20;
            #pragma unroll
            for(int i=0;i<16;++i) El[i]=lp[i];
            #pragma unroll
            for(int i=0;i<4;++i) bl[i]=lp[16+i];
        }
        __syncthreads();
        if(act){
            float En[16], bn[4];
            #pragma unroll
            for(int i=0;i<4;++i){
                #pragma unroll
                for(int j=0;j<4;++j)
                    En[i*4+j]=Eo[i*4]*El[j]+Eo[i*4+1]*El[4+j]+Eo[i*4+2]*El[8+j]+Eo[i*4+3]*El[12+j];
                bn[i]=Eo[i*4]*bl[0]+Eo[i*4+1]*bl[1]+Eo[i*4+2]*bl[2]+Eo[i*4+3]*bl[3]+bo[i];
            }
            #pragma unroll
            for(int i=0;i<16;++i){ Eo[i]=En[i]; elems[c*20+i]=En[i]; }
            #pragma unroll
            for(int i=0;i<4;++i){ bo[i]=bn[i]; elems[c*20+16+i]=bn[i]; }
        }
        __syncthreads();
    }

    float m0=0.f,m1=0.f,m2=0.f,m3=0.f;
    if(c>0){
        const float* pp=elems+(c-1)*20+16;
        m0=pp[0]; m1=pp[1]; m2=pp[2]; m3=pp[3];
    }
    float qd=0.0f;
    float prodm=1.0f;
    int eacc=0;
    #pragma unroll
    for(int k=0;k<CH;++k){
        int t=c*CH+k;
        float4 ka = g_kv[t*3+0];
        float4 kb = g_kv[t*3+1];
        float4 sc = g_kv[t*3+2];
        float p2=A00*m2+A10*m3;
        float p3=A01*m2+A11*m3;
        float y=sig[k];
        float z0=y-m0-cst*p2;
        float z1=y-m1-cst*p3;
        float id=sc.w;
        float u0=(sc.z*z0-sc.y*z1)*id;
        float u1=(sc.x*z1-sc.y*z0)*id;
        qd += z0*u0+z1*u1;
        float det=sc.x*sc.z-sc.y*sc.y;
        int bi=__float_as_int(det);
        eacc += ((bi>>23)&255)-127;
        prodm *= __int_as_float((bi&0x807FFFFF)|0x3F800000);
        int pb=__float_as_int(prodm);
        eacc += ((pb>>23)&255)-127;
        prodm = __int_as_float((pb&0x807FFFFF)|0x3F800000);
        m0 += ka.x*z0+ka.y*z1;
        m1 += ka.z*z0+ka.w*z1;
        m2  = p2 + kb.x*z0+kb.y*z1;
        m3  = p3 + kb.z*z0+kb.w*z1;
    }
    float ldt=fmaf((float)eacc, 0.6931471805599453f, logf(prodm));

    {
        float s=wred(qd);
        if(lane==0) fw[wid]=s;
        __syncthreads();
        if(c==0){
            double acc=0.0;
            for(int i=0;i<8;++i) acc+=(double)fw[i];
            sred[0]=acc;
        }
        __syncthreads();
        s=wred(ldt);
        if(lane==0) fw[wid]=s;
        __syncthreads();
        if(c==0){
            double acc=0.0;
            for(int i=0;i<8;++i) acc+=(double)fw[i];
            sred[1]=acc;
        }
        __syncthreads();
    }

    if(c==0){
        double ld2=sred[1];
        double s_wq=g_swq, s_qd=sred[0];
        double Td=(double)T, rr_=(double)r;
        double a0d=rr_/(double)bs0, a1d=rr_/(double)bs1, aud=rr_/(double)bsu;
        const double LOG2PI=1.8378770664093453;
        double ld_contrast=15.0*(4.0*Td*log(rr_)+2.0*log((a0d+Td)/a0d)+2.0*log((a1d+Td)/a1d));
        double ld_diff=2.0*(Td*log(rr_)+log((aud+Td)/aud));
        double logp=-0.5*(64.0*Td*LOG2PI)-0.5*(s_qd+2.0*s_wq)-0.5*(ld2+ld_contrast+ld_diff);
        shr[19]=(float)logp;

        float Mm[4][8];
        for(int i=0;i<4;++i)
            for(int j=0;j<4;++j){ Mm[i][j]=g_pTf[i*4+j]; Mm[i][4+j]=(i==j)?1.0f:0.0f; }
        for(int cc=0;cc<4;++cc){
            int piv=cc; float mx=fabsf(Mm[cc][cc]);
            for(int rr=cc+1;rr<4;++rr){
                float aa=fabsf(Mm[rr][cc]);
                if(aa>mx){mx=aa;piv=rr;}
            }
            if(piv!=cc)
                for(int j=0;j<8;++j){ float tm=Mm[cc][j]; Mm[cc][j]=Mm[piv][j]; Mm[piv][j]=tm; }
            float pv=1.0f/Mm[cc][cc];
            for(int j=0;j<8;++j) Mm[cc][j]*=pv;
            for(int rr=0;rr<4;++rr){
                if(rr==cc) continue;
                float f=Mm[rr][cc];
                for(int j=0;j<8;++j) Mm[rr][j]-=f*Mm[cc][j];
            }
        }
        for(int i=0;i<4;++i)
            for(int j=0;j<4;++j) shr[i*4+j]=Mm[i][4+j];
        shr[16]=(float)(1.0/(double)bs0+Td/rr_);
        shr[17]=(float)(1.0/(double)bs1+Td/rr_);
        shr[18]=(float)(1.0/(double)bsu+Td/rr_);
    }
    __syncthreads();

    if(c==0 && out_size>0) out[0]=shr[19];
    const int NP=66*66;
    const float INV32=0.03125f;
    const float INVS32=0.17677669529663687f;
    for(int idx=c; idx<NP; idx+=NTH){
        if(idx+1>=out_size) break;
        int i=idx/66, j=idx-66*i;
        float v;
        if(i<64 && j<64){
            int pi=i>>5, pj=j>>5, ei=i&1, ej=j&1;
            v=shr[pi*4+pj]*INV32;
            if(pi==pj){
                v += ((ei==ej)?shr[18]:-shr[18])*INV32;
                if(ei==ej){
                    v -= shr[16+ei]*0.0625f;
                    if(i==j) v += shr[16+ei];
                }
            }
        } else if(i<64){
            int pi=i>>5;
            v=shr[pi*4+2+(j-64)]*INVS32;
        } else if(j<64){
            int pj=j>>5;
            v=shr[pj*4+2+(i-64)]*INVS32;
        } else {
            v=shr[(2+i-64)*4+(2+j-64)];
        }
        out[1+idx]=v;
    }
}

extern "C" void kernel_launch(void* const* d_in, const int* in_sizes, int n_in,
                              void* d_out, int out_size) {
    const float* track     = (const float*)d_in[0];
    const float* bias_sc   = (const float*)d_in[1];
    const float* obs_noise = (const float*)d_in[2];
    const float* trans_n   = (const float*)d_in[3];
    const float* A         = (const float*)d_in[4];
    const float* init_cov  = (const float*)d_in[5];
    float* out = (float*)d_out;
    int T = in_sizes[0]/2;
    if (T > TT) T = TT;
    int t0 = (T >= T0) ? T0 : T;
    int nfill = (T + NTH - 1) / NTH;   // blocks covering t in [0, T)

    hmm_kA<<<nfill + 1, NTH>>>(track, bias_sc, obs_noise, trans_n, A, init_cov, T, t0, nfill);
    hmm_kB<<<1, NTH>>>(track, bias_sc, obs_noise, trans_n, A, init_cov, out, T, out_size);
}

// round 16
// speedup vs baseline: 84.1387x; 1.0616x over previous
#include <cuda_runtime.h>
#include <math.h>

#define NTH 256
#define CH 16
#define TT 4096
#define T0 16
#define NCH (TT/CH)

__device__ float4 g_kv[TT*3];
__device__ float  g_elems[NCH*20];
__device__ float  g_pTf[16];    // stores the INVERSE of final filtered covariance
__device__ float  g_consts[3];  // 1/bs0+T/r, 1/bs1+T/r, 1/bsu+T/r
__device__ double g_logc;       // folded logp constant (incl. s_wq)

// symmetric-PD 4x4 inverse via 2x2 block Schur, fp32 (proven)
__device__ __forceinline__ void finv4sym(const float* m, float* o){
    float a00=m[0], a01=m[1], a11=m[5];
    float idA=1.0f/(a00*a11-a01*a01);
    float Ai00=a11*idA, Ai01=-a01*idA, Ai11=a00*idA;
    float b00=m[2], b01=m[3], b10=m[6], b11=m[7];
    float U00=Ai00*b00+Ai01*b10, U01=Ai00*b01+Ai01*b11;
    float U10=Ai01*b00+Ai11*b10, U11=Ai01*b01+Ai11*b11;
    float c00=m[10]-(b00*U00+b10*U10);
    float c01=m[11]-(b00*U01+b10*U11);
    float c11=m[15]-(b01*U01+b11*U11);
    float idC=1.0f/(c00*c11-c01*c01);
    float Si00=c11*idC, Si01=-c01*idC, Si11=c00*idC;
    float TR00=-(U00*Si00+U01*Si01), TR01=-(U00*Si01+U01*Si11);
    float TR10=-(U10*Si00+U11*Si01), TR11=-(U10*Si01+U11*Si11);
    float TL00=Ai00-(TR00*U00+TR01*U01);
    float TL01=Ai01-(TR00*U10+TR01*U11);
    float TL11=Ai11-(TR10*U10+TR11*U11);
    o[0]=TL00; o[1]=TL01; o[2]=TR00; o[3]=TR01;
    o[4]=TL01; o[5]=TL11; o[6]=TR10; o[7]=TR11;
    o[8]=TR00; o[9]=TR10; o[10]=Si00; o[11]=Si01;
    o[12]=TR01; o[13]=TR11; o[14]=Si01; o[15]=Si11;
}

__device__ __forceinline__ float wred(float v){
    #pragma unroll
    for(int off=16; off; off>>=1) v += __shfl_down_sync(0xffffffffu, v, off);
    return v;
}

// ================= KA =================
__global__ void __launch_bounds__(NTH,1)
hmm_kA(const float* __restrict__ track, const float* __restrict__ bias_scales,
       const float* __restrict__ obs_noise, const float* __restrict__ trans_noise,
       const float* __restrict__ Ain, const float* __restrict__ init_cov,
       int T, int t0, int nfill)
{
    const float cst = 5.656854249492381f;
    const float SQ8 = 2.8284271247461903f;
    const float r = obs_noise[0]*obs_noise[0];
    const float bs0=bias_scales[0], bs1=bias_scales[1];
    const float bsu=0.5f*(bs0+bs1);

    if((int)blockIdx.x == nfill){
        // ---- diff-channel prefix scan (proven) + folded logp constants ----
        __shared__ float wtot[8];
        __shared__ float fw[8];
        const int c = threadIdx.x;
        const int lane = c&31, wid = c>>5;
        float del[CH];
        #pragma unroll
        for(int k=0;k<CH;++k){
            int t=c*CH+k;
            float x0 = (t<T)?track[2*t]:0.0f;
            float x1 = (t<T)?track[2*t+1]:0.0f;
            del[k]=SQ8*(x0-x1);
        }
        const float adf=r/bsu;
        float s=0.0f;
        #pragma unroll
        for(int k=0;k<CH;++k) s+=del[k];
        float v=s;
        #pragma unroll
        for(int off=1;off<32;off<<=1){
            float n=__shfl_up_sync(0xffffffffu,v,off);
            if(lane>=off) v+=n;
        }
        if(lane==31) wtot[wid]=v;
        __syncthreads();
        if(wid==0 && lane<8){
            float orig=wtot[lane], w=orig;
            #pragma unroll
            for(int off=1;off<8;off<<=1){
                float n=__shfl_up_sync(0xffu,w,off);
                if(lane>=off) w+=n;
            }
            wtot[lane]=w-orig;
        }
        __syncthreads();
        float run=(v-s)+wtot[wid];
        float wq=0.0f;
        #pragma unroll
        for(int k=0;k<CH;++k){
            int t=c*CH+k;
            if(t<T){
                float at=adf+(float)t;
                float zd=del[k]-run/at;
                wq += zd*zd*at/(r*(at+1.0f));
            }
            run+=del[k];
        }
        float ws=wred(wq);
        if(lane==0) fw[wid]=ws;
        __syncthreads();
        if(c==0){
            double s_wq=0.0;
            for(int i=0;i<8;++i) s_wq+=(double)fw[i];
            double Td=(double)T, rr_=(double)r;
            double a0d=rr_/(double)bs0, a1d=rr_/(double)bs1, aud=rr_/(double)bsu;
            const double LOG2PI=1.8378770664093453;
            double ld_contrast=15.0*(4.0*Td*log(rr_)+2.0*log((a0d+Td)/a0d)+2.0*log((a1d+Td)/a1d));
            double ld_diff=2.0*(Td*log(rr_)+log((aud+Td)/aud));
            g_logc = -0.5*(64.0*Td*LOG2PI + ld_contrast + ld_diff) - s_wq;
            g_consts[0]=(float)(1.0/(double)bs0 + Td/rr_);
            g_consts[1]=(float)(1.0/(double)bs1 + Td/rr_);
            g_consts[2]=(float)(1.0/(double)bsu + Td/rr_);
        }
        return;
    }

    __shared__ float lamW[19];
    const float q=trans_noise[0]*trans_noise[0];
    const float A00=Ain[0], A01=Ain[1], A10=Ain[2], A11=Ain[3];
    const float c2=32.0f;

    // ---- thread 0: redundant burn-in + fp32 bridge (proven) ----
    if(threadIdx.x==0){
        float puu00=bsu, puu01=0.0f, puu11=bsu;
        float pus00=0.f, pus01=0.f, pus10=0.f, pus11=0.f;
        float pss00=init_cov[0], pss01=init_cov[1], pss11=init_cov[3];
        bool store = (blockIdx.x==0);
        float4* gp = g_kv;
        for(int t=0;t<t0;++t){
            float b00=pss00*A00+pss01*A10;
            float b01=pss00*A01+pss01*A11;
            float b10=pss01*A00+pss11*A10;
            float b11=pss01*A01+pss11*A11;
            pss00=A00*b00+A10*b10+q;
            pss01=A00*b01+A10*b11;
            pss11=A01*b01+A11*b11+q;
            float t00=pus00*A00+pus01*A10;
            float t01=pus00*A01+pus01*A11;
            float t10=pus10*A00+pus11*A10;
            float t11=pus10*A01+pus11*A11;
            pus00=t00;pus01=t01;pus10=t10;pus11=t11;
            float S00=puu00+2.0f*cst*pus00+c2*pss00+r;
            float S01=puu01+cst*(pus01+pus10)+c2*pss01;
            float S11=puu11+2.0f*cst*pus11+c2*pss11+r;
            float det=S00*S11-S01*S01;
            float id=1.0f/det;
            float G00=puu00+cst*pus00, G01=puu01+cst*pus01;
            float G10=puu01+cst*pus10, G11=puu11+cst*pus11;
            float G20=pus00+cst*pss00, G21=pus10+cst*pss01;
            float G30=pus01+cst*pss01, G31=pus11+cst*pss11;
            float W00=(G00*S11-G01*S01)*id, W01=(G01*S00-G00*S01)*id;
            float W10=(G10*S11-G11*S01)*id, W11=(G11*S00-G10*S01)*id;
            float W20=(G20*S11-G21*S01)*id, W21=(G21*S00-G20*S01)*id;
            float W30=(G30*S11-G31*S01)*id, W31=(G31*S00-G30*S01)*id;
            if(store){
                gp[0]=make_float4(W00,W01,W10,W11);
                gp[1]=make_float4(W20,W21,W30,W31);
                gp[2]=make_float4(S00,S01,S11,id);
                gp+=3;
            }
            puu00-=W00*G00+W01*G01;
            puu01-=W00*G10+W01*G11;
            puu11-=W10*G10+W11*G11;
            pus00-=W00*G20+W01*G21;
            pus01-=W00*G30+W01*G31;
            pus10-=W10*G20+W11*G21;
            pus11-=W10*G30+W11*G31;
            pss00-=W20*G20+W21*G21;
            pss01-=W20*G30+W21*G31;
            pss11-=W30*G30+W31*G31;
        }
        if(t0==T && store){
            float Pm[16]={puu00,puu01,pus00,pus01, puu01,puu11,pus10,pus11,
                          pus00,pus10,pss00,pss01, pus01,pus11,pss01,pss11};
            float Qi[16];
            finv4sym(Pm,Qi);
            for(int i=0;i<16;++i) g_pTf[i]=Qi[i];
        }
        if(t0<T){
            float uu00=puu00, uu01=puu01, uu11=puu11;
            float us00=pus00, us01=pus01, us10=pus10, us11=pus11;
            float ss00=pss00, ss01=pss01, ss11=pss11;
            float L0[16], L1[16], M[16];
            for(int rep=0;rep<2;++rep){
                float b00=ss00*A00+ss01*A10, b01=ss00*A01+ss01*A11;
                float b10=ss01*A00+ss11*A10, b11=ss01*A01+ss11*A11;
                ss00=A00*b00+A10*b10+q;
                ss01=A00*b01+A10*b11;
                ss11=A01*b01+A11*b11+q;
                float t00=us00*A00+us01*A10, t01=us00*A01+us01*A11;
                float t10=us10*A00+us11*A10, t11=us10*A01+us11*A11;
                us00=t00;us01=t01;us10=t10;us11=t11;
                M[0]=uu00; M[1]=uu01; M[2]=us00; M[3]=us01;
                M[4]=uu01; M[5]=uu11; M[6]=us10; M[7]=us11;
                M[8]=us00; M[9]=us10; M[10]=ss00; M[11]=ss01;
                M[12]=us01; M[13]=us11; M[14]=ss01; M[15]=ss11;
                finv4sym(M, (rep==0)?L0:L1);
                if(rep==1) break;
                float S00=uu00+2.0f*cst*us00+c2*ss00+r;
                float S01=uu01+cst*(us01+us10)+c2*ss01;
                float S11=uu11+2.0f*cst*us11+c2*ss11+r;
                float id=1.0f/(S00*S11-S01*S01);
                float G00=uu00+cst*us00, G01=uu01+cst*us01;
                float G10=uu01+cst*us10, G11=uu11+cst*us11;
                float G20=us00+cst*ss00, G21=us10+cst*ss01;
                float G30=us01+cst*ss01, G31=us11+cst*ss11;
                float W00=(G00*S11-G01*S01)*id, W01=(G01*S00-G00*S01)*id;
                float W10=(G10*S11-G11*S01)*id, W11=(G11*S00-G10*S01)*id;
                float W20=(G20*S11-G21*S01)*id, W21=(G21*S00-G20*S01)*id;
                float W30=(G30*S11-G31*S01)*id, W31=(G31*S00-G30*S01)*id;
                uu00-=W00*G00+W01*G01;
                uu01-=W00*G10+W01*G11;
                uu11-=W10*G10+W11*G11;
                us00-=W00*G20+W01*G21;
                us01-=W00*G30+W01*G31;
                us10-=W10*G20+W11*G21;
                us11-=W10*G30+W11*G31;
                ss00-=W20*G20+W21*G21;
                ss01-=W20*G30+W21*G31;
                ss11-=W30*G30+W31*G31;
            }
            for(int i=0;i<16;++i) lamW[i]=L0[i];
            lamW[16]=L1[0]-L0[0];
            lamW[17]=L1[1]-L0[1];
            lamW[18]=L1[5]-L0[5];
        }
    }
    __syncthreads();

    // ---- gain fill: t = 256*b + tid (proven); t==T-1 also inverts pTf ----
    {
        int t = (int)blockIdx.x*NTH + threadIdx.x;
        if(t >= t0 && t < T){
            float l02=lamW[2],  l03=lamW[3];
            float l12=lamW[6],  l13=lamW[7];
            float l22=lamW[10], l23=lamW[11], l33=lamW[15];
            float L00=lamW[0], L01=lamW[1], L11=lamW[5];
            float W0=lamW[16], W1=lamW[17], W2=lamW[18];
            float kt=(float)(t-t0);
            float l00=fmaf(kt,W0,L00);
            float l01=fmaf(kt,W1,L01);
            float l11=fmaf(kt,W2,L11);
            float iX=1.0f/(l00*l11-l01*l01);
            float X00=l11*iX, X01=-l01*iX, X11=l00*iX;
            float B100=X00*l02+X01*l12, B101=X00*l03+X01*l13;
            float B110=X01*l02+X11*l12, B111=X01*l03+X11*l13;
            float Sp00=l22-(l02*B100+l12*B110);
            float Sp01=l23-(l02*B101+l12*B111);
            float Sp11=l33-(l03*B101+l13*B111);
            float iS=1.0f/(Sp00*Sp11-Sp01*Sp01);
            float Z00=Sp11*iS, Z01=-Sp01*iS, Z11=Sp00*iS;
            float pus00=-(B100*Z00+B101*Z01);
            float pus01=-(B100*Z01+B101*Z11);
            float pus10=-(B110*Z00+B111*Z01);
            float pus11=-(B110*Z01+B111*Z11);
            float puu00=X00-(pus00*B100+pus01*B101);
            float puu01=X01-(pus00*B110+pus01*B111);
            float puu11=X11-(pus10*B110+pus11*B111);
            float pss00=Z00, pss01=Z01, pss11=Z11;
            float S00=puu00+2.0f*cst*pus00+c2*pss00+r;
            float S01=puu01+cst*(pus01+pus10)+c2*pss01;
            float S11=puu11+2.0f*cst*pus11+c2*pss11+r;
            float det=S00*S11-S01*S01;
            float id=1.0f/det;
            float G00=puu00+cst*pus00, G01=puu01+cst*pus01;
            float G10=puu01+cst*pus10, G11=puu11+cst*pus11;
            float G20=pus00+cst*pss00, G21=pus10+cst*pss01;
            float G30=pus01+cst*pss01, G31=pus11+cst*pss11;
            float W00=(G00*S11-G01*S01)*id, W01=(G01*S00-G00*S01)*id;
            float W10=(G10*S11-G11*S01)*id, W11=(G11*S00-G10*S01)*id;
            float W20=(G20*S11-G21*S01)*id, W21=(G21*S00-G20*S01)*id;
            float W30=(G30*S11-G31*S01)*id, W31=(G31*S00-G30*S01)*id;
            g_kv[t*3+0]=make_float4(W00,W01,W10,W11);
            g_kv[t*3+1]=make_float4(W20,W21,W30,W31);
            g_kv[t*3+2]=make_float4(S00,S01,S11,id);
            if(t==T-1){
                float f0=puu00-(W00*G00+W01*G01);
                float f1=puu01-(W00*G10+W01*G11);
                float f5=puu11-(W10*G10+W11*G11);
                float f2=pus00-(W00*G20+W01*G21);
                float f3=pus01-(W00*G30+W01*G31);
                float f6=pus10-(W10*G20+W11*G21);
                float f7=pus11-(W10*G30+W11*G31);
                float f10=pss00-(W20*G20+W21*G21);
                float f11=pss01-(W20*G30+W21*G31);
                float f15=pss11-(W30*G30+W31*G31);
                float Pm[16]={f0,f1,f2,f3, f1,f5,f6,f7, f2,f6,f10,f11, f3,f7,f11,f15};
                float Qi[16];
                finv4sym(Pm,Qi);
                #pragma unroll
                for(int i=0;i<16;++i) g_pTf[i]=Qi[i];
            }
        }
    }
    __syncthreads();

    // ---- chunk composition: 16 chunks per block (proven) ----
    if(threadIdx.x < 16){
        int cidx = (int)blockIdx.x*16 + threadIdx.x;
        if(cidx*CH < T){
            float Eo[16]={1,0,0,0, 0,1,0,0, 0,0,1,0, 0,0,0,1};
            float bo[4]={0,0,0,0};
            #pragma unroll
            for(int k=0;k<CH;++k){
                int t=cidx*CH+k;
                if(t>=T) break;
                float4 ka = g_kv[t*3+0];
                float4 kb = g_kv[t*3+1];
                float N0[4]={1.0f-ka.x, -ka.y, -cst*ka.x, -cst*ka.y};
                float N1[4]={-ka.z, 1.0f-ka.w, -cst*ka.z, -cst*ka.w};
                float N2[4]={-kb.x, -kb.y, 1.0f-cst*kb.x, -cst*kb.y};
                float N3[4]={-kb.z, -kb.w, -cst*kb.z, 1.0f-cst*kb.w};
                float Ek[16];
                Ek[0]=N0[0]; Ek[1]=N0[1]; Ek[2]=N0[2]*A00+N0[3]*A01; Ek[3]=N0[2]*A10+N0[3]*A11;
                Ek[4]=N1[0]; Ek[5]=N1[1]; Ek[6]=N1[2]*A00+N1[3]*A01; Ek[7]=N1[2]*A10+N1[3]*A11;
                Ek[8]=N2[0]; Ek[9]=N2[1]; Ek[10]=N2[2]*A00+N2[3]*A01; Ek[11]=N2[2]*A10+N2[3]*A11;
                Ek[12]=N3[0]; Ek[13]=N3[1]; Ek[14]=N3[2]*A00+N3[3]*A01; Ek[15]=N3[2]*A10+N3[3]*A11;
                float y=SQ8*(track[2*t]+track[2*t+1]);
                float bs_[4]={(ka.x+ka.y)*y,(ka.z+ka.w)*y,(kb.x+kb.y)*y,(kb.z+kb.w)*y};
                float En[16], bn[4];
                #pragma unroll
                for(int i=0;i<4;++i){
                    #pragma unroll
                    for(int j=0;j<4;++j)
                        En[i*4+j]=Ek[i*4]*Eo[j]+Ek[i*4+1]*Eo[4+j]+Ek[i*4+2]*Eo[8+j]+Ek[i*4+3]*Eo[12+j];
                    bn[i]=Ek[i*4]*bo[0]+Ek[i*4+1]*bo[1]+Ek[i*4+2]*bo[2]+Ek[i*4+3]*bo[3]+bs_[i];
                }
                #pragma unroll
                for(int i=0;i<16;++i) Eo[i]=En[i];
                #pragma unroll
                for(int i=0;i<4;++i) bo[i]=bn[i];
            }
            #pragma unroll
            for(int i=0;i<16;++i) g_elems[cidx*20+i]=Eo[i];
            #pragma unroll
            for(int i=0;i<4;++i)  g_elems[cidx*20+16+i]=bo[i];
        }
    }
}

// ================= KB: scan + replay + slim finish + output =================
__global__ void __launch_bounds__(NTH,1)
hmm_kB(const float* __restrict__ track, const float* __restrict__ Ain,
       float* __restrict__ out, int T, int out_size)
{
    __shared__ float elems[NTH*20];
    __shared__ float fw[8];
    __shared__ double sred[2];
    __shared__ float shr[24];

    const int c = threadIdx.x;
    const int lane = c&31, wid = c>>5;
    const float SQ8 = 2.8284271247461903f;
    const float cst = 5.656854249492381f;
    const float A00=Ain[0], A01=Ain[1], A10=Ain[2], A11=Ain[3];

    float sig[CH];
    #pragma unroll
    for(int k=0;k<CH;++k){
        int t=c*CH+k;
        float x0 = (t<T)?track[2*t]:0.0f;
        float x1 = (t<T)?track[2*t+1]:0.0f;
        sig[k]=SQ8*(x0+x1);
    }

    float Eo[16], bo[4];
    {
        const float* ge = g_elems + c*20;
        #pragma unroll
        for(int i=0;i<16;++i){ Eo[i]=ge[i]; elems[c*20+i]=Eo[i]; }
        #pragma unroll
        for(int i=0;i<4;++i){ bo[i]=ge[16+i]; elems[c*20+16+i]=bo[i]; }
    }
    __syncthreads();

    for(int off=1; off<NTH; off<<=1){
        float El[16], bl[4];
        bool act = (c>=off);
        if(act){
            const float* lp=elems+(c-off)*20;
            #pragma unroll
            for(int i=0;i<16;++i) El[i]=lp[i];
            #pragma unroll
            for(int i=0;i<4;++i) bl[i]=lp[16+i];
        }
        __syncthreads();
        if(act){
            float En[16], bn[4];
            #pragma unroll
            for(int i=0;i<4;++i){
                #pragma unroll
                for(int j=0;j<4;++j)
                    En[i*4+j]=Eo[i*4]*El[j]+Eo[i*4+1]*El[4+j]+Eo[i*4+2]*El[8+j]+Eo[i*4+3]*El[12+j];
                bn[i]=Eo[i*4]*bl[0]+Eo[i*4+1]*bl[1]+Eo[i*4+2]*bl[2]+Eo[i*4+3]*bl[3]+bo[i];
            }
            #pragma unroll
            for(int i=0;i<16;++i){ Eo[i]=En[i]; elems[c*20+i]=En[i]; }
            #pragma unroll
            for(int i=0;i<4;++i){ bo[i]=bn[i]; elems[c*20+16+i]=bn[i]; }
        }
        __syncthreads();
    }

    float m0=0.f,m1=0.f,m2=0.f,m3=0.f;
    if(c>0){
        const float* pp=elems+(c-1)*20+16;
        m0=pp[0]; m1=pp[1]; m2=pp[2]; m3=pp[3];
    }
    float qd=0.0f;
    float prodm=1.0f;
    int eacc=0;
    #pragma unroll
    for(int k=0;k<CH;++k){
        int t=c*CH+k;
        float4 ka = g_kv[t*3+0];
        float4 kb = g_kv[t*3+1];
        float4 sc = g_kv[t*3+2];
        float p2=A00*m2+A10*m3;
        float p3=A01*m2+A11*m3;
        float y=sig[k];
        float z0=y-m0-cst*p2;
        float z1=y-m1-cst*p3;
        float id=sc.w;
        float u0=(sc.z*z0-sc.y*z1)*id;
        float u1=(sc.x*z1-sc.y*z0)*id;
        qd += z0*u0+z1*u1;
        float det=sc.x*sc.z-sc.y*sc.y;
        int bi=__float_as_int(det);
        eacc += ((bi>>23)&255)-127;
        prodm *= __int_as_float((bi&0x807FFFFF)|0x3F800000);
        int pb=__float_as_int(prodm);
        eacc += ((pb>>23)&255)-127;
        prodm = __int_as_float((pb&0x807FFFFF)|0x3F800000);
        m0 += ka.x*z0+ka.y*z1;
        m1 += ka.z*z0+ka.w*z1;
        m2  = p2 + kb.x*z0+kb.y*z1;
        m3  = p3 + kb.z*z0+kb.w*z1;
    }
    float ldt=fmaf((float)eacc, 0.6931471805599453f, logf(prodm));

    {
        float s=wred(qd);
        if(lane==0) fw[wid]=s;
        __syncthreads();
        if(c==0){
            double acc=0.0;
            for(int i=0;i<8;++i) acc+=(double)fw[i];
            sred[0]=acc;
        }
        __syncthreads();
        s=wred(ldt);
        if(lane==0) fw[wid]=s;
        __syncthreads();
        if(c==0){
            double acc=0.0;
            for(int i=0;i<8;++i) acc+=(double)fw[i];
            sred[1]=acc;
        }
        __syncthreads();
    }

    if(c==0){
        double logp = g_logc - 0.5*(sred[0] + sred[1]);
        shr[19]=(float)logp;
        for(int i=0;i<16;++i) shr[i]=g_pTf[i];
        shr[16]=g_consts[0]; shr[17]=g_consts[1]; shr[18]=g_consts[2];
    }
    __syncthreads();

    if(c==0 && out_size>0) out[0]=shr[19];
    const int NP=66*66;
    const float INV32=0.03125f;
    const float INVS32=0.17677669529663687f;
    for(int idx=c; idx<NP; idx+=NTH){
        if(idx+1>=out_size) break;
        int i=idx/66, j=idx-66*i;
        float v;
        if(i<64 && j<64){
            int pi=i>>5, pj=j>>5, ei=i&1, ej=j&1;
            v=shr[pi*4+pj]*INV32;
            if(pi==pj){
                v += ((ei==ej)?shr[18]:-shr[18])*INV32;
                if(ei==ej){
                    v -= shr[16+ei]*0.0625f;
                    if(i==j) v += shr[16+ei];
                }
            }
        } else if(i<64){
            int pi=i>>5;
            v=shr[pi*4+2+(j-64)]*INVS32;
        } else if(j<64){
            int pj=j>>5;
            v=shr[pj*4+2+(i-64)]*INVS32;
        } else {
            v=shr[(2+i-64)*4+(2+j-64)];
        }
        out[1+idx]=v;
    }
}

extern "C" void kernel_launch(void* const* d_in, const int* in_sizes, int n_in,
                              void* d_out, int out_size) {
    const float* track     = (const float*)d_in[0];
    const float* bias_sc   = (const float*)d_in[1];
    const float* obs_noise = (const float*)d_in[2];
    const float* trans_n   = (const float*)d_in[3];
    const float* A         = (const float*)d_in[4];
    const float* init_cov  = (const float*)d_in[5];
    float* out = (float*)d_out;
    int T = in_sizes[0]/2;
    if (T > TT) T = TT;
    int t0 = (T >= T0) ? T0 : T;
    int nfill = (T + NTH - 1) / NTH;

    hmm_kA<<<nfill + 1, NTH>>>(track, bias_sc, obs_noise, trans_n, A, init_cov, T, t0, nfill);
    hmm_kB<<<1, NTH>>>(track, A, out, T, out_size);
}

// round 17
// speedup vs baseline: 94.4942x; 1.1231x over previous
#include <cuda_runtime.h>
#include <math.h>

#define NTH 256
#define CH 16
#define TT 4096
#define T0 16
#define NCH (TT/CH)

__device__ float4 g_kv[TT*3];
__device__ float  g_elems[NCH*20];
__device__ float  g_pTf[16];    // INVERSE of final filtered covariance
__device__ double g_logc;       // folded logp constant (incl. s_wq)

__device__ __forceinline__ void finv4sym(const float* m, float* o){
    float a00=m[0], a01=m[1], a11=m[5];
    float idA=1.0f/(a00*a11-a01*a01);
    float Ai00=a11*idA, Ai01=-a01*idA, Ai11=a00*idA;
    float b00=m[2], b01=m[3], b10=m[6], b11=m[7];
    float U00=Ai00*b00+Ai01*b10, U01=Ai00*b01+Ai01*b11;
    float U10=Ai01*b00+Ai11*b10, U11=Ai01*b01+Ai11*b11;
    float c00=m[10]-(b00*U00+b10*U10);
    float c01=m[11]-(b00*U01+b10*U11);
    float c11=m[15]-(b01*U01+b11*U11);
    float idC=1.0f/(c00*c11-c01*c01);
    float Si00=c11*idC, Si01=-c01*idC, Si11=c00*idC;
    float TR00=-(U00*Si00+U01*Si01), TR01=-(U00*Si01+U01*Si11);
    float TR10=-(U10*Si00+U11*Si01), TR11=-(U10*Si01+U11*Si11);
    float TL00=Ai00-(TR00*U00+TR01*U01);
    float TL01=Ai01-(TR00*U10+TR01*U11);
    float TL11=Ai11-(TR10*U10+TR11*U11);
    o[0]=TL00; o[1]=TL01; o[2]=TR00; o[3]=TR01;
    o[4]=TL01; o[5]=TL11; o[6]=TR10; o[7]=TR11;
    o[8]=TR00; o[9]=TR10; o[10]=Si00; o[11]=Si01;
    o[12]=TR01; o[13]=TR11; o[14]=Si01; o[15]=Si11;
}

__device__ __forceinline__ float wred(float v){
    #pragma unroll
    for(int off=16; off; off>>=1) v += __shfl_down_sync(0xffffffffu, v, off);
    return v;
}

// ================= KA =================
__global__ void __launch_bounds__(NTH,1)
hmm_kA(const float* __restrict__ track, const float* __restrict__ bias_scales,
       const float* __restrict__ obs_noise, const float* __restrict__ trans_noise,
       const float* __restrict__ Ain, const float* __restrict__ init_cov,
       float* __restrict__ out, int T, int t0, int nfill, int out_size)
{
    const float cst = 5.656854249492381f;
    const float SQ8 = 2.8284271247461903f;
    const float r = obs_noise[0]*obs_noise[0];
    const float bs0=bias_scales[0], bs1=bias_scales[1];
    const float bsu=0.5f*(bs0+bs1);

    if((int)blockIdx.x == nfill){
        // ---- diff-channel prefix scan (proven) + folded logp constants ----
        __shared__ float wtot[8];
        __shared__ float fw[8];
        const int c = threadIdx.x;
        const int lane = c&31, wid = c>>5;
        float del[CH];
        #pragma unroll
        for(int k=0;k<CH;++k){
            int t=c*CH+k;
            float x0 = (t<T)?track[2*t]:0.0f;
            float x1 = (t<T)?track[2*t+1]:0.0f;
            del[k]=SQ8*(x0-x1);
        }
        const float adf=r/bsu;
        float s=0.0f;
        #pragma unroll
        for(int k=0;k<CH;++k) s+=del[k];
        float v=s;
        #pragma unroll
        for(int off=1;off<32;off<<=1){
            float n=__shfl_up_sync(0xffffffffu,v,off);
            if(lane>=off) v+=n;
        }
        if(lane==31) wtot[wid]=v;
        __syncthreads();
        if(wid==0 && lane<8){
            float orig=wtot[lane], w=orig;
            #pragma unroll
            for(int off=1;off<8;off<<=1){
                float n=__shfl_up_sync(0xffu,w,off);
                if(lane>=off) w+=n;
            }
            wtot[lane]=w-orig;
        }
        __syncthreads();
        float run=(v-s)+wtot[wid];
        float wq=0.0f;
        #pragma unroll
        for(int k=0;k<CH;++k){
            int t=c*CH+k;
            if(t<T){
                float at=adf+(float)t;
                float zd=del[k]-run/at;
                wq += zd*zd*at/(r*(at+1.0f));
            }
            run+=del[k];
        }
        float ws=wred(wq);
        if(lane==0) fw[wid]=ws;
        __syncthreads();
        if(c==0){
            double s_wq=0.0;
            for(int i=0;i<8;++i) s_wq+=(double)fw[i];
            double Td=(double)T, rr_=(double)r;
            double a0d=rr_/(double)bs0, a1d=rr_/(double)bs1, aud=rr_/(double)bsu;
            const double LOG2PI=1.8378770664093453;
            double ld_contrast=15.0*(4.0*Td*log(rr_)+2.0*log((a0d+Td)/a0d)+2.0*log((a1d+Td)/a1d));
            double ld_diff=2.0*(Td*log(rr_)+log((aud+Td)/aud));
            g_logc = -0.5*(64.0*Td*LOG2PI + ld_contrast + ld_diff) - s_wq;
        }
        return;
    }

    __shared__ float lamW[19];
    __shared__ float shp[16];   // pTf inverse copy (last block)
    __shared__ float shc[3];    // consts (last block)
    const float q=trans_noise[0]*trans_noise[0];
    const float A00=Ain[0], A01=Ain[1], A10=Ain[2], A11=Ain[3];
    const float c2=32.0f;

    // ---- thread 0: redundant burn-in + fp32 bridge (proven) ----
    if(threadIdx.x==0){
        float puu00=bsu, puu01=0.0f, puu11=bsu;
        float pus00=0.f, pus01=0.f, pus10=0.f, pus11=0.f;
        float pss00=init_cov[0], pss01=init_cov[1], pss11=init_cov[3];
        bool store = (blockIdx.x==0);
        float4* gp = g_kv;
        for(int t=0;t<t0;++t){
            float b00=pss00*A00+pss01*A10;
            float b01=pss00*A01+pss01*A11;
            float b10=pss01*A00+pss11*A10;
            float b11=pss01*A01+pss11*A11;
            pss00=A00*b00+A10*b10+q;
            pss01=A00*b01+A10*b11;
            pss11=A01*b01+A11*b11+q;
            float t00=pus00*A00+pus01*A10;
            float t01=pus00*A01+pus01*A11;
            float t10=pus10*A00+pus11*A10;
            float t11=pus10*A01+pus11*A11;
            pus00=t00;pus01=t01;pus10=t10;pus11=t11;
            float S00=puu00+2.0f*cst*pus00+c2*pss00+r;
            float S01=puu01+cst*(pus01+pus10)+c2*pss01;
            float S11=puu11+2.0f*cst*pus11+c2*pss11+r;
            float det=S00*S11-S01*S01;
            float id=1.0f/det;
            float G00=puu00+cst*pus00, G01=puu01+cst*pus01;
            float G10=puu01+cst*pus10, G11=puu11+cst*pus11;
            float G20=pus00+cst*pss00, G21=pus10+cst*pss01;
            float G30=pus01+cst*pss01, G31=pus11+cst*pss11;
            float W00=(G00*S11-G01*S01)*id, W01=(G01*S00-G00*S01)*id;
            float W10=(G10*S11-G11*S01)*id, W11=(G11*S00-G10*S01)*id;
            float W20=(G20*S11-G21*S01)*id, W21=(G21*S00-G20*S01)*id;
            float W30=(G30*S11-G31*S01)*id, W31=(G31*S00-G30*S01)*id;
            if(store){
                gp[0]=make_float4(W00,W01,W10,W11);
                gp[1]=make_float4(W20,W21,W30,W31);
                gp[2]=make_float4(S00,S01,S11,id);
                gp+=3;
            }
            puu00-=W00*G00+W01*G01;
            puu01-=W00*G10+W01*G11;
            puu11-=W10*G10+W11*G11;
            pus00-=W00*G20+W01*G21;
            pus01-=W00*G30+W01*G31;
            pus10-=W10*G20+W11*G21;
            pus11-=W10*G30+W11*G31;
            pss00-=W20*G20+W21*G21;
            pss01-=W20*G30+W21*G31;
            pss11-=W30*G30+W31*G31;
        }
        if(t0==T && store){
            float Pm[16]={puu00,puu01,pus00,pus01, puu01,puu11,pus10,pus11,
                          pus00,pus10,pss00,pss01, pus01,pus11,pss01,pss11};
            float Qi[16];
            finv4sym(Pm,Qi);
            for(int i=0;i<16;++i) g_pTf[i]=Qi[i];
        }
        if(t0<T){
            float uu00=puu00, uu01=puu01, uu11=puu11;
            float us00=pus00, us01=pus01, us10=pus10, us11=pus11;
            float ss00=pss00, ss01=pss01, ss11=pss11;
            float L0[16], L1[16], M[16];
            for(int rep=0;rep<2;++rep){
                float b00=ss00*A00+ss01*A10, b01=ss00*A01+ss01*A11;
                float b10=ss01*A00+ss11*A10, b11=ss01*A01+ss11*A11;
                ss00=A00*b00+A10*b10+q;
                ss01=A00*b01+A10*b11;
                ss11=A01*b01+A11*b11+q;
                float t00=us00*A00+us01*A10, t01=us00*A01+us01*A11;
                float t10=us10*A00+us11*A10, t11=us10*A01+us11*A11;
                us00=t00;us01=t01;us10=t10;us11=t11;
                M[0]=uu00; M[1]=uu01; M[2]=us00; M[3]=us01;
                M[4]=uu01; M[5]=uu11; M[6]=us10; M[7]=us11;
                M[8]=us00; M[9]=us10; M[10]=ss00; M[11]=ss01;
                M[12]=us01; M[13]=us11; M[14]=ss01; M[15]=ss11;
                finv4sym(M, (rep==0)?L0:L1);
                if(rep==1) break;
                float S00=uu00+2.0f*cst*us00+c2*ss00+r;
                float S01=uu01+cst*(us01+us10)+c2*ss01;
                float S11=uu11+2.0f*cst*us11+c2*ss11+r;
                float id=1.0f/(S00*S11-S01*S01);
                float G00=uu00+cst*us00, G01=uu01+cst*us01;
                float G10=uu01+cst*us10, G11=uu11+cst*us11;
                float G20=us00+cst*ss00, G21=us10+cst*ss01;
                float G30=us01+cst*ss01, G31=us11+cst*ss11;
                float W00=(G00*S11-G01*S01)*id, W01=(G01*S00-G00*S01)*id;
                float W10=(G10*S11-G11*S01)*id, W11=(G11*S00-G10*S01)*id;
                float W20=(G20*S11-G21*S01)*id, W21=(G21*S00-G20*S01)*id;
                float W30=(G30*S11-G31*S01)*id, W31=(G31*S00-G30*S01)*id;
                uu00-=W00*G00+W01*G01;
                uu01-=W00*G10+W01*G11;
                uu11-=W10*G10+W11*G11;
                us00-=W00*G20+W01*G21;
                us01-=W00*G30+W01*G31;
                us10-=W10*G20+W11*G21;
                us11-=W10*G30+W11*G31;
                ss00-=W20*G20+W21*G21;
                ss01-=W20*G30+W21*G31;
                ss11-=W30*G30+W31*G31;
            }
            for(int i=0;i<16;++i) lamW[i]=L0[i];
            lamW[16]=L1[0]-L0[0];
            lamW[17]=L1[1]-L0[1];
            lamW[18]=L1[5]-L0[5];
        }
    }
    __syncthreads();

    // ---- gain fill (proven); t==T-1 inverts pTf ----
    {
        int t = (int)blockIdx.x*NTH + threadIdx.x;
        if(t >= t0 && t < T){
            float l02=lamW[2],  l03=lamW[3];
            float l12=lamW[6],  l13=lamW[7];
            float l22=lamW[10], l23=lamW[11], l33=lamW[15];
            float L00=lamW[0], L01=lamW[1], L11=lamW[5];
            float W0=lamW[16], W1=lamW[17], W2=lamW[18];
            float kt=(float)(t-t0);
            float l00=fmaf(kt,W0,L00);
            float l01=fmaf(kt,W1,L01);
            float l11=fmaf(kt,W2,L11);
            float iX=1.0f/(l00*l11-l01*l01);
            float X00=l11*iX, X01=-l01*iX, X11=l00*iX;
            float B100=X00*l02+X01*l12, B101=X00*l03+X01*l13;
            float B110=X01*l02+X11*l12, B111=X01*l03+X11*l13;
            float Sp00=l22-(l02*B100+l12*B110);
            float Sp01=l23-(l02*B101+l12*B111);
            float Sp11=l33-(l03*B101+l13*B111);
            float iS=1.0f/(Sp00*Sp11-Sp01*Sp01);
            float Z00=Sp11*iS, Z01=-Sp01*iS, Z11=Sp00*iS;
            float pus00=-(B100*Z00+B101*Z01);
            float pus01=-(B100*Z01+B101*Z11);
            float pus10=-(B110*Z00+B111*Z01);
            float pus11=-(B110*Z01+B111*Z11);
            float puu00=X00-(pus00*B100+pus01*B101);
            float puu01=X01-(pus00*B110+pus01*B111);
            float puu11=X11-(pus10*B110+pus11*B111);
            float pss00=Z00, pss01=Z01, pss11=Z11;
            float S00=puu00+2.0f*cst*pus00+c2*pss00+r;
            float S01=puu01+cst*(pus01+pus10)+c2*pss01;
            float S11=puu11+2.0f*cst*pus11+c2*pss11+r;
            float det=S00*S11-S01*S01;
            float id=1.0f/det;
            float G00=puu00+cst*pus00, G01=puu01+cst*pus01;
            float G10=puu01+cst*pus10, G11=puu11+cst*pus11;
            float G20=pus00+cst*pss00, G21=pus10+cst*pss01;
            float G30=pus01+cst*pss01, G31=pus11+cst*pss11;
            float W00=(G00*S11-G01*S01)*id, W01=(G01*S00-G00*S01)*id;
            float W10=(G10*S11-G11*S01)*id, W11=(G11*S00-G10*S01)*id;
            float W20=(G20*S11-G21*S01)*id, W21=(G21*S00-G20*S01)*id;
            float W30=(G30*S11-G31*S01)*id, W31=(G31*S00-G30*S01)*id;
            g_kv[t*3+0]=make_float4(W00,W01,W10,W11);
            g_kv[t*3+1]=make_float4(W20,W21,W30,W31);
            g_kv[t*3+2]=make_float4(S00,S01,S11,id);
            if(t==T-1){
                float f0=puu00-(W00*G00+W01*G01);
                float f1=puu01-(W00*G10+W01*G11);
                float f5=puu11-(W10*G10+W11*G11);
                float f2=pus00-(W00*G20+W01*G21);
                float f3=pus01-(W00*G30+W01*G31);
                float f6=pus10-(W10*G20+W11*G21);
                float f7=pus11-(W10*G30+W11*G31);
                float f10=pss00-(W20*G20+W21*G21);
                float f11=pss01-(W20*G30+W21*G31);
                float f15=pss11-(W30*G30+W31*G31);
                float Pm[16]={f0,f1,f2,f3, f1,f5,f6,f7, f2,f6,f10,f11, f3,f7,f11,f15};
                float Qi[16];
                finv4sym(Pm,Qi);
                #pragma unroll
                for(int i=0;i<16;++i) g_pTf[i]=Qi[i];
            }
        }
    }
    __syncthreads();

    // ---- chunk composition (tid<16) + precision-output staging (last block) ----
    if(threadIdx.x < 16){
        int cidx = (int)blockIdx.x*16 + threadIdx.x;
        if(cidx*CH < T){
            float Eo[16]={1,0,0,0, 0,1,0,0, 0,0,1,0, 0,0,0,1};
            float bo[4]={0,0,0,0};
            #pragma unroll
            for(int k=0;k<CH;++k){
                int t=cidx*CH+k;
                if(t>=T) break;
                float4 ka = g_kv[t*3+0];
                float4 kb = g_kv[t*3+1];
                float N0[4]={1.0f-ka.x, -ka.y, -cst*ka.x, -cst*ka.y};
                float N1[4]={-ka.z, 1.0f-ka.w, -cst*ka.z, -cst*ka.w};
                float N2[4]={-kb.x, -kb.y, 1.0f-cst*kb.x, -cst*kb.y};
                float N3[4]={-kb.z, -kb.w, -cst*kb.z, 1.0f-cst*kb.w};
                float Ek[16];
                Ek[0]=N0[0]; Ek[1]=N0[1]; Ek[2]=N0[2]*A00+N0[3]*A01; Ek[3]=N0[2]*A10+N0[3]*A11;
                Ek[4]=N1[0]; Ek[5]=N1[1]; Ek[6]=N1[2]*A00+N1[3]*A01; Ek[7]=N1[2]*A10+N1[3]*A11;
                Ek[8]=N2[0]; Ek[9]=N2[1]; Ek[10]=N2[2]*A00+N2[3]*A01; Ek[11]=N2[2]*A10+N2[3]*A11;
                Ek[12]=N3[0]; Ek[13]=N3[1]; Ek[14]=N3[2]*A00+N3[3]*A01; Ek[15]=N3[2]*A10+N3[3]*A11;
                float y=SQ8*(track[2*t]+track[2*t+1]);
                float bs_[4]={(ka.x+ka.y)*y,(ka.z+ka.w)*y,(kb.x+kb.y)*y,(kb.z+kb.w)*y};
                float En[16], bn[4];
                #pragma unroll
                for(int i=0;i<4;++i){
                    #pragma unroll
                    for(int j=0;j<4;++j)
                        En[i*4+j]=Ek[i*4]*Eo[j]+Ek[i*4+1]*Eo[4+j]+Ek[i*4+2]*Eo[8+j]+Ek[i*4+3]*Eo[12+j];
                    bn[i]=Ek[i*4]*bo[0]+Ek[i*4+1]*bo[1]+Ek[i*4+2]*bo[2]+Ek[i*4+3]*bo[3]+bs_[i];
                }
                #pragma unroll
                for(int i=0;i<16;++i) Eo[i]=En[i];
                #pragma unroll
                for(int i=0;i<4;++i) bo[i]=bn[i];
            }
            #pragma unroll
            for(int i=0;i<16;++i) g_elems[cidx*20+i]=Eo[i];
            #pragma unroll
            for(int i=0;i<4;++i)  g_elems[cidx*20+16+i]=bo[i];
        }
    } else if((int)blockIdx.x == nfill-1){
        if(threadIdx.x>=32 && threadIdx.x<48) shp[threadIdx.x-32]=g_pTf[threadIdx.x-32];
        if(threadIdx.x==16){
            double Td=(double)T, rr_=(double)r;
            shc[0]=(float)(1.0/(double)bs0 + Td/rr_);
            shc[1]=(float)(1.0/(double)bs1 + Td/rr_);
            shc[2]=(float)(1.0/(double)bsu + Td/rr_);
        }
    }
    __syncthreads();

    // ---- 66x66 precision output (last fill block; proven mapping) ----
    if((int)blockIdx.x == nfill-1){
        const int c = threadIdx.x;
        const int NP=66*66;
        const float INV32=0.03125f;
        const float INVS32=0.17677669529663687f;
        for(int idx=c; idx<NP; idx+=NTH){
            if(idx+1>=out_size) break;
            int i=idx/66, j=idx-66*i;
            float v;
            if(i<64 && j<64){
                int pi=i>>5, pj=j>>5, ei=i&1, ej=j&1;
                v=shp[pi*4+pj]*INV32;
                if(pi==pj){
                    v += ((ei==ej)?shc[2]:-shc[2])*INV32;
                    if(ei==ej){
                        v -= shc[ei]*0.0625f;
                        if(i==j) v += shc[ei];
                    }
                }
            } else if(i<64){
                int pi=i>>5;
                v=shp[pi*4+2+(j-64)]*INVS32;
            } else if(j<64){
                int pj=j>>5;
                v=shp[pj*4+2+(i-64)]*INVS32;
            } else {
                v=shp[(2+i-64)*4+(2+j-64)];
            }
            out[1+idx]=v;
        }
    }
}

// ================= KB: warp-shuffle scan + replay + logp =================
__global__ void __launch_bounds__(NTH,1)
hmm_kB(const float* __restrict__ track, const float* __restrict__ Ain,
       float* __restrict__ out, int T, int out_size)
{
    __shared__ float wagg[8][20];
    __shared__ float bsh[NTH*4];
    __shared__ float fw[8];
    __shared__ double sred[2];

    const int c = threadIdx.x;
    const int lane = c&31, wid = c>>5;
    const float SQ8 = 2.8284271247461903f;
    const float cst = 5.656854249492381f;
    const float A00=Ain[0], A01=Ain[1], A10=Ain[2], A11=Ain[3];

    float sig[CH];
    #pragma unroll
    for(int k=0;k<CH;++k){
        int t=c*CH+k;
        float x0 = (t<T)?track[2*t]:0.0f;
        float x1 = (t<T)?track[2*t+1]:0.0f;
        sig[k]=SQ8*(x0+x1);
    }

    // load chunk element
    float Eo[16], bo[4];
    {
        const float* ge = g_elems + c*20;
        #pragma unroll
        for(int i=0;i<16;++i) Eo[i]=ge[i];
        #pragma unroll
        for(int i=0;i<4;++i)  bo[i]=ge[16+i];
    }

    // ---- Kogge-Stone warp scan (compose: new = self ∘ left) ----
    #pragma unroll
    for(int off=1; off<32; off<<=1){
        float El[16], bl[4];
        #pragma unroll
        for(int i=0;i<16;++i) El[i]=__shfl_up_sync(0xffffffffu, Eo[i], off);
        #pragma unroll
        for(int i=0;i<4;++i)  bl[i]=__shfl_up_sync(0xffffffffu, bo[i], off);
        if(lane>=off){
            float bn[4], En[16];
            #pragma unroll
            for(int i=0;i<4;++i)
                bn[i]=Eo[i*4]*bl[0]+Eo[i*4+1]*bl[1]+Eo[i*4+2]*bl[2]+Eo[i*4+3]*bl[3]+bo[i];
            #pragma unroll
            for(int i=0;i<4;++i)
                #pragma unroll
                for(int j=0;j<4;++j)
                    En[i*4+j]=Eo[i*4]*El[j]+Eo[i*4+1]*El[4+j]+Eo[i*4+2]*El[8+j]+Eo[i*4+3]*El[12+j];
            #pragma unroll
            for(int i=0;i<16;++i) Eo[i]=En[i];
            #pragma unroll
            for(int i=0;i<4;++i)  bo[i]=bn[i];
        }
    }
    if(lane==31){
        #pragma unroll
        for(int i=0;i<16;++i) wagg[wid][i]=Eo[i];
        #pragma unroll
        for(int i=0;i<4;++i)  wagg[wid][16+i]=bo[i];
    }
    __syncthreads();
    // ---- scan 8 warp aggregates in warp 0 (lanes 0..7) ----
    if(wid==0 && lane<8){
        float Ea[16], ba[4];
        #pragma unroll
        for(int i=0;i<16;++i) Ea[i]=wagg[lane][i];
        #pragma unroll
        for(int i=0;i<4;++i)  ba[i]=wagg[lane][16+i];
        #pragma unroll
        for(int off=1; off<8; off<<=1){
            float El[16], bl[4];
            #pragma unroll
            for(int i=0;i<16;++i) El[i]=__shfl_up_sync(0xffu, Ea[i], off);
            #pragma unroll
            for(int i=0;i<4;++i)  bl[i]=__shfl_up_sync(0xffu, ba[i], off);
            if(lane>=off){
                float bn[4], En[16];
                #pragma unroll
                for(int i=0;i<4;++i)
                    bn[i]=Ea[i*4]*bl[0]+Ea[i*4+1]*bl[1]+Ea[i*4+2]*bl[2]+Ea[i*4+3]*bl[3]+ba[i];
                #pragma unroll
                for(int i=0;i<4;++i)
                    #pragma unroll
                    for(int j=0;j<4;++j)
                        En[i*4+j]=Ea[i*4]*El[j]+Ea[i*4+1]*El[4+j]+Ea[i*4+2]*El[8+j]+Ea[i*4+3]*El[12+j];
                #pragma unroll
                for(int i=0;i<16;++i) Ea[i]=En[i];
                #pragma unroll
                for(int i=0;i<4;++i)  ba[i]=bn[i];
            }
        }
        #pragma unroll
        for(int i=0;i<16;++i) wagg[lane][i]=Ea[i];
        #pragma unroll
        for(int i=0;i<4;++i)  wagg[lane][16+i]=ba[i];
    }
    __syncthreads();
    // ---- apply cross-warp prefix ----
    if(wid>0){
        float Ep[16], bp[4];
        #pragma unroll
        for(int i=0;i<16;++i) Ep[i]=wagg[wid-1][i];
        #pragma unroll
        for(int i=0;i<4;++i)  bp[i]=wagg[wid-1][16+i];
        float bn[4], En[16];
        #pragma unroll
        for(int i=0;i<4;++i)
            bn[i]=Eo[i*4]*bp[0]+Eo[i*4+1]*bp[1]+Eo[i*4+2]*bp[2]+Eo[i*4+3]*bp[3]+bo[i];
        #pragma unroll
        for(int i=0;i<4;++i)
            #pragma unroll
            for(int j=0;j<4;++j)
                En[i*4+j]=Eo[i*4]*Ep[j]+Eo[i*4+1]*Ep[4+j]+Eo[i*4+2]*Ep[8+j]+Eo[i*4+3]*Ep[12+j];
        #pragma unroll
        for(int i=0;i<16;++i) Eo[i]=En[i];
        #pragma unroll
        for(int i=0;i<4;++i)  bo[i]=bn[i];
    }
    // stash inclusive b for replay
    #pragma unroll
    for(int i=0;i<4;++i) bsh[c*4+i]=bo[i];
    __syncthreads();

    // ---- replay (proven) ----
    float m0=0.f,m1=0.f,m2=0.f,m3=0.f;
    if(c>0){
        m0=bsh[(c-1)*4+0]; m1=bsh[(c-1)*4+1];
        m2=bsh[(c-1)*4+2]; m3=bsh[(c-1)*4+3];
    }
    float qd=0.0f;
    float prodm=1.0f;
    int eacc=0;
    #pragma unroll
    for(int k=0;k<CH;++k){
        int t=c*CH+k;
        float4 ka = g_kv[t*3+0];
        float4 kb = g_kv[t*3+1];
        float4 sc = g_kv[t*3+2];
        float p2=A00*m2+A10*m3;
        float p3=A01*m2+A11*m3;
        float y=sig[k];
        float z0=y-m0-cst*p2;
        float z1=y-m1-cst*p3;
        float id=sc.w;
        float u0=(sc.z*z0-sc.y*z1)*id;
        float u1=(sc.x*z1-sc.y*z0)*id;
        qd += z0*u0+z1*u1;
        float det=sc.x*sc.z-sc.y*sc.y;
        int bi=__float_as_int(det);
        eacc += ((bi>>23)&255)-127;
        prodm *= __int_as_float((bi&0x807FFFFF)|0x3F800000);
        int pb=__float_as_int(prodm);
        eacc += ((pb>>23)&255)-127;
        prodm = __int_as_float((pb&0x807FFFFF)|0x3F800000);
        m0 += ka.x*z0+ka.y*z1;
        m1 += ka.z*z0+ka.w*z1;
        m2  = p2 + kb.x*z0+kb.y*z1;
        m3  = p3 + kb.z*z0+kb.w*z1;
    }
    float ldt=fmaf((float)eacc, 0.6931471805599453f, logf(prodm));

    {
        float s=wred(qd);
        if(lane==0) fw[wid]=s;
        __syncthreads();
        if(c==0){
            double acc=0.0;
            for(int i=0;i<8;++i) acc+=(double)fw[i];
            sred[0]=acc;
        }
        __syncthreads();
        s=wred(ldt);
        if(lane==0) fw[wid]=s;
        __syncthreads();
        if(c==0){
            double acc=0.0;
            for(int i=0;i<8;++i) acc+=(double)fw[i];
            sred[1]=acc;
        }
        __syncthreads();
    }

    if(c==0 && out_size>0){
        double logp = g_logc - 0.5*(sred[0] + sred[1]);
        out[0]=(float)logp;
    }
}

extern "C" void kernel_launch(void* const* d_in, const int* in_sizes, int n_in,
                              void* d_out, int out_size) {
    const float* track     = (const float*)d_in[0];
    const float* bias_sc   = (const float*)d_in[1];
    const float* obs_noise = (const float*)d_in[2];
    const float* trans_n   = (const float*)d_in[3];
    const float* A         = (const float*)d_in[4];
    const float* init_cov  = (const float*)d_in[5];
    float* out = (float*)d_out;
    int T = in_sizes[0]/2;
    if (T > TT) T = TT;
    int t0 = (T >= T0) ? T0 : T;
    int nfill = (T + NTH - 1) / NTH;

    hmm_kA<<<nfill + 1, NTH>>>(track, bias_sc, obs_noise, trans_n, A, init_cov,
                               out, T, t0, nfill, out_size);
    hmm_kB<<<1, NTH>>>(track, A, out, T, out_size);
}